// round 10
// baseline (speedup 1.0000x reference)
#include <cuda_runtime.h>
#include <cuda_bf16.h>
#include <math.h>
#include <stdint.h>

#define NN 50000
#define EE 800000
#define HIDN 128
#define GG 256
#define NBLK 49   // ceil(NN/1024)

static inline int cdiv_h(int a, int b) { return (a + b - 1) / b; }

// ----------------------------- scratch (device globals) -----------------------------
__device__ float g_x[NN * HIDN];
__device__ float g_Q[NN * HIDN];
__device__ __nv_bfloat16 g_Kb[NN * HIDN];
__device__ __nv_bfloat16 g_Vb[NN * HIDN];
__device__ float g_aggr[NN * HIDN];
__device__ float g_h[NN * HIDN];
__device__ float g_comb[512 * HIDN];
__device__ __nv_bfloat16 g_tDPk[512 * HIDN];
__device__ __nv_bfloat16 g_tDPv[512 * HIDN];
__device__ uint32_t g_wHi[196608];   // prepacked weights (bf16 hi), smem-image layout
__device__ uint32_t g_wLo[196608];   // prepacked weights (bf16 lo residual)
__device__ int   g_cnt[NN];
__device__ int   g_segoff[NN + 1];
__device__ int   g_cursor[NN];
__device__ uint32_t g_edge[EE];      // packed: src | (dp<<16)
__device__ int   g_bsum[64];
__device__ int   g_boff[64];
__device__ int   g_gcnt[GG];
__device__ int   g_goff[GG + 1];

// image layout constants (words): per layer 98304
#define IMG_LAYER 98304
#define OFF_Q 0
#define OFF_K 12288
#define OFF_V 24576
#define OFF_A 36864
#define OFF_M 49152
#define OFF_O 73728

// ----------------------------- helpers -----------------------------
__device__ __forceinline__ float gelu_f(float x) {
    return 0.5f * x * (1.0f + erff(x * 0.7071067811865476f));
}

__device__ __forceinline__ void mma_bf16(float c[4], const uint32_t a[4], const uint32_t b[2]) {
    asm volatile(
        "mma.sync.aligned.m16n8k16.row.col.f32.bf16.bf16.f32 "
        "{%0,%1,%2,%3}, {%4,%5,%6,%7}, {%8,%9}, {%0,%1,%2,%3};"
        : "+f"(c[0]), "+f"(c[1]), "+f"(c[2]), "+f"(c[3])
        : "r"(a[0]), "r"(a[1]), "r"(a[2]), "r"(a[3]), "r"(b[0]), "r"(b[1]));
}

__device__ __forceinline__ void pack_hl(float x, float y, uint32_t& hi, uint32_t& lo) {
    __nv_bfloat16 hx = __float2bfloat16(x);
    __nv_bfloat16 hy = __float2bfloat16(y);
    __nv_bfloat16 lx = __float2bfloat16(x - __bfloat162float(hx));
    __nv_bfloat16 ly = __float2bfloat16(y - __bfloat162float(hy));
    __nv_bfloat162 h2 = __halves2bfloat162(hx, hy);
    __nv_bfloat162 l2 = __halves2bfloat162(lx, ly);
    hi = *(uint32_t*)&h2;
    lo = *(uint32_t*)&l2;
}

__device__ __forceinline__ float4 ld_bf16x4(const __nv_bfloat16* p) {
    uint2 u = *(const uint2*)p;
    __nv_bfloat162 a = *(__nv_bfloat162*)&u.x;
    __nv_bfloat162 b = *(__nv_bfloat162*)&u.y;
    float2 fa = __bfloat1622float2(a), fb = __bfloat1622float2(b);
    return make_float4(fa.x, fa.y, fb.x, fb.y);
}

__device__ __forceinline__ uint32_t f2bf2(float a, float b) {
    __nv_bfloat162 t = __halves2bfloat162(__float2bfloat16(a), __float2bfloat16(b));
    return *(uint32_t*)&t;
}

// ----------------------------- misc kernels -----------------------------
__global__ void zero_kernel() {
    int i = blockIdx.x * blockDim.x + threadIdx.x;
    if (i < NN) g_cnt[i] = 0;
    if (i < GG) g_gcnt[i] = 0;
}

__global__ void encoder_kernel(const int* __restrict__ attr, const float* __restrict__ aemb) {
    int c = threadIdx.x;
    for (int n = blockIdx.x; n < NN; n += gridDim.x) {
        int a0 = attr[n * 4 + 0], a1 = attr[n * 4 + 1], a2 = attr[n * 4 + 2], a3 = attr[n * 4 + 3];
        float v = aemb[(0 * 64 + a0) * HIDN + c] + aemb[(1 * 64 + a1) * HIDN + c]
                + aemb[(2 * 64 + a2) * HIDN + c] + aemb[(3 * 64 + a3) * HIDN + c];
        g_x[(size_t)n * HIDN + c] = v;
    }
}

// prepack ALL weights into GEMM smem-image layout (bf16 hi/lo, kpair-packed, n-major, stride 12)
__global__ void prepack_kernel(const float* __restrict__ Wq, const float* __restrict__ Wk,
                               const float* __restrict__ Wv, const float* __restrict__ Wa,
                               const float* __restrict__ Wm, const float* __restrict__ Wo) {
    for (int id = blockIdx.x * blockDim.x + threadIdx.x; id < 131072;
         id += gridDim.x * blockDim.x) {
        int layer = id >> 16;
        int r = id & 65535;
        const float* W; int N; int segoff; int wi;
        if (r < 32768) {
            int m = r >> 13; wi = r & 8191;
            W = (m == 0 ? Wq : m == 1 ? Wk : m == 2 ? Wv : Wa) + layer * 16384;
            N = 128; segoff = m * 12288;
        } else if (r < 49152) {
            wi = r - 32768; W = Wm + layer * 32768; N = 256; segoff = OFF_M;
        } else {
            wi = r - 49152; W = Wo + layer * 32768; N = 128; segoff = OFF_O;
        }
        int ch = wi / (8 * N);
        int rem = wi % (8 * N);
        int kp = rem / N;
        int n = rem % N;
        int k = ch * 16 + kp * 2;
        float a = W[(size_t)k * N + n], b = W[(size_t)(k + 1) * N + n];
        uint32_t hi, lo;
        pack_hl(a, b, hi, lo);
        int w = layer * IMG_LAYER + segoff + ch * N * 12 + n * 12 + kp;
        g_wHi[w] = hi;
        g_wLo[w] = lo;
    }
}

__global__ void count_kernel(const int* __restrict__ tgt, const int* __restrict__ bidx) {
    int i = blockIdx.x * blockDim.x + threadIdx.x;
    if (i < EE) atomicAdd(&g_cnt[tgt[i]], 1);
    if (i < NN) atomicAdd(&g_gcnt[bidx[i]], 1);
}

__global__ void scan1_kernel() {
    __shared__ int sh[256];
    int blk = blockIdx.x, t = threadIdx.x;
    int idx4 = blk * 256 + t;
    int4 v4 = make_int4(0, 0, 0, 0);
    if (idx4 < NN / 4) v4 = ((const int4*)g_cnt)[idx4];
    int s = v4.x + v4.y + v4.z + v4.w;
    sh[t] = s;
    __syncthreads();
    for (int d = 1; d < 256; d <<= 1) {
        int v = (t >= d) ? sh[t - d] : 0;
        __syncthreads();
        sh[t] += v;
        __syncthreads();
    }
    int run = (t == 0) ? 0 : sh[t - 1];
    int base = blk * 1024 + t * 4;
    int vv[4] = {v4.x, v4.y, v4.z, v4.w};
    for (int j = 0; j < 4; j++) {
        if (base + j < NN) g_segoff[base + j] = run;
        run += vv[j];
    }
    if (t == 255) g_bsum[blk] = sh[255];
}

__global__ void scan2_kernel() {
    __shared__ int sg[256];
    __shared__ int sb[64];
    int t = threadIdx.x;
    sg[t] = g_gcnt[t];
    if (t < 64) sb[t] = (t < NBLK) ? g_bsum[t] : 0;
    __syncthreads();
    for (int d = 1; d < 256; d <<= 1) {
        int v = (t >= d) ? sg[t - d] : 0;
        int v2 = 0;
        if (t < 64 && t >= d && d < 64) v2 = sb[t - d];
        __syncthreads();
        sg[t] += v;
        if (t < 64 && d < 64) sb[t] += v2;
        __syncthreads();
    }
    g_goff[t + 1] = sg[t];
    if (t == 0) g_goff[0] = 0;
    if (t < 64) g_boff[t] = (t == 0) ? 0 : sb[t - 1];
}

__global__ void scan3_kernel() {
    int blk = blockIdx.x, t = threadIdx.x;
    int off = g_boff[blk];
    int base = blk * 1024 + t * 4;
    for (int j = 0; j < 4; j++) {
        int i = base + j;
        if (i < NN) {
            int v = g_segoff[i] + off;
            g_segoff[i] = v;
            g_cursor[i] = v;
        }
    }
    if (blk == 0 && t == 0) g_segoff[NN] = EE;
}

__global__ void scatter_kernel(const int* __restrict__ src, const int* __restrict__ tgt,
                               const int* __restrict__ sdist, const int* __restrict__ spath) {
    int i = blockIdx.x * blockDim.x + threadIdx.x;
    if (i < EE) {
        int tg = tgt[i];
        int pos = atomicAdd(&g_cursor[tg], 1);
        uint32_t dp = (uint32_t)((sdist[i] << 4) | spath[i]);
        g_edge[pos] = (uint32_t)src[i] | (dp << 16);
    }
}

__global__ void comb_kernel(const float* __restrict__ de, const float* __restrict__ pe) {
    int c = threadIdx.x;
    for (int r = blockIdx.x; r < 512; r += gridDim.x) {
        int d = r >> 4, p = r & 15;
        g_comb[r * HIDN + c] = de[d * HIDN + c] + pe[p * HIDN + c];
    }
}

// ------------------- GEMM (double-buffered; Bl traffic only when needed) -------------
enum { EPI_LN = 2, EPI_NODE = 3, EPI_TBL = 4 };
#define G8_SMEM 51200

template <int KDIM, int EPI, bool GELU_A>
__global__ void __launch_bounds__(256) gemm9_kernel(
    const float* __restrict__ A,
    const uint32_t* __restrict__ BhGbase, const uint32_t* __restrict__ BlGbase, int yStride,
    const float* __restrict__ bias, const float* __restrict__ bias2,
    const float* __restrict__ res, const float* __restrict__ lng, const float* __restrict__ lnb,
    float* __restrict__ C, __nv_bfloat16* __restrict__ Cb, __nv_bfloat16* __restrict__ Cb2,
    int M)
{
    constexpr int TM = 128;
    constexpr int NC = 128;
    constexpr int CW = NC * 12;      // 1536 words per buffer

    extern __shared__ uint32_t dyn[];
    uint32_t* AhB = dyn;             // 2 x 1536
    uint32_t* AlB = AhB + 3072;      // 2 x 1536
    uint32_t* BhB = AlB + 3072;      // 2 x 1536
    uint32_t* BlB = BhB + 3072;      // 2 x 1536
    float2* redS = (float2*)(BlB + 3072);  // 128 x 2

    int tid = threadIdx.x;
    int wid = tid >> 5, lane = tid & 31;
    int g = lane >> 2, q = lane & 3;
    int wrow = (wid & 3) * 32;
    int wcol = (wid >> 2) * 64;
    int r0 = blockIdx.x * TM;

    const uint32_t* BhG = BhGbase + (size_t)blockIdx.y * yStride;
    const uint32_t* BlG = BlGbase + (size_t)blockIdx.y * yStride;
    const bool third = (EPI == EPI_NODE) ? (blockIdx.y == 0) : (EPI == EPI_LN);

    const float* bs = bias;
    __nv_bfloat16* outb = Cb;
    if (EPI == EPI_NODE && blockIdx.y != 0) {
        bs = nullptr;
        outb = (blockIdx.y == 1) ? Cb : Cb2;
    }
    if (EPI == EPI_TBL && blockIdx.y == 1) { bs = bias2; outb = Cb2; }

    float acc[2][8][4];
#pragma unroll
    for (int a = 0; a < 2; a++)
#pragma unroll
        for (int b = 0; b < 8; b++)
#pragma unroll
            for (int c = 0; c < 4; c++) acc[a][b][c] = 0.f;

    float4 aS[2];
    uint2 bPh[3], bPl[3];

    // prologue: stage chunk 0 (Bl only on 3-pass paths)
#pragma unroll
    for (int i = 0; i < 2; i++) {
        int j = tid + i * 256;
        int row = j >> 2, c4 = j & 3;
        int gr = r0 + row;
        aS[i] = (gr < M) ? *(const float4*)(A + (size_t)gr * KDIM + c4 * 4)
                         : make_float4(0.f, 0.f, 0.f, 0.f);
    }
#pragma unroll
    for (int i = 0; i < 3; i++) bPh[i] = ((const uint2*)BhG)[tid + i * 256];
    if (third) {
#pragma unroll
        for (int i = 0; i < 3; i++) bPl[i] = ((const uint2*)BlG)[tid + i * 256];
    }

    constexpr int NCH = KDIM / 16;
#pragma unroll 1
    for (int c = 0; c < NCH; c++) {
        int p = c & 1;
        uint32_t* Ah = AhB + p * 1536;
        uint32_t* Al = AlB + p * 1536;
        uint32_t* Bh = BhB + p * 1536;
        uint32_t* Bl = BlB + p * 1536;

        // store staged -> smem[p]
#pragma unroll
        for (int i = 0; i < 2; i++) {
            int j = tid + i * 256;
            int row = j >> 2, c4 = j & 3;
            float4 v = aS[i];
            if (GELU_A) { v.x = gelu_f(v.x); v.y = gelu_f(v.y); v.z = gelu_f(v.z); v.w = gelu_f(v.w); }
            uint32_t h01, l01, h23, l23;
            pack_hl(v.x, v.y, h01, l01);
            pack_hl(v.z, v.w, h23, l23);
            *(uint2*)&Ah[row * 12 + c4 * 2] = make_uint2(h01, h23);
            *(uint2*)&Al[row * 12 + c4 * 2] = make_uint2(l01, l23);
        }
#pragma unroll
        for (int i = 0; i < 3; i++) ((uint2*)Bh)[tid + i * 256] = bPh[i];
        if (third) {
#pragma unroll
            for (int i = 0; i < 3; i++) ((uint2*)Bl)[tid + i * 256] = bPl[i];
        }
        __syncthreads();   // single barrier per chunk (double-buffer safe)

        // prefetch next chunk into registers
        if (c + 1 < NCH) {
            int kn = (c + 1) * 16;
#pragma unroll
            for (int i = 0; i < 2; i++) {
                int j = tid + i * 256;
                int row = j >> 2, c4 = j & 3;
                int gr = r0 + row;
                aS[i] = (gr < M) ? *(const float4*)(A + (size_t)gr * KDIM + kn + c4 * 4)
                                 : make_float4(0.f, 0.f, 0.f, 0.f);
            }
            int cb = (c + 1) * CW;
#pragma unroll
            for (int i = 0; i < 3; i++) bPh[i] = ((const uint2*)(BhG + cb))[tid + i * 256];
            if (third) {
#pragma unroll
                for (int i = 0; i < 3; i++) bPl[i] = ((const uint2*)(BlG + cb))[tid + i * 256];
            }
        }

        // fragments + mma (from buffer p)
        uint32_t ah[2][4], al[2][4];
#pragma unroll
        for (int mt = 0; mt < 2; mt++) {
            int r = wrow + mt * 16 + g;
            ah[mt][0] = Ah[r * 12 + q];     ah[mt][1] = Ah[(r + 8) * 12 + q];
            ah[mt][2] = Ah[r * 12 + q + 4]; ah[mt][3] = Ah[(r + 8) * 12 + q + 4];
            al[mt][0] = Al[r * 12 + q];     al[mt][1] = Al[(r + 8) * 12 + q];
            al[mt][2] = Al[r * 12 + q + 4]; al[mt][3] = Al[(r + 8) * 12 + q + 4];
        }
#pragma unroll
        for (int nt = 0; nt < 8; nt++) {
            int n = wcol + nt * 8 + g;
            uint32_t bh[2] = {Bh[n * 12 + q], Bh[n * 12 + q + 4]};
#pragma unroll
            for (int mt = 0; mt < 2; mt++) {
                mma_bf16(acc[mt][nt], ah[mt], bh);
                mma_bf16(acc[mt][nt], al[mt], bh);
            }
            if (third) {
                uint32_t bl[2] = {Bl[n * 12 + q], Bl[n * 12 + q + 4]};
#pragma unroll
                for (int mt = 0; mt < 2; mt++) mma_bf16(acc[mt][nt], ah[mt], bl);
            }
        }
    }
    __syncthreads();

    if (EPI == EPI_LN) {
        int wh = wcol >> 6;
        float s0[2] = {0, 0}, q0[2] = {0, 0}, s1[2] = {0, 0}, q1[2] = {0, 0};
#pragma unroll
        for (int mt = 0; mt < 2; mt++) {
            int ra = r0 + wrow + mt * 16 + g, rb = ra + 8;
#pragma unroll
            for (int nt = 0; nt < 8; nt++) {
                int col = wcol + nt * 8 + q * 2;
                float b0 = bias[col], b1 = bias[col + 1];
                float ra0 = (ra < M) ? res[(size_t)ra * NC + col] : 0.f;
                float ra1 = (ra < M) ? res[(size_t)ra * NC + col + 1] : 0.f;
                float rb0 = (rb < M) ? res[(size_t)rb * NC + col] : 0.f;
                float rb1 = (rb < M) ? res[(size_t)rb * NC + col + 1] : 0.f;
                float va0 = acc[mt][nt][0] + b0 + ra0;
                float va1 = acc[mt][nt][1] + b1 + ra1;
                float vb0 = acc[mt][nt][2] + b0 + rb0;
                float vb1 = acc[mt][nt][3] + b1 + rb1;
                acc[mt][nt][0] = va0; acc[mt][nt][1] = va1;
                acc[mt][nt][2] = vb0; acc[mt][nt][3] = vb1;
                s0[mt] += va0 + va1; q0[mt] += va0 * va0 + va1 * va1;
                s1[mt] += vb0 + vb1; q1[mt] += vb0 * vb0 + vb1 * vb1;
            }
        }
#pragma unroll
        for (int mt = 0; mt < 2; mt++) {
            s0[mt] += __shfl_xor_sync(0xffffffffu, s0[mt], 1);
            s0[mt] += __shfl_xor_sync(0xffffffffu, s0[mt], 2);
            q0[mt] += __shfl_xor_sync(0xffffffffu, q0[mt], 1);
            q0[mt] += __shfl_xor_sync(0xffffffffu, q0[mt], 2);
            s1[mt] += __shfl_xor_sync(0xffffffffu, s1[mt], 1);
            s1[mt] += __shfl_xor_sync(0xffffffffu, s1[mt], 2);
            q1[mt] += __shfl_xor_sync(0xffffffffu, q1[mt], 1);
            q1[mt] += __shfl_xor_sync(0xffffffffu, q1[mt], 2);
            if (q == 0) {
                redS[(wrow + mt * 16 + g) * 2 + wh] = make_float2(s0[mt], q0[mt]);
                redS[(wrow + mt * 16 + 8 + g) * 2 + wh] = make_float2(s1[mt], q1[mt]);
            }
        }
        __syncthreads();
#pragma unroll
        for (int mt = 0; mt < 2; mt++) {
            int lra = wrow + mt * 16 + g;
            float2 p0 = redS[lra * 2], p1 = redS[lra * 2 + 1];
            float2 p0b = redS[(lra + 8) * 2], p1b = redS[(lra + 8) * 2 + 1];
            float sa = p0.x + p1.x, qa = p0.y + p1.y;
            float sb = p0b.x + p1b.x, qb = p0b.y + p1b.y;
            float ma = sa * (1.f / 128.f), mb = sb * (1.f / 128.f);
            float rsa = rsqrtf(qa * (1.f / 128.f) - ma * ma + 1e-5f);
            float rsb = rsqrtf(qb * (1.f / 128.f) - mb * mb + 1e-5f);
            int ra = r0 + lra, rb = ra + 8;
#pragma unroll
            for (int nt = 0; nt < 8; nt++) {
                int col = wcol + nt * 8 + q * 2;
                float g0 = lng[col], g1 = lng[col + 1], o0 = lnb[col], o1 = lnb[col + 1];
                if (ra < M)
                    *(float2*)(C + (size_t)ra * NC + col) =
                        make_float2((acc[mt][nt][0] - ma) * rsa * g0 + o0,
                                    (acc[mt][nt][1] - ma) * rsa * g1 + o1);
                if (rb < M)
                    *(float2*)(C + (size_t)rb * NC + col) =
                        make_float2((acc[mt][nt][2] - mb) * rsb * g0 + o0,
                                    (acc[mt][nt][3] - mb) * rsb * g1 + o1);
            }
        }
    } else if (EPI == EPI_NODE) {
#pragma unroll
        for (int mt = 0; mt < 2; mt++) {
            int ra = r0 + wrow + mt * 16 + g, rb = ra + 8;
#pragma unroll
            for (int nt = 0; nt < 8; nt++) {
                int col = wcol + nt * 8 + q * 2;
                float b0 = bs ? bs[col] : 0.f, b1 = bs ? bs[col + 1] : 0.f;
                float oa0 = acc[mt][nt][0] + b0, oa1 = acc[mt][nt][1] + b1;
                float ob0 = acc[mt][nt][2] + b0, ob1 = acc[mt][nt][3] + b1;
                if (blockIdx.y == 0) {
                    if (ra < M) *(float2*)(C + (size_t)ra * NC + col) = make_float2(oa0, oa1);
                    if (rb < M) *(float2*)(C + (size_t)rb * NC + col) = make_float2(ob0, ob1);
                } else {
                    if (ra < M) *(uint32_t*)(outb + (size_t)ra * NC + col) = f2bf2(oa0, oa1);
                    if (rb < M) *(uint32_t*)(outb + (size_t)rb * NC + col) = f2bf2(ob0, ob1);
                }
            }
        }
    } else {  // EPI_TBL
#pragma unroll
        for (int mt = 0; mt < 2; mt++) {
            int ra = r0 + wrow + mt * 16 + g, rb = ra + 8;
#pragma unroll
            for (int nt = 0; nt < 8; nt++) {
                int col = wcol + nt * 8 + q * 2;
                float b0 = bs[col], b1 = bs[col + 1];
                if (ra < M) *(uint32_t*)(outb + (size_t)ra * NC + col) =
                    f2bf2(acc[mt][nt][0] + b0, acc[mt][nt][1] + b1);
                if (rb < M) *(uint32_t*)(outb + (size_t)rb * NC + col) =
                    f2bf2(acc[mt][nt][2] + b0, acc[mt][nt][3] + b1);
            }
        }
    }
}

// ----------------------------- fused FFN (unchanged) ---------------------------------
__global__ void __launch_bounds__(256, 1) ffn_kernel(
    const float* __restrict__ H,
    const uint32_t* __restrict__ wh, const uint32_t* __restrict__ wl,
    const float* __restrict__ bmid, const float* __restrict__ bo,
    const float* __restrict__ lng, const float* __restrict__ lnb,
    float* __restrict__ C, int M)
{
    extern __shared__ uint32_t dyn[];
    uint32_t* Ah  = dyn;
    uint32_t* Al_ = Ah + 1536;
    uint32_t* BhS = Al_ + 1536;
    uint32_t* BlS = BhS + 1536;
    uint32_t* Mh  = BlS + 1536;
    uint32_t* Ml  = Mh + 9216;
    float2* redS = (float2*)(Ml + 9216);

    int tid = threadIdx.x;
    int wid = tid >> 5, lane = tid & 31;
    int g = lane >> 2, q = lane & 3;
    int wrow = (wid & 3) * 32;
    int wcol = (wid >> 2) * 64;
    int r0 = blockIdx.x * 128;

    float outacc[2][8][4];
#pragma unroll
    for (int a = 0; a < 2; a++)
#pragma unroll
        for (int b = 0; b < 8; b++)
#pragma unroll
            for (int c = 0; c < 4; c++) outacc[a][b][c] = 0.f;

#pragma unroll 1
    for (int nh = 0; nh < 2; nh++) {
        float midacc[2][8][4];
#pragma unroll
        for (int a = 0; a < 2; a++)
#pragma unroll
            for (int b = 0; b < 8; b++)
#pragma unroll
                for (int c = 0; c < 4; c++) midacc[a][b][c] = 0.f;

        float4 aS[2];
        uint2 bPh[3], bPl[3];
        const uint32_t* BmH = wh + OFF_M + nh * 1536;
        const uint32_t* BmL = wl + OFF_M + nh * 1536;
        {
#pragma unroll
            for (int i = 0; i < 2; i++) {
                int j = tid + i * 256;
                int row = j >> 2, c4 = j & 3;
                int gr = r0 + row;
                aS[i] = (gr < M) ? *(const float4*)(H + (size_t)gr * 128 + c4 * 4)
                                 : make_float4(0.f, 0.f, 0.f, 0.f);
            }
#pragma unroll
            for (int i = 0; i < 3; i++) {
                bPh[i] = ((const uint2*)BmH)[tid + i * 256];
                bPl[i] = ((const uint2*)BmL)[tid + i * 256];
            }
        }
        for (int k0 = 0; k0 < 128; k0 += 16) {
#pragma unroll
            for (int i = 0; i < 2; i++) {
                int j = tid + i * 256;
                int row = j >> 2, c4 = j & 3;
                uint32_t h01, l01, h23, l23;
                pack_hl(aS[i].x, aS[i].y, h01, l01);
                pack_hl(aS[i].z, aS[i].w, h23, l23);
                *(uint2*)&Ah[row * 12 + c4 * 2] = make_uint2(h01, h23);
                *(uint2*)&Al_[row * 12 + c4 * 2] = make_uint2(l01, l23);
            }
#pragma unroll
            for (int i = 0; i < 3; i++) {
                ((uint2*)BhS)[tid + i * 256] = bPh[i];
                ((uint2*)BlS)[tid + i * 256] = bPl[i];
            }
            __syncthreads();
            int kn = k0 + 16;
            if (kn < 128) {
#pragma unroll
                for (int i = 0; i < 2; i++) {
                    int j = tid + i * 256;
                    int row = j >> 2, c4 = j & 3;
                    int gr = r0 + row;
                    aS[i] = (gr < M) ? *(const float4*)(H + (size_t)gr * 128 + kn + c4 * 4)
                                     : make_float4(0.f, 0.f, 0.f, 0.f);
                }
                const uint32_t* ch = BmH + (kn / 16) * 3072;
                const uint32_t* cl = BmL + (kn / 16) * 3072;
#pragma unroll
                for (int i = 0; i < 3; i++) {
                    bPh[i] = ((const uint2*)ch)[tid + i * 256];
                    bPl[i] = ((const uint2*)cl)[tid + i * 256];
                }
            }
            uint32_t ah[2][4], al[2][4];
#pragma unroll
            for (int mt = 0; mt < 2; mt++) {
                int r = wrow + mt * 16 + g;
                ah[mt][0] = Ah[r * 12 + q];     ah[mt][1] = Ah[(r + 8) * 12 + q];
                ah[mt][2] = Ah[r * 12 + q + 4]; ah[mt][3] = Ah[(r + 8) * 12 + q + 4];
                al[mt][0] = Al_[r * 12 + q];     al[mt][1] = Al_[(r + 8) * 12 + q];
                al[mt][2] = Al_[r * 12 + q + 4]; al[mt][3] = Al_[(r + 8) * 12 + q + 4];
            }
#pragma unroll
            for (int nt = 0; nt < 8; nt++) {
                int n = wcol + nt * 8 + g;
                uint32_t bh[2] = {BhS[n * 12 + q], BhS[n * 12 + q + 4]};
                uint32_t bl[2] = {BlS[n * 12 + q], BlS[n * 12 + q + 4]};
#pragma unroll
                for (int mt = 0; mt < 2; mt++) {
                    mma_bf16(midacc[mt][nt], ah[mt], bh);
                    mma_bf16(midacc[mt][nt], al[mt], bh);
                    mma_bf16(midacc[mt][nt], ah[mt], bl);
                }
            }
            __syncthreads();
        }

#pragma unroll
        for (int mt = 0; mt < 2; mt++) {
            int r1 = wrow + mt * 16 + g, r2 = r1 + 8;
#pragma unroll
            for (int nt = 0; nt < 8; nt++) {
                int col = wcol + nt * 8 + 2 * q;
                float b0 = bmid[nh * 128 + col], b1 = bmid[nh * 128 + col + 1];
                float m0 = gelu_f(midacc[mt][nt][0] + b0);
                float m1 = gelu_f(midacc[mt][nt][1] + b1);
                float m2 = gelu_f(midacc[mt][nt][2] + b0);
                float m3 = gelu_f(midacc[mt][nt][3] + b1);
                int chi = (wcol >> 4) + (nt >> 1);
                int pi = (nt & 1) * 4 + q;
                uint32_t hi, lo;
                pack_hl(m0, m1, hi, lo);
                Mh[(chi * 128 + r1) * 9 + pi] = hi;
                Ml[(chi * 128 + r1) * 9 + pi] = lo;
                pack_hl(m2, m3, hi, lo);
                Mh[(chi * 128 + r2) * 9 + pi] = hi;
                Ml[(chi * 128 + r2) * 9 + pi] = lo;
            }
        }
        __syncthreads();

        const uint32_t* BoH = wh + OFF_O + nh * 8 * 1536;
        const uint32_t* BoL = wl + OFF_O + nh * 8 * 1536;
#pragma unroll
        for (int i = 0; i < 3; i++) {
            bPh[i] = ((const uint2*)BoH)[tid + i * 256];
            bPl[i] = ((const uint2*)BoL)[tid + i * 256];
        }
        for (int c2 = 0; c2 < 8; c2++) {
#pragma unroll
            for (int i = 0; i < 3; i++) {
                ((uint2*)BhS)[tid + i * 256] = bPh[i];
                ((uint2*)BlS)[tid + i * 256] = bPl[i];
            }
            __syncthreads();
            if (c2 < 7) {
                const uint32_t* ch = BoH + (c2 + 1) * 1536;
                const uint32_t* cl = BoL + (c2 + 1) * 1536;
#pragma unroll
                for (int i = 0; i < 3; i++) {
                    bPh[i] = ((const uint2*)ch)[tid + i * 256];
                    bPl[i] = ((const uint2*)cl)[tid + i * 256];
                }
            }
            uint32_t ah[2][4], al[2][4];
#pragma unroll
            for (int mt = 0; mt < 2; mt++) {
                int r = wrow + mt * 16 + g;
                ah[mt][0] = Mh[(c2 * 128 + r) * 9 + q];
                ah[mt][1] = Mh[(c2 * 128 + r + 8) * 9 + q];
                ah[mt][2] = Mh[(c2 * 128 + r) * 9 + q + 4];
                ah[mt][3] = Mh[(c2 * 128 + r + 8) * 9 + q + 4];
                al[mt][0] = Ml[(c2 * 128 + r) * 9 + q];
                al[mt][1] = Ml[(c2 * 128 + r + 8) * 9 + q];
                al[mt][2] = Ml[(c2 * 128 + r) * 9 + q + 4];
                al[mt][3] = Ml[(c2 * 128 + r + 8) * 9 + q + 4];
            }
#pragma unroll
            for (int nt = 0; nt < 8; nt++) {
                int n = wcol + nt * 8 + g;
                uint32_t bh[2] = {BhS[n * 12 + q], BhS[n * 12 + q + 4]};
                uint32_t bl[2] = {BlS[n * 12 + q], BlS[n * 12 + q + 4]};
#pragma unroll
                for (int mt = 0; mt < 2; mt++) {
                    mma_bf16(outacc[mt][nt], ah[mt], bh);
                    mma_bf16(outacc[mt][nt], al[mt], bh);
                    mma_bf16(outacc[mt][nt], ah[mt], bl);
                }
            }
            __syncthreads();
        }
    }

    int whf = wcol >> 6;
    float s0[2] = {0, 0}, q0[2] = {0, 0}, s1[2] = {0, 0}, q1[2] = {0, 0};
#pragma unroll
    for (int mt = 0; mt < 2; mt++) {
        int ra = r0 + wrow + mt * 16 + g, rb = ra + 8;
#pragma unroll
        for (int nt = 0; nt < 8; nt++) {
            int col = wcol + nt * 8 + q * 2;
            float b0 = bo[col], b1 = bo[col + 1];
            float ra0 = (ra < M) ? H[(size_t)ra * 128 + col] : 0.f;
            float ra1 = (ra < M) ? H[(size_t)ra * 128 + col + 1] : 0.f;
            float rb0 = (rb < M) ? H[(size_t)rb * 128 + col] : 0.f;
            float rb1 = (rb < M) ? H[(size_t)rb * 128 + col + 1] : 0.f;
            float va0 = outacc[mt][nt][0] + b0 + ra0;
            float va1 = outacc[mt][nt][1] + b1 + ra1;
            float vb0 = outacc[mt][nt][2] + b0 + rb0;
            float vb1 = outacc[mt][nt][3] + b1 + rb1;
            outacc[mt][nt][0] = va0; outacc[mt][nt][1] = va1;
            outacc[mt][nt][2] = vb0; outacc[mt][nt][3] = vb1;
            s0[mt] += va0 + va1; q0[mt] += va0 * va0 + va1 * va1;
            s1[mt] += vb0 + vb1; q1[mt] += vb0 * vb0 + vb1 * vb1;
        }
    }
#pragma unroll
    for (int mt = 0; mt < 2; mt++) {
        s0[mt] += __shfl_xor_sync(0xffffffffu, s0[mt], 1);
        s0[mt] += __shfl_xor_sync(0xffffffffu, s0[mt], 2);
        q0[mt] += __shfl_xor_sync(0xffffffffu, q0[mt], 1);
        q0[mt] += __shfl_xor_sync(0xffffffffu, q0[mt], 2);
        s1[mt] += __shfl_xor_sync(0xffffffffu, s1[mt], 1);
        s1[mt] += __shfl_xor_sync(0xffffffffu, s1[mt], 2);
        q1[mt] += __shfl_xor_sync(0xffffffffu, q1[mt], 1);
        q1[mt] += __shfl_xor_sync(0xffffffffu, q1[mt], 2);
        if (q == 0) {
            redS[(wrow + mt * 16 + g) * 2 + whf] = make_float2(s0[mt], q0[mt]);
            redS[(wrow + mt * 16 + 8 + g) * 2 + whf] = make_float2(s1[mt], q1[mt]);
        }
    }
    __syncthreads();
#pragma unroll
    for (int mt = 0; mt < 2; mt++) {
        int lra = wrow + mt * 16 + g;
        float2 p0 = redS[lra * 2], p1 = redS[lra * 2 + 1];
        float2 p0b = redS[(lra + 8) * 2], p1b = redS[(lra + 8) * 2 + 1];
        float sa = p0.x + p1.x, qa = p0.y + p1.y;
        float sb = p0b.x + p1b.x, qb = p0b.y + p1b.y;
        float ma = sa * (1.f / 128.f), mb = sb * (1.f / 128.f);
        float rsa = rsqrtf(qa * (1.f / 128.f) - ma * ma + 1e-5f);
        float rsb = rsqrtf(qb * (1.f / 128.f) - mb * mb + 1e-5f);
        int ra = r0 + lra, rb = ra + 8;
#pragma unroll
        for (int nt = 0; nt < 8; nt++) {
            int col = wcol + nt * 8 + q * 2;
            float g0 = lng[col], g1 = lng[col + 1], o0 = lnb[col], o1 = lnb[col + 1];
            if (ra < M)
                *(float2*)(C + (size_t)ra * 128 + col) =
                    make_float2((outacc[mt][nt][0] - ma) * rsa * g0 + o0,
                                (outacc[mt][nt][1] - ma) * rsa * g1 + o1);
            if (rb < M)
                *(float2*)(C + (size_t)rb * 128 + col) =
                    make_float2((outacc[mt][nt][2] - mb) * rsb * g0 + o0,
                                (outacc[mt][nt][3] - mb) * rsb * g1 + o1);
        }
    }
}

// ---------------- edge attention (2 warps per node, smem combine) --------------------
__global__ void __launch_bounds__(256) edge_attn_kernel() {
    __shared__ float part[4 * 32 * 5];   // stride-5 per lane: conflict-free (gcd(5,32)=1)
    int w = threadIdx.x >> 5, lane = threadIdx.x & 31;
    int local = w >> 1, half = w & 1;
    int n = blockIdx.x * 4 + local;      // NN divisible by 4 -> always valid
    int beg = g_segoff[n], end = g_segoff[n + 1];
    float4 q4 = *(const float4*)(g_Q + (size_t)n * HIDN + lane * 4);
    float den = 0.f, ax = 0.f, ay = 0.f, az = 0.f, aw = 0.f;
    int p = beg + half;
    for (; p + 2 < end; p += 4) {        // edges p and p+2 both valid
        uint32_t e0 = g_edge[p], e1 = g_edge[p + 2];
        int s0 = (int)(e0 & 0xFFFFu), i0 = (int)(e0 >> 16);
        int s1 = (int)(e1 & 0xFFFFu), i1 = (int)(e1 >> 16);
        float4 ks0 = ld_bf16x4(g_Kb + (size_t)s0 * HIDN + lane * 4);
        float4 kt0 = ld_bf16x4(g_tDPk + (size_t)i0 * HIDN + lane * 4);
        float4 vs0 = ld_bf16x4(g_Vb + (size_t)s0 * HIDN + lane * 4);
        float4 vt0 = ld_bf16x4(g_tDPv + (size_t)i0 * HIDN + lane * 4);
        float4 ks1 = ld_bf16x4(g_Kb + (size_t)s1 * HIDN + lane * 4);
        float4 kt1 = ld_bf16x4(g_tDPk + (size_t)i1 * HIDN + lane * 4);
        float4 vs1 = ld_bf16x4(g_Vb + (size_t)s1 * HIDN + lane * 4);
        float4 vt1 = ld_bf16x4(g_tDPv + (size_t)i1 * HIDN + lane * 4);
        float sc0 = q4.x * (ks0.x + kt0.x) + q4.y * (ks0.y + kt0.y)
                  + q4.z * (ks0.z + kt0.z) + q4.w * (ks0.w + kt0.w);
        float sc1 = q4.x * (ks1.x + kt1.x) + q4.y * (ks1.y + kt1.y)
                  + q4.z * (ks1.z + kt1.z) + q4.w * (ks1.w + kt1.w);
        sc0 += __shfl_xor_sync(0xffffffffu, sc0, 1);
        sc1 += __shfl_xor_sync(0xffffffffu, sc1, 1);
        sc0 += __shfl_xor_sync(0xffffffffu, sc0, 2);
        sc1 += __shfl_xor_sync(0xffffffffu, sc1, 2);
        float w0 = __expf(sc0 * 0.25f);
        float w1 = __expf(sc1 * 0.25f);
        den += w0 + w1;
        ax += w0 * (vs0.x + vt0.x) + w1 * (vs1.x + vt1.x);
        ay += w0 * (vs0.y + vt0.y) + w1 * (vs1.y + vt1.y);
        az += w0 * (vs0.z + vt0.z) + w1 * (vs1.z + vt1.z);
        aw += w0 * (vs0.w + vt0.w) + w1 * (vs1.w + vt1.w);
    }
    if (p < end) {
        uint32_t e0 = g_edge[p];
        int s0 = (int)(e0 & 0xFFFFu), i0 = (int)(e0 >> 16);
        float4 ks0 = ld_bf16x4(g_Kb + (size_t)s0 * HIDN + lane * 4);
        float4 kt0 = ld_bf16x4(g_tDPk + (size_t)i0 * HIDN + lane * 4);
        float4 vs0 = ld_bf16x4(g_Vb + (size_t)s0 * HIDN + lane * 4);
        float4 vt0 = ld_bf16x4(g_tDPv + (size_t)i0 * HIDN + lane * 4);
        float sc0 = q4.x * (ks0.x + kt0.x) + q4.y * (ks0.y + kt0.y)
                  + q4.z * (ks0.z + kt0.z) + q4.w * (ks0.w + kt0.w);
        sc0 += __shfl_xor_sync(0xffffffffu, sc0, 1);
        sc0 += __shfl_xor_sync(0xffffffffu, sc0, 2);
        float w0 = __expf(sc0 * 0.25f);
        den += w0;
        ax += w0 * (vs0.x + vt0.x);
        ay += w0 * (vs0.y + vt0.y);
        az += w0 * (vs0.z + vt0.z);
        aw += w0 * (vs0.w + vt0.w);
    }
    if (half == 1) {
        float* dst = &part[(local * 32 + lane) * 5];
        dst[0] = den; dst[1] = ax; dst[2] = ay; dst[3] = az; dst[4] = aw;
    }
    __syncthreads();
    if (half == 0) {
        const float* src = &part[(local * 32 + lane) * 5];
        den += src[0]; ax += src[1]; ay += src[2]; az += src[3]; aw += src[4];
        float inv = 1.f / (den + 1e-16f);
        *(float4*)(g_aggr + (size_t)n * HIDN + lane * 4) =
            make_float4(ax * inv, ay * inv, az * inv, aw * inv);
    }
}

// ----------------------------- fused pool + readout -----------------------------
__global__ void pool_readout_kernel(const float* __restrict__ Wout, const float* __restrict__ bout,
                                    float* __restrict__ out) {
    int gi = blockIdx.x;
    int t = threadIdx.x;
    int s = g_goff[gi], e = g_goff[gi + 1];
    float acc = 0.f;
    for (int n = s; n < e; n++) acc += g_x[(size_t)n * HIDN + t];
    float cnt = fmaxf((float)(e - s), 1.f);
    float v = acc / cnt * Wout[t];
    for (int d = 16; d; d >>= 1) v += __shfl_xor_sync(0xffffffffu, v, d);
    __shared__ float sw[4];
    if ((t & 31) == 0) sw[t >> 5] = v;
    __syncthreads();
    if (t == 0) out[gi] = sw[0] + sw[1] + sw[2] + sw[3] + bout[0];
}

// ----------------------------- launch -----------------------------
extern "C" void kernel_launch(void* const* d_in, const int* in_sizes, int n_in,
                              void* d_out, int out_size) {
    const int*   node_attr = (const int*)d_in[0];
    const int*   batch_idx = (const int*)d_in[1];
    const int*   eidx      = (const int*)d_in[2];
    const int*   sdist     = (const int*)d_in[3];
    const int*   spath     = (const int*)d_in[4];
    const float* atom_emb  = (const float*)d_in[5];
    const float* dist_emb  = (const float*)d_in[6];
    const float* path_emb  = (const float*)d_in[7];
    const float* Wq = (const float*)d_in[8];
    const float* bq = (const float*)d_in[9];
    const float* Wk = (const float*)d_in[10];
    const float* bk = (const float*)d_in[11];
    const float* Wv = (const float*)d_in[12];
    const float* bv = (const float*)d_in[13];
    const float* Wa = (const float*)d_in[14];
    const float* ba = (const float*)d_in[15];
    const float* ln1g = (const float*)d_in[16];
    const float* ln1b = (const float*)d_in[17];
    const float* Wmid = (const float*)d_in[18];
    const float* bmid = (const float*)d_in[19];
    const float* Wo = (const float*)d_in[20];
    const float* bo = (const float*)d_in[21];
    const float* ln2g = (const float*)d_in[22];
    const float* ln2b = (const float*)d_in[23];
    const float* Wout = (const float*)d_in[24];
    const float* bout = (const float*)d_in[25];
    float* out = (float*)d_out;

    float *px, *pQ, *pag, *ph, *pcomb;
    __nv_bfloat16 *pKb, *pVb, *pDPk, *pDPv;
    uint32_t *pWh, *pWl;
    cudaGetSymbolAddress((void**)&px, g_x);
    cudaGetSymbolAddress((void**)&pQ, g_Q);
    cudaGetSymbolAddress((void**)&pKb, g_Kb);
    cudaGetSymbolAddress((void**)&pVb, g_Vb);
    cudaGetSymbolAddress((void**)&pag, g_aggr);
    cudaGetSymbolAddress((void**)&ph, g_h);
    cudaGetSymbolAddress((void**)&pcomb, g_comb);
    cudaGetSymbolAddress((void**)&pDPk, g_tDPk);
    cudaGetSymbolAddress((void**)&pDPv, g_tDPv);
    cudaGetSymbolAddress((void**)&pWh, g_wHi);
    cudaGetSymbolAddress((void**)&pWl, g_wLo);

    static bool attr_set = false;
    if (!attr_set) {
        cudaFuncSetAttribute(ffn_kernel, cudaFuncAttributeMaxDynamicSharedMemorySize, 100352);
        cudaFuncSetAttribute(gemm9_kernel<128, EPI_NODE, false>,
                             cudaFuncAttributeMaxDynamicSharedMemorySize, G8_SMEM);
        cudaFuncSetAttribute(gemm9_kernel<128, EPI_TBL, false>,
                             cudaFuncAttributeMaxDynamicSharedMemorySize, G8_SMEM);
        cudaFuncSetAttribute(gemm9_kernel<128, EPI_LN, true>,
                             cudaFuncAttributeMaxDynamicSharedMemorySize, G8_SMEM);
        attr_set = true;
    }

    const int* esrc = eidx;
    const int* etgt = eidx + EE;
    int grid128 = cdiv_h(NN, 128);

    // ---- launch #4 is the layer-0 QKV GEMM (profiled slot) ----
    zero_kernel<<<cdiv_h(NN, 256), 256>>>();                               // 1
    encoder_kernel<<<512, 128>>>(node_attr, atom_emb);                     // 2
    prepack_kernel<<<512, 256>>>(Wq, Wk, Wv, Wa, Wmid, Wo);                // 3
    gemm9_kernel<128, EPI_NODE, false><<<dim3(grid128, 3), 256, G8_SMEM>>>( // 4 <- profiled
        px, pWh + OFF_Q, pWl + OFF_Q, 12288, bq, nullptr,
        nullptr, nullptr, nullptr, pQ, pKb, pVb, NN);
    comb_kernel<<<128, 128>>>(dist_emb, path_emb);                         // 5
    gemm9_kernel<128, EPI_TBL, false><<<dim3(4, 2), 256, G8_SMEM>>>(       // 6
        pcomb, pWh + OFF_K, pWl + OFF_K, 12288, bk, bv,
        nullptr, nullptr, nullptr, nullptr, pDPk, pDPv, 512);
    count_kernel<<<cdiv_h(EE, 256), 256>>>(etgt, batch_idx);
    scan1_kernel<<<NBLK, 256>>>();
    scan2_kernel<<<1, 256>>>();
    scan3_kernel<<<NBLK, 256>>>();
    scatter_kernel<<<cdiv_h(EE, 256), 256>>>(esrc, etgt, sdist, spath);

    for (int l = 0; l < 2; l++) {
        const uint32_t* wh = pWh + (size_t)l * IMG_LAYER;
        const uint32_t* wl = pWl + (size_t)l * IMG_LAYER;

        if (l == 1) {
            comb_kernel<<<128, 128>>>(dist_emb + (size_t)l * 32 * 128,
                                      path_emb + (size_t)l * 16 * 128);
            gemm9_kernel<128, EPI_TBL, false><<<dim3(4, 2), 256, G8_SMEM>>>(
                pcomb, wh + OFF_K, wl + OFF_K, 12288, bk + l * 128, bv + l * 128,
                nullptr, nullptr, nullptr, nullptr, pDPk, pDPv, 512);
            gemm9_kernel<128, EPI_NODE, false><<<dim3(grid128, 3), 256, G8_SMEM>>>(
                px, wh + OFF_Q, wl + OFF_Q, 12288, bq + l * 128, nullptr,
                nullptr, nullptr, nullptr, pQ, pKb, pVb, NN);
        }

        edge_attn_kernel<<<NN / 4, 256>>>();

        // h = LN(gelu(aggr)@Wa + ba + x)
        gemm9_kernel<128, EPI_LN, true><<<dim3(grid128, 1), 256, G8_SMEM>>>(
            pag, wh + OFF_A, wl + OFF_A, 0, ba + l * 128, nullptr,
            px, ln1g + l * 128, ln1b + l * 128, ph, nullptr, nullptr, NN);
        // x = LN(gelu(h@Wmid+bmid)@Wo + bo + h)
        ffn_kernel<<<grid128, 256, 100352>>>(
            ph, wh, wl, bmid + l * 256, bo + l * 128,
            ln2g + l * 128, ln2b + l * 128, px, NN);
    }

    pool_readout_kernel<<<GG, 128>>>(Wout, bout, out);
}

// round 11
// speedup vs baseline: 1.0176x; 1.0176x over previous
#include <cuda_runtime.h>
#include <cuda_bf16.h>
#include <math.h>
#include <stdint.h>

#define NN 50000
#define EE 800000
#define HIDN 128
#define GG 256
#define NBLK 49    // ceil(NN/1024)
#define CHROW 400384  // 50048 rows * 8 words, per-chunk stride of the mid image

static inline int cdiv_h(int a, int b) { return (a + b - 1) / b; }

// ----------------------------- scratch (device globals) -----------------------------
__device__ float g_x[NN * HIDN];
__device__ float g_Q[NN * HIDN];
__device__ __nv_bfloat16 g_Kb[NN * HIDN];
__device__ __nv_bfloat16 g_Vb[NN * HIDN];
__device__ float g_aggr[NN * HIDN];
__device__ float g_h[NN * HIDN];
__device__ float g_comb[512 * HIDN];
__device__ __nv_bfloat16 g_tDPk[512 * HIDN];
__device__ __nv_bfloat16 g_tDPv[512 * HIDN];
__device__ uint32_t g_wHi[196608];   // prepacked weights (bf16 hi), smem-image layout
__device__ uint32_t g_wLo[196608];   // prepacked weights (bf16 lo residual)
__device__ uint32_t g_midH[16 * CHROW];  // FFN mid image (bf16 hi), chunk-major
__device__ uint32_t g_midL[16 * CHROW];  // FFN mid image (bf16 lo)
__device__ int   g_cnt[NN];
__device__ int   g_segoff[NN + 1];
__device__ int   g_cursor[NN];
__device__ uint32_t g_edge[EE];      // packed: src | (dp<<16)
__device__ int   g_bsum[64];
__device__ int   g_boff[64];
__device__ int   g_gcnt[GG];
__device__ int   g_goff[GG + 1];

// image layout constants (words): per layer 98304
#define IMG_LAYER 98304
#define OFF_Q 0
#define OFF_K 12288
#define OFF_V 24576
#define OFF_A 36864
#define OFF_M 49152
#define OFF_O 73728

// ----------------------------- helpers -----------------------------
__device__ __forceinline__ float gelu_f(float x) {
    return 0.5f * x * (1.0f + erff(x * 0.7071067811865476f));
}

__device__ __forceinline__ void mma_bf16(float c[4], const uint32_t a[4], const uint32_t b[2]) {
    asm volatile(
        "mma.sync.aligned.m16n8k16.row.col.f32.bf16.bf16.f32 "
        "{%0,%1,%2,%3}, {%4,%5,%6,%7}, {%8,%9}, {%0,%1,%2,%3};"
        : "+f"(c[0]), "+f"(c[1]), "+f"(c[2]), "+f"(c[3])
        : "r"(a[0]), "r"(a[1]), "r"(a[2]), "r"(a[3]), "r"(b[0]), "r"(b[1]));
}

__device__ __forceinline__ void pack_hl(float x, float y, uint32_t& hi, uint32_t& lo) {
    __nv_bfloat16 hx = __float2bfloat16(x);
    __nv_bfloat16 hy = __float2bfloat16(y);
    __nv_bfloat16 lx = __float2bfloat16(x - __bfloat162float(hx));
    __nv_bfloat16 ly = __float2bfloat16(y - __bfloat162float(hy));
    __nv_bfloat162 h2 = __halves2bfloat162(hx, hy);
    __nv_bfloat162 l2 = __halves2bfloat162(lx, ly);
    hi = *(uint32_t*)&h2;
    lo = *(uint32_t*)&l2;
}

__device__ __forceinline__ float4 ld_bf16x4(const __nv_bfloat16* p) {
    uint2 u = *(const uint2*)p;
    __nv_bfloat162 a = *(__nv_bfloat162*)&u.x;
    __nv_bfloat162 b = *(__nv_bfloat162*)&u.y;
    float2 fa = __bfloat1622float2(a), fb = __bfloat1622float2(b);
    return make_float4(fa.x, fa.y, fb.x, fb.y);
}

__device__ __forceinline__ uint32_t f2bf2(float a, float b) {
    __nv_bfloat162 t = __halves2bfloat162(__float2bfloat16(a), __float2bfloat16(b));
    return *(uint32_t*)&t;
}

// ----------------------------- misc kernels -----------------------------
__global__ void zero_kernel() {
    int i = blockIdx.x * blockDim.x + threadIdx.x;
    if (i < NN) g_cnt[i] = 0;
    if (i < GG) g_gcnt[i] = 0;
}

__global__ void encoder_kernel(const int* __restrict__ attr, const float* __restrict__ aemb) {
    int c = threadIdx.x;
    for (int n = blockIdx.x; n < NN; n += gridDim.x) {
        int a0 = attr[n * 4 + 0], a1 = attr[n * 4 + 1], a2 = attr[n * 4 + 2], a3 = attr[n * 4 + 3];
        float v = aemb[(0 * 64 + a0) * HIDN + c] + aemb[(1 * 64 + a1) * HIDN + c]
                + aemb[(2 * 64 + a2) * HIDN + c] + aemb[(3 * 64 + a3) * HIDN + c];
        g_x[(size_t)n * HIDN + c] = v;
    }
}

// prepack ALL weights into GEMM smem-image layout (bf16 hi/lo, kpair-packed, n-major, stride 12)
__global__ void prepack_kernel(const float* __restrict__ Wq, const float* __restrict__ Wk,
                               const float* __restrict__ Wv, const float* __restrict__ Wa,
                               const float* __restrict__ Wm, const float* __restrict__ Wo) {
    for (int id = blockIdx.x * blockDim.x + threadIdx.x; id < 131072;
         id += gridDim.x * blockDim.x) {
        int layer = id >> 16;
        int r = id & 65535;
        const float* W; int N; int segoff; int wi;
        if (r < 32768) {
            int m = r >> 13; wi = r & 8191;
            W = (m == 0 ? Wq : m == 1 ? Wk : m == 2 ? Wv : Wa) + layer * 16384;
            N = 128; segoff = m * 12288;
        } else if (r < 49152) {
            wi = r - 32768; W = Wm + layer * 32768; N = 256; segoff = OFF_M;
        } else {
            wi = r - 49152; W = Wo + layer * 32768; N = 128; segoff = OFF_O;
        }
        int ch = wi / (8 * N);
        int rem = wi % (8 * N);
        int kp = rem / N;
        int n = rem % N;
        int k = ch * 16 + kp * 2;
        float a = W[(size_t)k * N + n], b = W[(size_t)(k + 1) * N + n];
        uint32_t hi, lo;
        pack_hl(a, b, hi, lo);
        int w = layer * IMG_LAYER + segoff + ch * N * 12 + n * 12 + kp;
        g_wHi[w] = hi;
        g_wLo[w] = lo;
    }
}

__global__ void count_kernel(const int* __restrict__ tgt, const int* __restrict__ bidx) {
    int i = blockIdx.x * blockDim.x + threadIdx.x;
    if (i < EE) atomicAdd(&g_cnt[tgt[i]], 1);
    if (i < NN) atomicAdd(&g_gcnt[bidx[i]], 1);
}

__global__ void scan1_kernel() {
    __shared__ int sh[256];
    int blk = blockIdx.x, t = threadIdx.x;
    int idx4 = blk * 256 + t;
    int4 v4 = make_int4(0, 0, 0, 0);
    if (idx4 < NN / 4) v4 = ((const int4*)g_cnt)[idx4];
    int s = v4.x + v4.y + v4.z + v4.w;
    sh[t] = s;
    __syncthreads();
    for (int d = 1; d < 256; d <<= 1) {
        int v = (t >= d) ? sh[t - d] : 0;
        __syncthreads();
        sh[t] += v;
        __syncthreads();
    }
    int run = (t == 0) ? 0 : sh[t - 1];
    int base = blk * 1024 + t * 4;
    int vv[4] = {v4.x, v4.y, v4.z, v4.w};
    for (int j = 0; j < 4; j++) {
        if (base + j < NN) g_segoff[base + j] = run;
        run += vv[j];
    }
    if (t == 255) g_bsum[blk] = sh[255];
}

__global__ void scan2_kernel() {
    __shared__ int sg[256];
    __shared__ int sb[64];
    int t = threadIdx.x;
    sg[t] = g_gcnt[t];
    if (t < 64) sb[t] = (t < NBLK) ? g_bsum[t] : 0;
    __syncthreads();
    for (int d = 1; d < 256; d <<= 1) {
        int v = (t >= d) ? sg[t - d] : 0;
        int v2 = 0;
        if (t < 64 && t >= d && d < 64) v2 = sb[t - d];
        __syncthreads();
        sg[t] += v;
        if (t < 64 && d < 64) sb[t] += v2;
        __syncthreads();
    }
    g_goff[t + 1] = sg[t];
    if (t == 0) g_goff[0] = 0;
    if (t < 64) g_boff[t] = (t == 0) ? 0 : sb[t - 1];
}

__global__ void scan3_kernel() {
    int blk = blockIdx.x, t = threadIdx.x;
    int off = g_boff[blk];
    int base = blk * 1024 + t * 4;
    for (int j = 0; j < 4; j++) {
        int i = base + j;
        if (i < NN) {
            int v = g_segoff[i] + off;
            g_segoff[i] = v;
            g_cursor[i] = v;
        }
    }
    if (blk == 0 && t == 0) g_segoff[NN] = EE;
}

__global__ void scatter_kernel(const int* __restrict__ src, const int* __restrict__ tgt,
                               const int* __restrict__ sdist, const int* __restrict__ spath) {
    int i = blockIdx.x * blockDim.x + threadIdx.x;
    if (i < EE) {
        int tg = tgt[i];
        int pos = atomicAdd(&g_cursor[tg], 1);
        uint32_t dp = (uint32_t)((sdist[i] << 4) | spath[i]);
        g_edge[pos] = (uint32_t)src[i] | (dp << 16);
    }
}

__global__ void comb_kernel(const float* __restrict__ de, const float* __restrict__ pe) {
    int c = threadIdx.x;
    for (int r = blockIdx.x; r < 512; r += gridDim.x) {
        int d = r >> 4, p = r & 15;
        g_comb[r * HIDN + c] = de[d * HIDN + c] + pe[p * HIDN + c];
    }
}

// ------------------- GEMM (double-buffered; Bl only when needed; A from fp32 or image)
enum { EPI_LN = 2, EPI_NODE = 3, EPI_TBL = 4, EPI_MID = 5 };
#define G8_SMEM 51200

template <int KDIM, int EPI, bool GELU_A, bool A_IMG>
__global__ void __launch_bounds__(256) gemm9_kernel(
    const float* __restrict__ A,
    const uint32_t* __restrict__ BhGbase, const uint32_t* __restrict__ BlGbase,
    int yStride, int chB,
    uint32_t* __restrict__ AimgH, uint32_t* __restrict__ AimgL,
    const float* __restrict__ bias, const float* __restrict__ bias2,
    const float* __restrict__ res, const float* __restrict__ lng, const float* __restrict__ lnb,
    float* __restrict__ C, __nv_bfloat16* __restrict__ Cb, __nv_bfloat16* __restrict__ Cb2,
    int M)
{
    constexpr int TM = 128;
    constexpr int NC = 128;

    extern __shared__ uint32_t dyn[];
    uint32_t* AhB = dyn;             // 2 x 1536
    uint32_t* AlB = AhB + 3072;
    uint32_t* BhB = AlB + 3072;
    uint32_t* BlB = BhB + 3072;
    float2* redS = (float2*)(BlB + 3072);  // 128 x 2

    int tid = threadIdx.x;
    int wid = tid >> 5, lane = tid & 31;
    int g = lane >> 2, q = lane & 3;
    int wrow = (wid & 3) * 32;
    int wcol = (wid >> 2) * 64;
    int r0 = blockIdx.x * TM;

    const uint32_t* BhG = BhGbase + (size_t)blockIdx.y * yStride;
    const uint32_t* BlG = BlGbase + (size_t)blockIdx.y * yStride;
    const bool third = (EPI == EPI_NODE) ? (blockIdx.y == 0)
                                         : (EPI == EPI_LN || EPI == EPI_MID);

    const float* bs = bias;
    __nv_bfloat16* outb = Cb;
    if (EPI == EPI_NODE && blockIdx.y != 0) {
        bs = nullptr;
        outb = (blockIdx.y == 1) ? Cb : Cb2;
    }
    if (EPI == EPI_TBL && blockIdx.y == 1) { bs = bias2; outb = Cb2; }
    if (EPI == EPI_MID) bs = bias + blockIdx.y * 128;

    float acc[2][8][4];
#pragma unroll
    for (int a = 0; a < 2; a++)
#pragma unroll
        for (int b = 0; b < 8; b++)
#pragma unroll
            for (int c = 0; c < 4; c++) acc[a][b][c] = 0.f;

    float4 aS[2];
    uint4 aPh4, aPl4;
    uint2 bPh[3], bPl[3];
    int arow = tid >> 1, apart = (tid & 1) * 4;
    size_t abase = (size_t)(r0 + arow) * 8 + apart;

    // prologue: stage chunk 0
    if (A_IMG) {
        aPh4 = *(const uint4*)(AimgH + abase);
        aPl4 = *(const uint4*)(AimgL + abase);
    } else {
#pragma unroll
        for (int i = 0; i < 2; i++) {
            int j = tid + i * 256;
            int row = j >> 2, c4 = j & 3;
            int gr = r0 + row;
            aS[i] = (gr < M) ? *(const float4*)(A + (size_t)gr * KDIM + c4 * 4)
                             : make_float4(0.f, 0.f, 0.f, 0.f);
        }
    }
#pragma unroll
    for (int i = 0; i < 3; i++) bPh[i] = ((const uint2*)BhG)[tid + i * 256];
    if (third) {
#pragma unroll
        for (int i = 0; i < 3; i++) bPl[i] = ((const uint2*)BlG)[tid + i * 256];
    }

    constexpr int NCH = KDIM / 16;
#pragma unroll 1
    for (int c = 0; c < NCH; c++) {
        int p = c & 1;
        uint32_t* Ah = AhB + p * 1536;
        uint32_t* Al = AlB + p * 1536;
        uint32_t* Bh = BhB + p * 1536;
        uint32_t* Bl = BlB + p * 1536;

        // store staged -> smem[p]
        if (A_IMG) {
            *(uint4*)&Ah[arow * 12 + apart] = aPh4;
            *(uint4*)&Al[arow * 12 + apart] = aPl4;
        } else {
#pragma unroll
            for (int i = 0; i < 2; i++) {
                int j = tid + i * 256;
                int row = j >> 2, c4 = j & 3;
                float4 v = aS[i];
                if (GELU_A) { v.x = gelu_f(v.x); v.y = gelu_f(v.y); v.z = gelu_f(v.z); v.w = gelu_f(v.w); }
                uint32_t h01, l01, h23, l23;
                pack_hl(v.x, v.y, h01, l01);
                pack_hl(v.z, v.w, h23, l23);
                *(uint2*)&Ah[row * 12 + c4 * 2] = make_uint2(h01, h23);
                *(uint2*)&Al[row * 12 + c4 * 2] = make_uint2(l01, l23);
            }
        }
#pragma unroll
        for (int i = 0; i < 3; i++) ((uint2*)Bh)[tid + i * 256] = bPh[i];
        if (third) {
#pragma unroll
            for (int i = 0; i < 3; i++) ((uint2*)Bl)[tid + i * 256] = bPl[i];
        }
        __syncthreads();   // single barrier per chunk (double-buffer safe)

        // prefetch next chunk into registers
        if (c + 1 < NCH) {
            if (A_IMG) {
                size_t off = (size_t)(c + 1) * CHROW + abase;
                aPh4 = *(const uint4*)(AimgH + off);
                aPl4 = *(const uint4*)(AimgL + off);
            } else {
                int kn = (c + 1) * 16;
#pragma unroll
                for (int i = 0; i < 2; i++) {
                    int j = tid + i * 256;
                    int row = j >> 2, c4 = j & 3;
                    int gr = r0 + row;
                    aS[i] = (gr < M) ? *(const float4*)(A + (size_t)gr * KDIM + kn + c4 * 4)
                                     : make_float4(0.f, 0.f, 0.f, 0.f);
                }
            }
            int cb = (c + 1) * chB;
#pragma unroll
            for (int i = 0; i < 3; i++) bPh[i] = ((const uint2*)(BhG + cb))[tid + i * 256];
            if (third) {
#pragma unroll
                for (int i = 0; i < 3; i++) bPl[i] = ((const uint2*)(BlG + cb))[tid + i * 256];
            }
        }

        // fragments + mma (from buffer p)
        uint32_t ah[2][4], al[2][4];
#pragma unroll
        for (int mt = 0; mt < 2; mt++) {
            int r = wrow + mt * 16 + g;
            ah[mt][0] = Ah[r * 12 + q];     ah[mt][1] = Ah[(r + 8) * 12 + q];
            ah[mt][2] = Ah[r * 12 + q + 4]; ah[mt][3] = Ah[(r + 8) * 12 + q + 4];
            al[mt][0] = Al[r * 12 + q];     al[mt][1] = Al[(r + 8) * 12 + q];
            al[mt][2] = Al[r * 12 + q + 4]; al[mt][3] = Al[(r + 8) * 12 + q + 4];
        }
#pragma unroll
        for (int nt = 0; nt < 8; nt++) {
            int n = wcol + nt * 8 + g;
            uint32_t bh[2] = {Bh[n * 12 + q], Bh[n * 12 + q + 4]};
#pragma unroll
            for (int mt = 0; mt < 2; mt++) {
                mma_bf16(acc[mt][nt], ah[mt], bh);
                mma_bf16(acc[mt][nt], al[mt], bh);
            }
            if (third) {
                uint32_t bl[2] = {Bl[n * 12 + q], Bl[n * 12 + q + 4]};
#pragma unroll
                for (int mt = 0; mt < 2; mt++) mma_bf16(acc[mt][nt], ah[mt], bl);
            }
        }
    }
    __syncthreads();

    if (EPI == EPI_LN) {
        int wh = wcol >> 6;
        float s0[2] = {0, 0}, q0[2] = {0, 0}, s1[2] = {0, 0}, q1[2] = {0, 0};
#pragma unroll
        for (int mt = 0; mt < 2; mt++) {
            int ra = r0 + wrow + mt * 16 + g, rb = ra + 8;
#pragma unroll
            for (int nt = 0; nt < 8; nt++) {
                int col = wcol + nt * 8 + q * 2;
                float b0 = bias[col], b1 = bias[col + 1];
                float ra0 = (ra < M) ? res[(size_t)ra * NC + col] : 0.f;
                float ra1 = (ra < M) ? res[(size_t)ra * NC + col + 1] : 0.f;
                float rb0 = (rb < M) ? res[(size_t)rb * NC + col] : 0.f;
                float rb1 = (rb < M) ? res[(size_t)rb * NC + col + 1] : 0.f;
                float va0 = acc[mt][nt][0] + b0 + ra0;
                float va1 = acc[mt][nt][1] + b1 + ra1;
                float vb0 = acc[mt][nt][2] + b0 + rb0;
                float vb1 = acc[mt][nt][3] + b1 + rb1;
                acc[mt][nt][0] = va0; acc[mt][nt][1] = va1;
                acc[mt][nt][2] = vb0; acc[mt][nt][3] = vb1;
                s0[mt] += va0 + va1; q0[mt] += va0 * va0 + va1 * va1;
                s1[mt] += vb0 + vb1; q1[mt] += vb0 * vb0 + vb1 * vb1;
            }
        }
#pragma unroll
        for (int mt = 0; mt < 2; mt++) {
            s0[mt] += __shfl_xor_sync(0xffffffffu, s0[mt], 1);
            s0[mt] += __shfl_xor_sync(0xffffffffu, s0[mt], 2);
            q0[mt] += __shfl_xor_sync(0xffffffffu, q0[mt], 1);
            q0[mt] += __shfl_xor_sync(0xffffffffu, q0[mt], 2);
            s1[mt] += __shfl_xor_sync(0xffffffffu, s1[mt], 1);
            s1[mt] += __shfl_xor_sync(0xffffffffu, s1[mt], 2);
            q1[mt] += __shfl_xor_sync(0xffffffffu, q1[mt], 1);
            q1[mt] += __shfl_xor_sync(0xffffffffu, q1[mt], 2);
            if (q == 0) {
                redS[(wrow + mt * 16 + g) * 2 + wh] = make_float2(s0[mt], q0[mt]);
                redS[(wrow + mt * 16 + 8 + g) * 2 + wh] = make_float2(s1[mt], q1[mt]);
            }
        }
        __syncthreads();
#pragma unroll
        for (int mt = 0; mt < 2; mt++) {
            int lra = wrow + mt * 16 + g;
            float2 p0 = redS[lra * 2], p1 = redS[lra * 2 + 1];
            float2 p0b = redS[(lra + 8) * 2], p1b = redS[(lra + 8) * 2 + 1];
            float sa = p0.x + p1.x, qa = p0.y + p1.y;
            float sb = p0b.x + p1b.x, qb = p0b.y + p1b.y;
            float ma = sa * (1.f / 128.f), mb = sb * (1.f / 128.f);
            float rsa = rsqrtf(qa * (1.f / 128.f) - ma * ma + 1e-5f);
            float rsb = rsqrtf(qb * (1.f / 128.f) - mb * mb + 1e-5f);
            int ra = r0 + lra, rb = ra + 8;
#pragma unroll
            for (int nt = 0; nt < 8; nt++) {
                int col = wcol + nt * 8 + q * 2;
                float g0 = lng[col], g1 = lng[col + 1], o0 = lnb[col], o1 = lnb[col + 1];
                if (ra < M)
                    *(float2*)(C + (size_t)ra * NC + col) =
                        make_float2((acc[mt][nt][0] - ma) * rsa * g0 + o0,
                                    (acc[mt][nt][1] - ma) * rsa * g1 + o1);
                if (rb < M)
                    *(float2*)(C + (size_t)rb * NC + col) =
                        make_float2((acc[mt][nt][2] - mb) * rsb * g0 + o0,
                                    (acc[mt][nt][3] - mb) * rsb * g1 + o1);
            }
        }
    } else if (EPI == EPI_MID) {
#pragma unroll
        for (int mt = 0; mt < 2; mt++) {
            int ra = r0 + wrow + mt * 16 + g, rb = ra + 8;
#pragma unroll
            for (int nt = 0; nt < 8; nt++) {
                int col = wcol + nt * 8 + q * 2;
                float b0 = bs[col], b1 = bs[col + 1];
                float va0 = gelu_f(acc[mt][nt][0] + b0);
                float va1 = gelu_f(acc[mt][nt][1] + b1);
                float vb0 = gelu_f(acc[mt][nt][2] + b0);
                float vb1 = gelu_f(acc[mt][nt][3] + b1);
                int kpl = (wcol >> 1) + nt * 4 + q;       // 0..63
                int ch = ((int)blockIdx.y << 3) + (kpl >> 3);
                int kpin = kpl & 7;
                size_t base = (size_t)ch * CHROW + kpin;
                uint32_t hi, lo;
                if (ra < M) {
                    pack_hl(va0, va1, hi, lo);
                    AimgH[base + (size_t)ra * 8] = hi;
                    AimgL[base + (size_t)ra * 8] = lo;
                }
                if (rb < M) {
                    pack_hl(vb0, vb1, hi, lo);
                    AimgH[base + (size_t)rb * 8] = hi;
                    AimgL[base + (size_t)rb * 8] = lo;
                }
            }
        }
    } else if (EPI == EPI_NODE) {
#pragma unroll
        for (int mt = 0; mt < 2; mt++) {
            int ra = r0 + wrow + mt * 16 + g, rb = ra + 8;
#pragma unroll
            for (int nt = 0; nt < 8; nt++) {
                int col = wcol + nt * 8 + q * 2;
                float b0 = bs ? bs[col] : 0.f, b1 = bs ? bs[col + 1] : 0.f;
                float oa0 = acc[mt][nt][0] + b0, oa1 = acc[mt][nt][1] + b1;
                float ob0 = acc[mt][nt][2] + b0, ob1 = acc[mt][nt][3] + b1;
                if (blockIdx.y == 0) {
                    if (ra < M) *(float2*)(C + (size_t)ra * NC + col) = make_float2(oa0, oa1);
                    if (rb < M) *(float2*)(C + (size_t)rb * NC + col) = make_float2(ob0, ob1);
                } else {
                    if (ra < M) *(uint32_t*)(outb + (size_t)ra * NC + col) = f2bf2(oa0, oa1);
                    if (rb < M) *(uint32_t*)(outb + (size_t)rb * NC + col) = f2bf2(ob0, ob1);
                }
            }
        }
    } else {  // EPI_TBL
#pragma unroll
        for (int mt = 0; mt < 2; mt++) {
            int ra = r0 + wrow + mt * 16 + g, rb = ra + 8;
#pragma unroll
            for (int nt = 0; nt < 8; nt++) {
                int col = wcol + nt * 8 + q * 2;
                float b0 = bs[col], b1 = bs[col + 1];
                if (ra < M) *(uint32_t*)(outb + (size_t)ra * NC + col) =
                    f2bf2(acc[mt][nt][0] + b0, acc[mt][nt][1] + b1);
                if (rb < M) *(uint32_t*)(outb + (size_t)rb * NC + col) =
                    f2bf2(acc[mt][nt][2] + b0, acc[mt][nt][3] + b1);
            }
        }
    }
}

// ---------------- edge attention (R9 winner: warp per node, 2-edge unrolled) ---------
__global__ void __launch_bounds__(256) edge_attn_kernel() {
    int warp = threadIdx.x >> 5, lane = threadIdx.x & 31;
    int n = blockIdx.x * 8 + warp;
    if (n >= NN) return;
    int beg = g_segoff[n], end = g_segoff[n + 1];
    float4 q4 = *(const float4*)(g_Q + (size_t)n * HIDN + lane * 4);
    float den = 0.f, ax = 0.f, ay = 0.f, az = 0.f, aw = 0.f;
    int p = beg;
    for (; p + 2 <= end; p += 2) {
        uint32_t e0 = g_edge[p], e1 = g_edge[p + 1];
        int s0 = (int)(e0 & 0xFFFFu), i0 = (int)(e0 >> 16);
        int s1 = (int)(e1 & 0xFFFFu), i1 = (int)(e1 >> 16);
        float4 ks0 = ld_bf16x4(g_Kb + (size_t)s0 * HIDN + lane * 4);
        float4 kt0 = ld_bf16x4(g_tDPk + (size_t)i0 * HIDN + lane * 4);
        float4 vs0 = ld_bf16x4(g_Vb + (size_t)s0 * HIDN + lane * 4);
        float4 vt0 = ld_bf16x4(g_tDPv + (size_t)i0 * HIDN + lane * 4);
        float4 ks1 = ld_bf16x4(g_Kb + (size_t)s1 * HIDN + lane * 4);
        float4 kt1 = ld_bf16x4(g_tDPk + (size_t)i1 * HIDN + lane * 4);
        float4 vs1 = ld_bf16x4(g_Vb + (size_t)s1 * HIDN + lane * 4);
        float4 vt1 = ld_bf16x4(g_tDPv + (size_t)i1 * HIDN + lane * 4);
        float sc0 = q4.x * (ks0.x + kt0.x) + q4.y * (ks0.y + kt0.y)
                  + q4.z * (ks0.z + kt0.z) + q4.w * (ks0.w + kt0.w);
        float sc1 = q4.x * (ks1.x + kt1.x) + q4.y * (ks1.y + kt1.y)
                  + q4.z * (ks1.z + kt1.z) + q4.w * (ks1.w + kt1.w);
        sc0 += __shfl_xor_sync(0xffffffffu, sc0, 1);
        sc1 += __shfl_xor_sync(0xffffffffu, sc1, 1);
        sc0 += __shfl_xor_sync(0xffffffffu, sc0, 2);
        sc1 += __shfl_xor_sync(0xffffffffu, sc1, 2);
        float w0 = __expf(sc0 * 0.25f);
        float w1 = __expf(sc1 * 0.25f);
        den += w0 + w1;
        ax += w0 * (vs0.x + vt0.x) + w1 * (vs1.x + vt1.x);
        ay += w0 * (vs0.y + vt0.y) + w1 * (vs1.y + vt1.y);
        az += w0 * (vs0.z + vt0.z) + w1 * (vs1.z + vt1.z);
        aw += w0 * (vs0.w + vt0.w) + w1 * (vs1.w + vt1.w);
    }
    if (p < end) {
        uint32_t e0 = g_edge[p];
        int s0 = (int)(e0 & 0xFFFFu), i0 = (int)(e0 >> 16);
        float4 ks0 = ld_bf16x4(g_Kb + (size_t)s0 * HIDN + lane * 4);
        float4 kt0 = ld_bf16x4(g_tDPk + (size_t)i0 * HIDN + lane * 4);
        float4 vs0 = ld_bf16x4(g_Vb + (size_t)s0 * HIDN + lane * 4);
        float4 vt0 = ld_bf16x4(g_tDPv + (size_t)i0 * HIDN + lane * 4);
        float sc0 = q4.x * (ks0.x + kt0.x) + q4.y * (ks0.y + kt0.y)
                  + q4.z * (ks0.z + kt0.z) + q4.w * (ks0.w + kt0.w);
        sc0 += __shfl_xor_sync(0xffffffffu, sc0, 1);
        sc0 += __shfl_xor_sync(0xffffffffu, sc0, 2);
        float w0 = __expf(sc0 * 0.25f);
        den += w0;
        ax += w0 * (vs0.x + vt0.x);
        ay += w0 * (vs0.y + vt0.y);
        az += w0 * (vs0.z + vt0.z);
        aw += w0 * (vs0.w + vt0.w);
    }
    float inv = 1.f / (den + 1e-16f);
    *(float4*)(g_aggr + (size_t)n * HIDN + lane * 4) =
        make_float4(ax * inv, ay * inv, az * inv, aw * inv);
}

// ----------------------------- fused pool + readout -----------------------------
__global__ void pool_readout_kernel(const float* __restrict__ Wout, const float* __restrict__ bout,
                                    float* __restrict__ out) {
    int gi = blockIdx.x;
    int t = threadIdx.x;
    int s = g_goff[gi], e = g_goff[gi + 1];
    float acc = 0.f;
    for (int n = s; n < e; n++) acc += g_x[(size_t)n * HIDN + t];
    float cnt = fmaxf((float)(e - s), 1.f);
    float v = acc / cnt * Wout[t];
    for (int d = 16; d; d >>= 1) v += __shfl_xor_sync(0xffffffffu, v, d);
    __shared__ float sw[4];
    if ((t & 31) == 0) sw[t >> 5] = v;
    __syncthreads();
    if (t == 0) out[gi] = sw[0] + sw[1] + sw[2] + sw[3] + bout[0];
}

// ----------------------------- launch -----------------------------
extern "C" void kernel_launch(void* const* d_in, const int* in_sizes, int n_in,
                              void* d_out, int out_size) {
    const int*   node_attr = (const int*)d_in[0];
    const int*   batch_idx = (const int*)d_in[1];
    const int*   eidx      = (const int*)d_in[2];
    const int*   sdist     = (const int*)d_in[3];
    const int*   spath     = (const int*)d_in[4];
    const float* atom_emb  = (const float*)d_in[5];
    const float* dist_emb  = (const float*)d_in[6];
    const float* path_emb  = (const float*)d_in[7];
    const float* Wq = (const float*)d_in[8];
    const float* bq = (const float*)d_in[9];
    const float* Wk = (const float*)d_in[10];
    const float* bk = (const float*)d_in[11];
    const float* Wv = (const float*)d_in[12];
    const float* bv = (const float*)d_in[13];
    const float* Wa = (const float*)d_in[14];
    const float* ba = (const float*)d_in[15];
    const float* ln1g = (const float*)d_in[16];
    const float* ln1b = (const float*)d_in[17];
    const float* Wmid = (const float*)d_in[18];
    const float* bmid = (const float*)d_in[19];
    const float* Wo = (const float*)d_in[20];
    const float* bo = (const float*)d_in[21];
    const float* ln2g = (const float*)d_in[22];
    const float* ln2b = (const float*)d_in[23];
    const float* Wout = (const float*)d_in[24];
    const float* bout = (const float*)d_in[25];
    float* out = (float*)d_out;

    float *px, *pQ, *pag, *ph, *pcomb;
    __nv_bfloat16 *pKb, *pVb, *pDPk, *pDPv;
    uint32_t *pWh, *pWl, *pMh, *pMl;
    cudaGetSymbolAddress((void**)&px, g_x);
    cudaGetSymbolAddress((void**)&pQ, g_Q);
    cudaGetSymbolAddress((void**)&pKb, g_Kb);
    cudaGetSymbolAddress((void**)&pVb, g_Vb);
    cudaGetSymbolAddress((void**)&pag, g_aggr);
    cudaGetSymbolAddress((void**)&ph, g_h);
    cudaGetSymbolAddress((void**)&pcomb, g_comb);
    cudaGetSymbolAddress((void**)&pDPk, g_tDPk);
    cudaGetSymbolAddress((void**)&pDPv, g_tDPv);
    cudaGetSymbolAddress((void**)&pWh, g_wHi);
    cudaGetSymbolAddress((void**)&pWl, g_wLo);
    cudaGetSymbolAddress((void**)&pMh, g_midH);
    cudaGetSymbolAddress((void**)&pMl, g_midL);

    static bool attr_set = false;
    if (!attr_set) {
        cudaFuncSetAttribute(gemm9_kernel<128, EPI_NODE, false, false>,
                             cudaFuncAttributeMaxDynamicSharedMemorySize, G8_SMEM);
        cudaFuncSetAttribute(gemm9_kernel<128, EPI_TBL, false, false>,
                             cudaFuncAttributeMaxDynamicSharedMemorySize, G8_SMEM);
        cudaFuncSetAttribute(gemm9_kernel<128, EPI_LN, true, false>,
                             cudaFuncAttributeMaxDynamicSharedMemorySize, G8_SMEM);
        cudaFuncSetAttribute(gemm9_kernel<128, EPI_MID, false, false>,
                             cudaFuncAttributeMaxDynamicSharedMemorySize, G8_SMEM);
        cudaFuncSetAttribute(gemm9_kernel<256, EPI_LN, false, true>,
                             cudaFuncAttributeMaxDynamicSharedMemorySize, G8_SMEM);
        attr_set = true;
    }

    const int* esrc = eidx;
    const int* etgt = eidx + EE;
    int grid128 = cdiv_h(NN, 128);

    // ---- launch #4 is the layer-0 QKV GEMM (profiled slot) ----
    zero_kernel<<<cdiv_h(NN, 256), 256>>>();                               // 1
    encoder_kernel<<<512, 128>>>(node_attr, atom_emb);                     // 2
    prepack_kernel<<<512, 256>>>(Wq, Wk, Wv, Wa, Wmid, Wo);                // 3
    gemm9_kernel<128, EPI_NODE, false, false><<<dim3(grid128, 3), 256, G8_SMEM>>>( // 4
        px, pWh + OFF_Q, pWl + OFF_Q, 12288, 1536, nullptr, nullptr, bq, nullptr,
        nullptr, nullptr, nullptr, pQ, pKb, pVb, NN);
    comb_kernel<<<128, 128>>>(dist_emb, path_emb);                         // 5
    gemm9_kernel<128, EPI_TBL, false, false><<<dim3(4, 2), 256, G8_SMEM>>>( // 6
        pcomb, pWh + OFF_K, pWl + OFF_K, 12288, 1536, nullptr, nullptr, bk, bv,
        nullptr, nullptr, nullptr, nullptr, pDPk, pDPv, 512);
    count_kernel<<<cdiv_h(EE, 256), 256>>>(etgt, batch_idx);
    scan1_kernel<<<NBLK, 256>>>();
    scan2_kernel<<<1, 256>>>();
    scan3_kernel<<<NBLK, 256>>>();
    scatter_kernel<<<cdiv_h(EE, 256), 256>>>(esrc, etgt, sdist, spath);

    for (int l = 0; l < 2; l++) {
        const uint32_t* wh = pWh + (size_t)l * IMG_LAYER;
        const uint32_t* wl = pWl + (size_t)l * IMG_LAYER;

        if (l == 1) {
            comb_kernel<<<128, 128>>>(dist_emb + (size_t)l * 32 * 128,
                                      path_emb + (size_t)l * 16 * 128);
            gemm9_kernel<128, EPI_TBL, false, false><<<dim3(4, 2), 256, G8_SMEM>>>(
                pcomb, wh + OFF_K, wl + OFF_K, 12288, 1536, nullptr, nullptr,
                bk + l * 128, bv + l * 128,
                nullptr, nullptr, nullptr, nullptr, pDPk, pDPv, 512);
            gemm9_kernel<128, EPI_NODE, false, false><<<dim3(grid128, 3), 256, G8_SMEM>>>(
                px, wh + OFF_Q, wl + OFF_Q, 12288, 1536, nullptr, nullptr,
                bq + l * 128, nullptr,
                nullptr, nullptr, nullptr, pQ, pKb, pVb, NN);
        }

        edge_attn_kernel<<<cdiv_h(NN, 8), 256>>>();

        // h = LN(gelu(aggr)@Wa + ba + x)
        gemm9_kernel<128, EPI_LN, true, false><<<dim3(grid128, 1), 256, G8_SMEM>>>(
            pag, wh + OFF_A, wl + OFF_A, 0, 1536, nullptr, nullptr, ba + l * 128, nullptr,
            px, ln1g + l * 128, ln1b + l * 128, ph, nullptr, nullptr, NN);
        // mid = gelu(h@Wmid + bmid) -> global bf16 hi/lo image (chunk-major)
        gemm9_kernel<128, EPI_MID, false, false><<<dim3(grid128, 2), 256, G8_SMEM>>>(
            ph, wh + OFF_M, wl + OFF_M, 1536, 3072, pMh, pMl, bmid + l * 256, nullptr,
            nullptr, nullptr, nullptr, nullptr, nullptr, nullptr, NN);
        // x = LN(mid@Wo + bo + h), A streamed from the mid image (pure memcpy staging)
        gemm9_kernel<256, EPI_LN, false, true><<<dim3(grid128, 1), 256, G8_SMEM>>>(
            nullptr, wh + OFF_O, wl + OFF_O, 0, 1536, pMh, pMl, bo + l * 128, nullptr,
            ph, ln2g + l * 128, ln2b + l * 128, px, nullptr, nullptr, NN);
    }

    pool_readout_kernel<<<GG, 128>>>(Wout, bout, out);
}

// round 12
// speedup vs baseline: 1.0265x; 1.0088x over previous
#include <cuda_runtime.h>
#include <cuda_bf16.h>
#include <math.h>
#include <stdint.h>

#define NN 50000
#define EE 800000
#define HIDN 128
#define GG 256
#define NBLK 49    // ceil(NN/1024)
#define CHROW 400384  // 50048 rows * 8 words, per-chunk stride of the mid image

static inline int cdiv_h(int a, int b) { return (a + b - 1) / b; }

// ----------------------------- scratch (device globals) -----------------------------
__device__ float g_x[NN * HIDN];
__device__ float g_Q[NN * HIDN];
__device__ __nv_bfloat16 g_Kb[NN * HIDN];
__device__ __nv_bfloat16 g_Vb[NN * HIDN];
__device__ float g_aggr[NN * HIDN];
__device__ float g_h[NN * HIDN];
__device__ float g_comb2[2 * 512 * HIDN];
__device__ __nv_bfloat16 g_tDPk[2 * 512 * HIDN];
__device__ __nv_bfloat16 g_tDPv[2 * 512 * HIDN];
__device__ uint32_t g_wHi[196608];   // prepacked weights (bf16 hi), smem-image layout
__device__ uint32_t g_wLo[196608];   // prepacked weights (bf16 lo residual)
__device__ uint32_t g_midH[16 * CHROW];  // FFN mid image (bf16 hi), chunk-major
__device__ uint32_t g_midL[16 * CHROW];  // FFN mid image (bf16 lo)
__device__ int   g_cnt[NN];
__device__ int   g_segoff[NN + 1];
__device__ int   g_cursor[NN];
__device__ uint32_t g_edge[EE];      // packed: src | (dp<<16)
__device__ int   g_bsum[64];
__device__ int   g_boff[64];
__device__ int   g_gcnt[GG];
__device__ int   g_goff[GG + 1];

// image layout constants (words): per layer 98304
#define IMG_LAYER 98304
#define OFF_Q 0
#define OFF_K 12288
#define OFF_V 24576
#define OFF_A 36864
#define OFF_M 49152
#define OFF_O 73728

// ----------------------------- helpers -----------------------------
__device__ __forceinline__ float gelu_f(float x) {
    return 0.5f * x * (1.0f + erff(x * 0.7071067811865476f));
}

__device__ __forceinline__ void mma_bf16(float c[4], const uint32_t a[4], const uint32_t b[2]) {
    asm volatile(
        "mma.sync.aligned.m16n8k16.row.col.f32.bf16.bf16.f32 "
        "{%0,%1,%2,%3}, {%4,%5,%6,%7}, {%8,%9}, {%0,%1,%2,%3};"
        : "+f"(c[0]), "+f"(c[1]), "+f"(c[2]), "+f"(c[3])
        : "r"(a[0]), "r"(a[1]), "r"(a[2]), "r"(a[3]), "r"(b[0]), "r"(b[1]));
}

__device__ __forceinline__ void pack_hl(float x, float y, uint32_t& hi, uint32_t& lo) {
    __nv_bfloat16 hx = __float2bfloat16(x);
    __nv_bfloat16 hy = __float2bfloat16(y);
    __nv_bfloat16 lx = __float2bfloat16(x - __bfloat162float(hx));
    __nv_bfloat16 ly = __float2bfloat16(y - __bfloat162float(hy));
    __nv_bfloat162 h2 = __halves2bfloat162(hx, hy);
    __nv_bfloat162 l2 = __halves2bfloat162(lx, ly);
    hi = *(uint32_t*)&h2;
    lo = *(uint32_t*)&l2;
}

__device__ __forceinline__ float4 ld_bf16x4(const __nv_bfloat16* p) {
    uint2 u = *(const uint2*)p;
    __nv_bfloat162 a = *(__nv_bfloat162*)&u.x;
    __nv_bfloat162 b = *(__nv_bfloat162*)&u.y;
    float2 fa = __bfloat1622float2(a), fb = __bfloat1622float2(b);
    return make_float4(fa.x, fa.y, fb.x, fb.y);
}

__device__ __forceinline__ uint32_t f2bf2(float a, float b) {
    __nv_bfloat162 t = __halves2bfloat162(__float2bfloat16(a), __float2bfloat16(b));
    return *(uint32_t*)&t;
}

__device__ __forceinline__ void cp_a16(uint32_t s, const void* g) {
    asm volatile("cp.async.ca.shared.global [%0], [%1], 16;" :: "r"(s), "l"(g));
}
__device__ __forceinline__ void cp_a8(uint32_t s, const void* g) {
    asm volatile("cp.async.ca.shared.global [%0], [%1], 8;" :: "r"(s), "l"(g));
}
#define CP_COMMIT() asm volatile("cp.async.commit_group;" ::: "memory")
#define CP_WAIT1()  asm volatile("cp.async.wait_group 1;" ::: "memory")
#define CP_WAIT0()  asm volatile("cp.async.wait_group 0;" ::: "memory")

// ----------------------------- misc kernels -----------------------------
__global__ void zero_kernel() {
    int i = blockIdx.x * blockDim.x + threadIdx.x;
    if (i < NN) g_cnt[i] = 0;
    if (i < GG) g_gcnt[i] = 0;
}

__global__ void encoder_kernel(const int* __restrict__ attr, const float* __restrict__ aemb) {
    int c = threadIdx.x;
    for (int n = blockIdx.x; n < NN; n += gridDim.x) {
        int a0 = attr[n * 4 + 0], a1 = attr[n * 4 + 1], a2 = attr[n * 4 + 2], a3 = attr[n * 4 + 3];
        float v = aemb[(0 * 64 + a0) * HIDN + c] + aemb[(1 * 64 + a1) * HIDN + c]
                + aemb[(2 * 64 + a2) * HIDN + c] + aemb[(3 * 64 + a3) * HIDN + c];
        g_x[(size_t)n * HIDN + c] = v;
    }
}

// prepack ALL weights into GEMM smem-image layout (bf16 hi/lo, kpair-packed, n-major, stride 12)
__global__ void prepack_kernel(const float* __restrict__ Wq, const float* __restrict__ Wk,
                               const float* __restrict__ Wv, const float* __restrict__ Wa,
                               const float* __restrict__ Wm, const float* __restrict__ Wo) {
    for (int id = blockIdx.x * blockDim.x + threadIdx.x; id < 131072;
         id += gridDim.x * blockDim.x) {
        int layer = id >> 16;
        int r = id & 65535;
        const float* W; int N; int segoff; int wi;
        if (r < 32768) {
            int m = r >> 13; wi = r & 8191;
            W = (m == 0 ? Wq : m == 1 ? Wk : m == 2 ? Wv : Wa) + layer * 16384;
            N = 128; segoff = m * 12288;
        } else if (r < 49152) {
            wi = r - 32768; W = Wm + layer * 32768; N = 256; segoff = OFF_M;
        } else {
            wi = r - 49152; W = Wo + layer * 32768; N = 128; segoff = OFF_O;
        }
        int ch = wi / (8 * N);
        int rem = wi % (8 * N);
        int kp = rem / N;
        int n = rem % N;
        int k = ch * 16 + kp * 2;
        float a = W[(size_t)k * N + n], b = W[(size_t)(k + 1) * N + n];
        uint32_t hi, lo;
        pack_hl(a, b, hi, lo);
        int w = layer * IMG_LAYER + segoff + ch * N * 12 + n * 12 + kp;
        g_wHi[w] = hi;
        g_wLo[w] = lo;
    }
}

__global__ void count_kernel(const int* __restrict__ tgt, const int* __restrict__ bidx) {
    int i = blockIdx.x * blockDim.x + threadIdx.x;
    if (i < EE) atomicAdd(&g_cnt[tgt[i]], 1);
    if (i < NN) atomicAdd(&g_gcnt[bidx[i]], 1);
}

__global__ void scan1_kernel() {
    __shared__ int sh[256];
    int blk = blockIdx.x, t = threadIdx.x;
    int idx4 = blk * 256 + t;
    int4 v4 = make_int4(0, 0, 0, 0);
    if (idx4 < NN / 4) v4 = ((const int4*)g_cnt)[idx4];
    int s = v4.x + v4.y + v4.z + v4.w;
    sh[t] = s;
    __syncthreads();
    for (int d = 1; d < 256; d <<= 1) {
        int v = (t >= d) ? sh[t - d] : 0;
        __syncthreads();
        sh[t] += v;
        __syncthreads();
    }
    int run = (t == 0) ? 0 : sh[t - 1];
    int base = blk * 1024 + t * 4;
    int vv[4] = {v4.x, v4.y, v4.z, v4.w};
    for (int j = 0; j < 4; j++) {
        if (base + j < NN) g_segoff[base + j] = run;
        run += vv[j];
    }
    if (t == 255) g_bsum[blk] = sh[255];
}

__global__ void scan2_kernel() {
    __shared__ int sg[256];
    __shared__ int sb[64];
    int t = threadIdx.x;
    sg[t] = g_gcnt[t];
    if (t < 64) sb[t] = (t < NBLK) ? g_bsum[t] : 0;
    __syncthreads();
    for (int d = 1; d < 256; d <<= 1) {
        int v = (t >= d) ? sg[t - d] : 0;
        int v2 = 0;
        if (t < 64 && t >= d && d < 64) v2 = sb[t - d];
        __syncthreads();
        sg[t] += v;
        if (t < 64 && d < 64) sb[t] += v2;
        __syncthreads();
    }
    g_goff[t + 1] = sg[t];
    if (t == 0) g_goff[0] = 0;
    if (t < 64) g_boff[t] = (t == 0) ? 0 : sb[t - 1];
}

__global__ void scan3_kernel() {
    int blk = blockIdx.x, t = threadIdx.x;
    int off = g_boff[blk];
    int base = blk * 1024 + t * 4;
    for (int j = 0; j < 4; j++) {
        int i = base + j;
        if (i < NN) {
            int v = g_segoff[i] + off;
            g_segoff[i] = v;
            g_cursor[i] = v;
        }
    }
    if (blk == 0 && t == 0) g_segoff[NN] = EE;
}

__global__ void scatter_kernel(const int* __restrict__ src, const int* __restrict__ tgt,
                               const int* __restrict__ sdist, const int* __restrict__ spath) {
    int i = blockIdx.x * blockDim.x + threadIdx.x;
    if (i < EE) {
        int tg = tgt[i];
        int pos = atomicAdd(&g_cursor[tg], 1);
        uint32_t dp = (uint32_t)((sdist[i] << 4) | spath[i]);
        g_edge[pos] = (uint32_t)src[i] | (dp << 16);
    }
}

// combine dist+path embeddings for BOTH layers
__global__ void comb2_kernel(const float* __restrict__ de, const float* __restrict__ pe) {
    int c = threadIdx.x;
    for (int r = blockIdx.x; r < 1024; r += gridDim.x) {
        int l = r >> 9;
        int rr = r & 511;
        int d = rr >> 4, p = rr & 15;
        g_comb2[r * HIDN + c] = de[(l * 32 + d) * HIDN + c] + pe[(l * 16 + p) * HIDN + c];
    }
}

// ------------- GEMM (double-buffered A, cp.async 3-ring B, Bl only when needed) -------
enum { EPI_LN = 2, EPI_NODE = 3, EPI_TBL = 4, EPI_MID = 5 };
#define G10_SMEM 64512

template <int KDIM, int EPI, bool GELU_A, bool A_IMG>
__global__ void __launch_bounds__(256) gemm10_kernel(
    const float* __restrict__ Ain,
    const uint32_t* __restrict__ BhGbase, const uint32_t* __restrict__ BlGbase,
    int yStride, int chB,
    uint32_t* __restrict__ AimgH, uint32_t* __restrict__ AimgL,
    const float* __restrict__ bias, const float* __restrict__ bias2,
    const float* __restrict__ res, const float* __restrict__ lng, const float* __restrict__ lnb,
    float* __restrict__ C, __nv_bfloat16* __restrict__ Cb, __nv_bfloat16* __restrict__ Cb2,
    int M)
{
    constexpr int TM = 128;
    constexpr int NC = 128;

    extern __shared__ uint32_t dyn[];
    uint32_t* AhB = dyn;              // 2 x 1536
    uint32_t* AlB = AhB + 3072;       // 2 x 1536
    uint32_t* BhR = AlB + 3072;       // 3 x 1536
    uint32_t* BlR = BhR + 4608;       // 3 x 1536
    float2* redS = (float2*)(BlR + 4608);  // 128 x 2

    int tid = threadIdx.x;
    int wid = tid >> 5, lane = tid & 31;
    int g = lane >> 2, q = lane & 3;
    int wrow = (wid & 3) * 32;
    int wcol = (wid >> 2) * 64;
    int r0 = blockIdx.x * TM;

    const float* A = Ain;
    const uint32_t* BhG;
    const uint32_t* BlG;
    const float* bs = bias;
    __nv_bfloat16* outb = Cb;
    bool third;
    if (EPI == EPI_TBL) {
        int layer = blockIdx.y >> 1, kv = blockIdx.y & 1;
        size_t off = (size_t)layer * IMG_LAYER + kv * 12288;
        BhG = BhGbase + off;
        BlG = BlGbase + off;
        A = Ain + (size_t)layer * 65536;
        bs = (kv ? bias2 : bias) + layer * 128;
        outb = (kv ? Cb2 : Cb) + (size_t)layer * 65536;
        third = false;
    } else {
        BhG = BhGbase + (size_t)blockIdx.y * yStride;
        BlG = BlGbase + (size_t)blockIdx.y * yStride;
        third = (EPI == EPI_NODE) ? (blockIdx.y == 0) : (EPI == EPI_LN || EPI == EPI_MID);
        if (EPI == EPI_NODE && blockIdx.y != 0) {
            bs = nullptr;
            outb = (blockIdx.y == 1) ? Cb : Cb2;
        }
        if (EPI == EPI_MID) bs = bias + blockIdx.y * 128;
    }

    uint32_t shBh = (uint32_t)__cvta_generic_to_shared(BhR);
    uint32_t shBl = (uint32_t)__cvta_generic_to_shared(BlR);

    float acc[2][8][4];
#pragma unroll
    for (int a = 0; a < 2; a++)
#pragma unroll
        for (int b = 0; b < 8; b++)
#pragma unroll
            for (int c = 0; c < 4; c++) acc[a][b][c] = 0.f;

    float4 aS[2];
    uint4 aPh4, aPl4;
    int arow = tid >> 1, apart = (tid & 1) * 4;
    size_t abase = (size_t)(r0 + arow) * 8 + apart;

    // per-thread cp.async assignments: 16B at tid*16 (first 4KB), 8B at 4096+tid*8 (last 2KB)
    int cpo16 = tid * 16;
    int cpo8 = 4096 + tid * 8;

    // prologue: issue B chunk 0 -> ring slot 0; stage A chunk 0 -> regs
    {
        cp_a16(shBh + cpo16, (const uint8_t*)BhG + cpo16);
        cp_a8(shBh + cpo8, (const uint8_t*)BhG + cpo8);
        if (third) {
            cp_a16(shBl + cpo16, (const uint8_t*)BlG + cpo16);
            cp_a8(shBl + cpo8, (const uint8_t*)BlG + cpo8);
        }
        CP_COMMIT();
    }
    if (A_IMG) {
        aPh4 = *(const uint4*)(AimgH + abase);
        aPl4 = *(const uint4*)(AimgL + abase);
    } else {
#pragma unroll
        for (int i = 0; i < 2; i++) {
            int j = tid + i * 256;
            int row = j >> 2, c4 = j & 3;
            int gr = r0 + row;
            aS[i] = (gr < M) ? *(const float4*)(A + (size_t)gr * KDIM + c4 * 4)
                             : make_float4(0.f, 0.f, 0.f, 0.f);
        }
    }

    constexpr int NCH = KDIM / 16;
#pragma unroll 1
    for (int c = 0; c < NCH; c++) {
        int p = c & 1;
        int br = c % 3;
        uint32_t* Ah = AhB + p * 1536;
        uint32_t* Al = AlB + p * 1536;
        uint32_t* Bh = BhR + br * 1536;
        uint32_t* Bl = BlR + br * 1536;

        // store staged A -> smem[p] (safe: after barrier(c-1), readers of p done pre-barrier)
        if (A_IMG) {
            *(uint4*)&Ah[arow * 12 + apart] = aPh4;
            *(uint4*)&Al[arow * 12 + apart] = aPl4;
        } else {
#pragma unroll
            for (int i = 0; i < 2; i++) {
                int j = tid + i * 256;
                int row = j >> 2, c4 = j & 3;
                float4 v = aS[i];
                if (GELU_A) { v.x = gelu_f(v.x); v.y = gelu_f(v.y); v.z = gelu_f(v.z); v.w = gelu_f(v.w); }
                uint32_t h01, l01, h23, l23;
                pack_hl(v.x, v.y, h01, l01);
                pack_hl(v.z, v.w, h23, l23);
                *(uint2*)&Ah[row * 12 + c4 * 2] = make_uint2(h01, h23);
                *(uint2*)&Al[row * 12 + c4 * 2] = make_uint2(l01, l23);
            }
        }

        // issue B chunk c+1 into ring slot (c+1)%3; prefetch A c+1 into regs
        if (c + 1 < NCH) {
            int bn = (c + 1) % 3;
            const uint8_t* srcH = (const uint8_t*)(BhG + (size_t)(c + 1) * chB);
            uint32_t dstH = shBh + bn * 6144;
            cp_a16(dstH + cpo16, srcH + cpo16);
            cp_a8(dstH + cpo8, srcH + cpo8);
            if (third) {
                const uint8_t* srcL = (const uint8_t*)(BlG + (size_t)(c + 1) * chB);
                uint32_t dstL = shBl + bn * 6144;
                cp_a16(dstL + cpo16, srcL + cpo16);
                cp_a8(dstL + cpo8, srcL + cpo8);
            }
            CP_COMMIT();
            if (A_IMG) {
                size_t off = (size_t)(c + 1) * CHROW + abase;
                aPh4 = *(const uint4*)(AimgH + off);
                aPl4 = *(const uint4*)(AimgL + off);
            } else {
                int kn = (c + 1) * 16;
#pragma unroll
                for (int i = 0; i < 2; i++) {
                    int j = tid + i * 256;
                    int row = j >> 2, c4 = j & 3;
                    int gr = r0 + row;
                    aS[i] = (gr < M) ? *(const float4*)(A + (size_t)gr * KDIM + kn + c4 * 4)
                                     : make_float4(0.f, 0.f, 0.f, 0.f);
                }
            }
            CP_WAIT1();   // chunk c's group complete
        } else {
            CP_WAIT0();
        }
        __syncthreads();  // visibility of cp.async data + A stores across warps

        // fragments + mma (from A buffer p, B ring slot br)
        uint32_t ah[2][4], al[2][4];
#pragma unroll
        for (int mt = 0; mt < 2; mt++) {
            int r = wrow + mt * 16 + g;
            ah[mt][0] = Ah[r * 12 + q];     ah[mt][1] = Ah[(r + 8) * 12 + q];
            ah[mt][2] = Ah[r * 12 + q + 4]; ah[mt][3] = Ah[(r + 8) * 12 + q + 4];
            al[mt][0] = Al[r * 12 + q];     al[mt][1] = Al[(r + 8) * 12 + q];
            al[mt][2] = Al[r * 12 + q + 4]; al[mt][3] = Al[(r + 8) * 12 + q + 4];
        }
#pragma unroll
        for (int nt = 0; nt < 8; nt++) {
            int n = wcol + nt * 8 + g;
            uint32_t bh[2] = {Bh[n * 12 + q], Bh[n * 12 + q + 4]};
#pragma unroll
            for (int mt = 0; mt < 2; mt++) {
                mma_bf16(acc[mt][nt], ah[mt], bh);
                mma_bf16(acc[mt][nt], al[mt], bh);
            }
            if (third) {
                uint32_t bl[2] = {Bl[n * 12 + q], Bl[n * 12 + q + 4]};
#pragma unroll
                for (int mt = 0; mt < 2; mt++) mma_bf16(acc[mt][nt], ah[mt], bl);
            }
        }
    }
    __syncthreads();

    if (EPI == EPI_LN) {
        int wh = wcol >> 6;
        float s0[2] = {0, 0}, q0[2] = {0, 0}, s1[2] = {0, 0}, q1[2] = {0, 0};
#pragma unroll
        for (int mt = 0; mt < 2; mt++) {
            int ra = r0 + wrow + mt * 16 + g, rb = ra + 8;
#pragma unroll
            for (int nt = 0; nt < 8; nt++) {
                int col = wcol + nt * 8 + q * 2;
                float b0 = bias[col], b1 = bias[col + 1];
                float ra0 = (ra < M) ? res[(size_t)ra * NC + col] : 0.f;
                float ra1 = (ra < M) ? res[(size_t)ra * NC + col + 1] : 0.f;
                float rb0 = (rb < M) ? res[(size_t)rb * NC + col] : 0.f;
                float rb1 = (rb < M) ? res[(size_t)rb * NC + col + 1] : 0.f;
                float va0 = acc[mt][nt][0] + b0 + ra0;
                float va1 = acc[mt][nt][1] + b1 + ra1;
                float vb0 = acc[mt][nt][2] + b0 + rb0;
                float vb1 = acc[mt][nt][3] + b1 + rb1;
                acc[mt][nt][0] = va0; acc[mt][nt][1] = va1;
                acc[mt][nt][2] = vb0; acc[mt][nt][3] = vb1;
                s0[mt] += va0 + va1; q0[mt] += va0 * va0 + va1 * va1;
                s1[mt] += vb0 + vb1; q1[mt] += vb0 * vb0 + vb1 * vb1;
            }
        }
#pragma unroll
        for (int mt = 0; mt < 2; mt++) {
            s0[mt] += __shfl_xor_sync(0xffffffffu, s0[mt], 1);
            s0[mt] += __shfl_xor_sync(0xffffffffu, s0[mt], 2);
            q0[mt] += __shfl_xor_sync(0xffffffffu, q0[mt], 1);
            q0[mt] += __shfl_xor_sync(0xffffffffu, q0[mt], 2);
            s1[mt] += __shfl_xor_sync(0xffffffffu, s1[mt], 1);
            s1[mt] += __shfl_xor_sync(0xffffffffu, s1[mt], 2);
            q1[mt] += __shfl_xor_sync(0xffffffffu, q1[mt], 1);
            q1[mt] += __shfl_xor_sync(0xffffffffu, q1[mt], 2);
            if (q == 0) {
                redS[(wrow + mt * 16 + g) * 2 + wh] = make_float2(s0[mt], q0[mt]);
                redS[(wrow + mt * 16 + 8 + g) * 2 + wh] = make_float2(s1[mt], q1[mt]);
            }
        }
        __syncthreads();
#pragma unroll
        for (int mt = 0; mt < 2; mt++) {
            int lra = wrow + mt * 16 + g;
            float2 p0 = redS[lra * 2], p1 = redS[lra * 2 + 1];
            float2 p0b = redS[(lra + 8) * 2], p1b = redS[(lra + 8) * 2 + 1];
            float sa = p0.x + p1.x, qa = p0.y + p1.y;
            float sb = p0b.x + p1b.x, qb = p0b.y + p1b.y;
            float ma = sa * (1.f / 128.f), mb = sb * (1.f / 128.f);
            float rsa = rsqrtf(qa * (1.f / 128.f) - ma * ma + 1e-5f);
            float rsb = rsqrtf(qb * (1.f / 128.f) - mb * mb + 1e-5f);
            int ra = r0 + lra, rb = ra + 8;
#pragma unroll
            for (int nt = 0; nt < 8; nt++) {
                int col = wcol + nt * 8 + q * 2;
                float g0 = lng[col], g1 = lng[col + 1], o0 = lnb[col], o1 = lnb[col + 1];
                if (ra < M)
                    *(float2*)(C + (size_t)ra * NC + col) =
                        make_float2((acc[mt][nt][0] - ma) * rsa * g0 + o0,
                                    (acc[mt][nt][1] - ma) * rsa * g1 + o1);
                if (rb < M)
                    *(float2*)(C + (size_t)rb * NC + col) =
                        make_float2((acc[mt][nt][2] - mb) * rsb * g0 + o0,
                                    (acc[mt][nt][3] - mb) * rsb * g1 + o1);
            }
        }
    } else if (EPI == EPI_MID) {
#pragma unroll
        for (int mt = 0; mt < 2; mt++) {
            int ra = r0 + wrow + mt * 16 + g, rb = ra + 8;
#pragma unroll
            for (int nt = 0; nt < 8; nt++) {
                int col = wcol + nt * 8 + q * 2;
                float b0 = bs[col], b1 = bs[col + 1];
                float va0 = gelu_f(acc[mt][nt][0] + b0);
                float va1 = gelu_f(acc[mt][nt][1] + b1);
                float vb0 = gelu_f(acc[mt][nt][2] + b0);
                float vb1 = gelu_f(acc[mt][nt][3] + b1);
                int kpl = (wcol >> 1) + nt * 4 + q;       // 0..63
                int ch = ((int)blockIdx.y << 3) + (kpl >> 3);
                int kpin = kpl & 7;
                size_t base = (size_t)ch * CHROW + kpin;
                uint32_t hi, lo;
                if (ra < M) {
                    pack_hl(va0, va1, hi, lo);
                    AimgH[base + (size_t)ra * 8] = hi;
                    AimgL[base + (size_t)ra * 8] = lo;
                }
                if (rb < M) {
                    pack_hl(vb0, vb1, hi, lo);
                    AimgH[base + (size_t)rb * 8] = hi;
                    AimgL[base + (size_t)rb * 8] = lo;
                }
            }
        }
    } else if (EPI == EPI_NODE) {
#pragma unroll
        for (int mt = 0; mt < 2; mt++) {
            int ra = r0 + wrow + mt * 16 + g, rb = ra + 8;
#pragma unroll
            for (int nt = 0; nt < 8; nt++) {
                int col = wcol + nt * 8 + q * 2;
                float b0 = bs ? bs[col] : 0.f, b1 = bs ? bs[col + 1] : 0.f;
                float oa0 = acc[mt][nt][0] + b0, oa1 = acc[mt][nt][1] + b1;
                float ob0 = acc[mt][nt][2] + b0, ob1 = acc[mt][nt][3] + b1;
                if (blockIdx.y == 0) {
                    if (ra < M) *(float2*)(C + (size_t)ra * NC + col) = make_float2(oa0, oa1);
                    if (rb < M) *(float2*)(C + (size_t)rb * NC + col) = make_float2(ob0, ob1);
                } else {
                    if (ra < M) *(uint32_t*)(outb + (size_t)ra * NC + col) = f2bf2(oa0, oa1);
                    if (rb < M) *(uint32_t*)(outb + (size_t)rb * NC + col) = f2bf2(ob0, ob1);
                }
            }
        }
    } else {  // EPI_TBL
#pragma unroll
        for (int mt = 0; mt < 2; mt++) {
            int ra = r0 + wrow + mt * 16 + g, rb = ra + 8;
#pragma unroll
            for (int nt = 0; nt < 8; nt++) {
                int col = wcol + nt * 8 + q * 2;
                float b0 = bs[col], b1 = bs[col + 1];
                if (ra < M) *(uint32_t*)(outb + (size_t)ra * NC + col) =
                    f2bf2(acc[mt][nt][0] + b0, acc[mt][nt][1] + b1);
                if (rb < M) *(uint32_t*)(outb + (size_t)rb * NC + col) =
                    f2bf2(acc[mt][nt][2] + b0, acc[mt][nt][3] + b1);
            }
        }
    }
}

// ---------------- edge attention (R9 winner: warp per node, 2-edge unrolled) ---------
__global__ void __launch_bounds__(256) edge_attn_kernel(
    const __nv_bfloat16* __restrict__ tk, const __nv_bfloat16* __restrict__ tv)
{
    int warp = threadIdx.x >> 5, lane = threadIdx.x & 31;
    int n = blockIdx.x * 8 + warp;
    if (n >= NN) return;
    int beg = g_segoff[n], end = g_segoff[n + 1];
    float4 q4 = *(const float4*)(g_Q + (size_t)n * HIDN + lane * 4);
    float den = 0.f, ax = 0.f, ay = 0.f, az = 0.f, aw = 0.f;
    int p = beg;
    for (; p + 2 <= end; p += 2) {
        uint32_t e0 = g_edge[p], e1 = g_edge[p + 1];
        int s0 = (int)(e0 & 0xFFFFu), i0 = (int)(e0 >> 16);
        int s1 = (int)(e1 & 0xFFFFu), i1 = (int)(e1 >> 16);
        float4 ks0 = ld_bf16x4(g_Kb + (size_t)s0 * HIDN + lane * 4);
        float4 kt0 = ld_bf16x4(tk + (size_t)i0 * HIDN + lane * 4);
        float4 vs0 = ld_bf16x4(g_Vb + (size_t)s0 * HIDN + lane * 4);
        float4 vt0 = ld_bf16x4(tv + (size_t)i0 * HIDN + lane * 4);
        float4 ks1 = ld_bf16x4(g_Kb + (size_t)s1 * HIDN + lane * 4);
        float4 kt1 = ld_bf16x4(tk + (size_t)i1 * HIDN + lane * 4);
        float4 vs1 = ld_bf16x4(g_Vb + (size_t)s1 * HIDN + lane * 4);
        float4 vt1 = ld_bf16x4(tv + (size_t)i1 * HIDN + lane * 4);
        float sc0 = q4.x * (ks0.x + kt0.x) + q4.y * (ks0.y + kt0.y)
                  + q4.z * (ks0.z + kt0.z) + q4.w * (ks0.w + kt0.w);
        float sc1 = q4.x * (ks1.x + kt1.x) + q4.y * (ks1.y + kt1.y)
                  + q4.z * (ks1.z + kt1.z) + q4.w * (ks1.w + kt1.w);
        sc0 += __shfl_xor_sync(0xffffffffu, sc0, 1);
        sc1 += __shfl_xor_sync(0xffffffffu, sc1, 1);
        sc0 += __shfl_xor_sync(0xffffffffu, sc0, 2);
        sc1 += __shfl_xor_sync(0xffffffffu, sc1, 2);
        float w0 = __expf(sc0 * 0.25f);
        float w1 = __expf(sc1 * 0.25f);
        den += w0 + w1;
        ax += w0 * (vs0.x + vt0.x) + w1 * (vs1.x + vt1.x);
        ay += w0 * (vs0.y + vt0.y) + w1 * (vs1.y + vt1.y);
        az += w0 * (vs0.z + vt0.z) + w1 * (vs1.z + vt1.z);
        aw += w0 * (vs0.w + vt0.w) + w1 * (vs1.w + vt1.w);
    }
    if (p < end) {
        uint32_t e0 = g_edge[p];
        int s0 = (int)(e0 & 0xFFFFu), i0 = (int)(e0 >> 16);
        float4 ks0 = ld_bf16x4(g_Kb + (size_t)s0 * HIDN + lane * 4);
        float4 kt0 = ld_bf16x4(tk + (size_t)i0 * HIDN + lane * 4);
        float4 vs0 = ld_bf16x4(g_Vb + (size_t)s0 * HIDN + lane * 4);
        float4 vt0 = ld_bf16x4(tv + (size_t)i0 * HIDN + lane * 4);
        float sc0 = q4.x * (ks0.x + kt0.x) + q4.y * (ks0.y + kt0.y)
                  + q4.z * (ks0.z + kt0.z) + q4.w * (ks0.w + kt0.w);
        sc0 += __shfl_xor_sync(0xffffffffu, sc0, 1);
        sc0 += __shfl_xor_sync(0xffffffffu, sc0, 2);
        float w0 = __expf(sc0 * 0.25f);
        den += w0;
        ax += w0 * (vs0.x + vt0.x);
        ay += w0 * (vs0.y + vt0.y);
        az += w0 * (vs0.z + vt0.z);
        aw += w0 * (vs0.w + vt0.w);
    }
    float inv = 1.f / (den + 1e-16f);
    *(float4*)(g_aggr + (size_t)n * HIDN + lane * 4) =
        make_float4(ax * inv, ay * inv, az * inv, aw * inv);
}

// ----------------------------- fused pool + readout -----------------------------
__global__ void pool_readout_kernel(const float* __restrict__ Wout, const float* __restrict__ bout,
                                    float* __restrict__ out) {
    int gi = blockIdx.x;
    int t = threadIdx.x;
    int s = g_goff[gi], e = g_goff[gi + 1];
    float acc = 0.f;
    for (int n = s; n < e; n++) acc += g_x[(size_t)n * HIDN + t];
    float cnt = fmaxf((float)(e - s), 1.f);
    float v = acc / cnt * Wout[t];
    for (int d = 16; d; d >>= 1) v += __shfl_xor_sync(0xffffffffu, v, d);
    __shared__ float sw[4];
    if ((t & 31) == 0) sw[t >> 5] = v;
    __syncthreads();
    if (t == 0) out[gi] = sw[0] + sw[1] + sw[2] + sw[3] + bout[0];
}

// ----------------------------- launch -----------------------------
extern "C" void kernel_launch(void* const* d_in, const int* in_sizes, int n_in,
                              void* d_out, int out_size) {
    const int*   node_attr = (const int*)d_in[0];
    const int*   batch_idx = (const int*)d_in[1];
    const int*   eidx      = (const int*)d_in[2];
    const int*   sdist     = (const int*)d_in[3];
    const int*   spath     = (const int*)d_in[4];
    const float* atom_emb  = (const float*)d_in[5];
    const float* dist_emb  = (const float*)d_in[6];
    const float* path_emb  = (const float*)d_in[7];
    const float* Wq = (const float*)d_in[8];
    const float* bq = (const float*)d_in[9];
    const float* Wk = (const float*)d_in[10];
    const float* bk = (const float*)d_in[11];
    const float* Wv = (const float*)d_in[12];
    const float* bv = (const float*)d_in[13];
    const float* Wa = (const float*)d_in[14];
    const float* ba = (const float*)d_in[15];
    const float* ln1g = (const float*)d_in[16];
    const float* ln1b = (const float*)d_in[17];
    const float* Wmid = (const float*)d_in[18];
    const float* bmid = (const float*)d_in[19];
    const float* Wo = (const float*)d_in[20];
    const float* bo = (const float*)d_in[21];
    const float* ln2g = (const float*)d_in[22];
    const float* ln2b = (const float*)d_in[23];
    const float* Wout = (const float*)d_in[24];
    const float* bout = (const float*)d_in[25];
    float* out = (float*)d_out;

    float *px, *pQ, *pag, *ph, *pcomb;
    __nv_bfloat16 *pKb, *pVb, *pDPk, *pDPv;
    uint32_t *pWh, *pWl, *pMh, *pMl;
    cudaGetSymbolAddress((void**)&px, g_x);
    cudaGetSymbolAddress((void**)&pQ, g_Q);
    cudaGetSymbolAddress((void**)&pKb, g_Kb);
    cudaGetSymbolAddress((void**)&pVb, g_Vb);
    cudaGetSymbolAddress((void**)&pag, g_aggr);
    cudaGetSymbolAddress((void**)&ph, g_h);
    cudaGetSymbolAddress((void**)&pcomb, g_comb2);
    cudaGetSymbolAddress((void**)&pDPk, g_tDPk);
    cudaGetSymbolAddress((void**)&pDPv, g_tDPv);
    cudaGetSymbolAddress((void**)&pWh, g_wHi);
    cudaGetSymbolAddress((void**)&pWl, g_wLo);
    cudaGetSymbolAddress((void**)&pMh, g_midH);
    cudaGetSymbolAddress((void**)&pMl, g_midL);

    static bool attr_set = false;
    if (!attr_set) {
        cudaFuncSetAttribute(gemm10_kernel<128, EPI_NODE, false, false>,
                             cudaFuncAttributeMaxDynamicSharedMemorySize, G10_SMEM);
        cudaFuncSetAttribute(gemm10_kernel<128, EPI_TBL, false, false>,
                             cudaFuncAttributeMaxDynamicSharedMemorySize, G10_SMEM);
        cudaFuncSetAttribute(gemm10_kernel<128, EPI_LN, true, false>,
                             cudaFuncAttributeMaxDynamicSharedMemorySize, G10_SMEM);
        cudaFuncSetAttribute(gemm10_kernel<128, EPI_MID, false, false>,
                             cudaFuncAttributeMaxDynamicSharedMemorySize, G10_SMEM);
        cudaFuncSetAttribute(gemm10_kernel<256, EPI_LN, false, true>,
                             cudaFuncAttributeMaxDynamicSharedMemorySize, G10_SMEM);
        attr_set = true;
    }

    const int* esrc = eidx;
    const int* etgt = eidx + EE;
    int grid128 = cdiv_h(NN, 128);

    // ---- launch #4 is the layer-0 QKV GEMM (profiled slot) ----
    zero_kernel<<<cdiv_h(NN, 256), 256>>>();                               // 1
    encoder_kernel<<<512, 128>>>(node_attr, atom_emb);                     // 2
    prepack_kernel<<<512, 256>>>(Wq, Wk, Wv, Wa, Wmid, Wo);                // 3
    gemm10_kernel<128, EPI_NODE, false, false><<<dim3(grid128, 3), 256, G10_SMEM>>>( // 4
        px, pWh + OFF_Q, pWl + OFF_Q, 12288, 1536, nullptr, nullptr, bq, nullptr,
        nullptr, nullptr, nullptr, pQ, pKb, pVb, NN);
    comb2_kernel<<<256, 128>>>(dist_emb, path_emb);                        // 5
    gemm10_kernel<128, EPI_TBL, false, false><<<dim3(4, 4), 256, G10_SMEM>>>( // 6: both layers' tables
        pcomb, pWh + OFF_K, pWl + OFF_K, 0, 1536, nullptr, nullptr, bk, bv,
        nullptr, nullptr, nullptr, nullptr, pDPk, pDPv, 512);
    count_kernel<<<cdiv_h(EE, 256), 256>>>(etgt, batch_idx);
    scan1_kernel<<<NBLK, 256>>>();
    scan2_kernel<<<1, 256>>>();
    scan3_kernel<<<NBLK, 256>>>();
    scatter_kernel<<<cdiv_h(EE, 256), 256>>>(esrc, etgt, sdist, spath);

    for (int l = 0; l < 2; l++) {
        const uint32_t* wh = pWh + (size_t)l * IMG_LAYER;
        const uint32_t* wl = pWl + (size_t)l * IMG_LAYER;

        if (l == 1) {
            gemm10_kernel<128, EPI_NODE, false, false><<<dim3(grid128, 3), 256, G10_SMEM>>>(
                px, wh + OFF_Q, wl + OFF_Q, 12288, 1536, nullptr, nullptr,
                bq + l * 128, nullptr,
                nullptr, nullptr, nullptr, pQ, pKb, pVb, NN);
        }

        edge_attn_kernel<<<cdiv_h(NN, 8), 256>>>(pDPk + (size_t)l * 65536,
                                                 pDPv + (size_t)l * 65536);

        // h = LN(gelu(aggr)@Wa + ba + x)
        gemm10_kernel<128, EPI_LN, true, false><<<dim3(grid128, 1), 256, G10_SMEM>>>(
            pag, wh + OFF_A, wl + OFF_A, 0, 1536, nullptr, nullptr, ba + l * 128, nullptr,
            px, ln1g + l * 128, ln1b + l * 128, ph, nullptr, nullptr, NN);
        // mid = gelu(h@Wmid + bmid) -> global bf16 hi/lo image (chunk-major)
        gemm10_kernel<128, EPI_MID, false, false><<<dim3(grid128, 2), 256, G10_SMEM>>>(
            ph, wh + OFF_M, wl + OFF_M, 1536, 3072, pMh, pMl, bmid + l * 256, nullptr,
            nullptr, nullptr, nullptr, nullptr, nullptr, nullptr, NN);
        // x = LN(mid@Wo + bo + h), A streamed from the mid image (pure memcpy staging)
        gemm10_kernel<256, EPI_LN, false, true><<<dim3(grid128, 1), 256, G10_SMEM>>>(
            nullptr, wh + OFF_O, wl + OFF_O, 0, 1536, pMh, pMl, bo + l * 128, nullptr,
            ph, ln2g + l * 128, ln2b + l * 128, px, nullptr, nullptr, NN);
    }

    pool_readout_kernel<<<GG, 128>>>(Wout, bout, out);
}

// round 13
// speedup vs baseline: 1.0461x; 1.0191x over previous
#include <cuda_runtime.h>
#include <cuda_bf16.h>
#include <math.h>
#include <stdint.h>

#define NN 50000
#define EE 800000
#define HIDN 128
#define GG 256
#define NBLK 49    // ceil(NN/1024)
#define CHROW 400384  // 50048 rows * 8 words, per-chunk stride of the mid image

static inline int cdiv_h(int a, int b) { return (a + b - 1) / b; }

// ----------------------------- scratch (device globals) -----------------------------
__device__ float g_x[NN * HIDN];
__device__ float g_Q[NN * HIDN];
__device__ __nv_bfloat16 g_Kb[NN * HIDN];
__device__ __nv_bfloat16 g_Vb[NN * HIDN];
__device__ float g_aggr[NN * HIDN];
__device__ float g_h[NN * HIDN];
__device__ float g_comb2[2 * 512 * HIDN];
__device__ __nv_bfloat16 g_tDPk[2 * 512 * HIDN];
__device__ __nv_bfloat16 g_tDPv[2 * 512 * HIDN];
__device__ uint32_t g_wHi[196608];   // prepacked weights (bf16 hi), smem-image layout
__device__ uint32_t g_wLo[196608];   // prepacked weights (bf16 lo residual)
__device__ uint32_t g_midH[16 * CHROW];  // FFN mid image (bf16 hi), chunk-major
__device__ uint32_t g_midL[16 * CHROW];  // FFN mid image (bf16 lo)
__device__ int   g_cnt[NN];
__device__ int   g_segoff[NN + 1];
__device__ int   g_cursor[NN];
__device__ uint32_t g_edge[EE];      // packed: src | (dp<<16)
__device__ int   g_bsum[64];
__device__ int   g_boff[64];
__device__ int   g_gcnt[GG];
__device__ int   g_goff[GG + 1];

// image layout constants (words): per layer 98304
#define IMG_LAYER 98304
#define OFF_Q 0
#define OFF_K 12288
#define OFF_V 24576
#define OFF_A 36864
#define OFF_M 49152
#define OFF_O 73728

// ----------------------------- helpers -----------------------------
__device__ __forceinline__ float gelu_f(float x) {
    return 0.5f * x * (1.0f + erff(x * 0.7071067811865476f));
}

__device__ __forceinline__ void mma_bf16(float c[4], const uint32_t a[4], const uint32_t b[2]) {
    asm volatile(
        "mma.sync.aligned.m16n8k16.row.col.f32.bf16.bf16.f32 "
        "{%0,%1,%2,%3}, {%4,%5,%6,%7}, {%8,%9}, {%0,%1,%2,%3};"
        : "+f"(c[0]), "+f"(c[1]), "+f"(c[2]), "+f"(c[3])
        : "r"(a[0]), "r"(a[1]), "r"(a[2]), "r"(a[3]), "r"(b[0]), "r"(b[1]));
}

__device__ __forceinline__ void pack_hl(float x, float y, uint32_t& hi, uint32_t& lo) {
    __nv_bfloat16 hx = __float2bfloat16(x);
    __nv_bfloat16 hy = __float2bfloat16(y);
    __nv_bfloat16 lx = __float2bfloat16(x - __bfloat162float(hx));
    __nv_bfloat16 ly = __float2bfloat16(y - __bfloat162float(hy));
    __nv_bfloat162 h2 = __halves2bfloat162(hx, hy);
    __nv_bfloat162 l2 = __halves2bfloat162(lx, ly);
    hi = *(uint32_t*)&h2;
    lo = *(uint32_t*)&l2;
}

__device__ __forceinline__ float4 ld_bf16x4(const __nv_bfloat16* p) {
    uint2 u = *(const uint2*)p;
    __nv_bfloat162 a = *(__nv_bfloat162*)&u.x;
    __nv_bfloat162 b = *(__nv_bfloat162*)&u.y;
    float2 fa = __bfloat1622float2(a), fb = __bfloat1622float2(b);
    return make_float4(fa.x, fa.y, fb.x, fb.y);
}

__device__ __forceinline__ uint32_t f2bf2(float a, float b) {
    __nv_bfloat162 t = __halves2bfloat162(__float2bfloat16(a), __float2bfloat16(b));
    return *(uint32_t*)&t;
}

// ----------------------------- misc kernels -----------------------------
__global__ void zero_kernel() {
    int i = blockIdx.x * blockDim.x + threadIdx.x;
    if (i < NN) g_cnt[i] = 0;
    if (i < GG) g_gcnt[i] = 0;
}

__global__ void encoder_kernel(const int* __restrict__ attr, const float* __restrict__ aemb) {
    int c = threadIdx.x;
    for (int n = blockIdx.x; n < NN; n += gridDim.x) {
        int a0 = attr[n * 4 + 0], a1 = attr[n * 4 + 1], a2 = attr[n * 4 + 2], a3 = attr[n * 4 + 3];
        float v = aemb[(0 * 64 + a0) * HIDN + c] + aemb[(1 * 64 + a1) * HIDN + c]
                + aemb[(2 * 64 + a2) * HIDN + c] + aemb[(3 * 64 + a3) * HIDN + c];
        g_x[(size_t)n * HIDN + c] = v;
    }
}

// prepack ALL weights into GEMM smem-image layout (bf16 hi/lo, kpair-packed, n-major, stride 12)
__global__ void prepack_kernel(const float* __restrict__ Wq, const float* __restrict__ Wk,
                               const float* __restrict__ Wv, const float* __restrict__ Wa,
                               const float* __restrict__ Wm, const float* __restrict__ Wo) {
    for (int id = blockIdx.x * blockDim.x + threadIdx.x; id < 131072;
         id += gridDim.x * blockDim.x) {
        int layer = id >> 16;
        int r = id & 65535;
        const float* W; int N; int segoff; int wi;
        if (r < 32768) {
            int m = r >> 13; wi = r & 8191;
            W = (m == 0 ? Wq : m == 1 ? Wk : m == 2 ? Wv : Wa) + layer * 16384;
            N = 128; segoff = m * 12288;
        } else if (r < 49152) {
            wi = r - 32768; W = Wm + layer * 32768; N = 256; segoff = OFF_M;
        } else {
            wi = r - 49152; W = Wo + layer * 32768; N = 128; segoff = OFF_O;
        }
        int ch = wi / (8 * N);
        int rem = wi % (8 * N);
        int kp = rem / N;
        int n = rem % N;
        int k = ch * 16 + kp * 2;
        float a = W[(size_t)k * N + n], b = W[(size_t)(k + 1) * N + n];
        uint32_t hi, lo;
        pack_hl(a, b, hi, lo);
        int w = layer * IMG_LAYER + segoff + ch * N * 12 + n * 12 + kp;
        g_wHi[w] = hi;
        g_wLo[w] = lo;
    }
}

__global__ void count_kernel(const int* __restrict__ tgt, const int* __restrict__ bidx) {
    int i = blockIdx.x * blockDim.x + threadIdx.x;
    if (i < EE) atomicAdd(&g_cnt[tgt[i]], 1);
    if (i < NN) atomicAdd(&g_gcnt[bidx[i]], 1);
}

__global__ void scan1_kernel() {
    __shared__ int sh[256];
    int blk = blockIdx.x, t = threadIdx.x;
    int idx4 = blk * 256 + t;
    int4 v4 = make_int4(0, 0, 0, 0);
    if (idx4 < NN / 4) v4 = ((const int4*)g_cnt)[idx4];
    int s = v4.x + v4.y + v4.z + v4.w;
    sh[t] = s;
    __syncthreads();
    for (int d = 1; d < 256; d <<= 1) {
        int v = (t >= d) ? sh[t - d] : 0;
        __syncthreads();
        sh[t] += v;
        __syncthreads();
    }
    int run = (t == 0) ? 0 : sh[t - 1];
    int base = blk * 1024 + t * 4;
    int vv[4] = {v4.x, v4.y, v4.z, v4.w};
    for (int j = 0; j < 4; j++) {
        if (base + j < NN) g_segoff[base + j] = run;
        run += vv[j];
    }
    if (t == 255) g_bsum[blk] = sh[255];
}

__global__ void scan2_kernel() {
    __shared__ int sg[256];
    __shared__ int sb[64];
    int t = threadIdx.x;
    sg[t] = g_gcnt[t];
    if (t < 64) sb[t] = (t < NBLK) ? g_bsum[t] : 0;
    __syncthreads();
    for (int d = 1; d < 256; d <<= 1) {
        int v = (t >= d) ? sg[t - d] : 0;
        int v2 = 0;
        if (t < 64 && t >= d && d < 64) v2 = sb[t - d];
        __syncthreads();
        sg[t] += v;
        if (t < 64 && d < 64) sb[t] += v2;
        __syncthreads();
    }
    g_goff[t + 1] = sg[t];
    if (t == 0) g_goff[0] = 0;
    if (t < 64) g_boff[t] = (t == 0) ? 0 : sb[t - 1];
}

__global__ void scan3_kernel() {
    int blk = blockIdx.x, t = threadIdx.x;
    int off = g_boff[blk];
    int base = blk * 1024 + t * 4;
    for (int j = 0; j < 4; j++) {
        int i = base + j;
        if (i < NN) {
            int v = g_segoff[i] + off;
            g_segoff[i] = v;
            g_cursor[i] = v;
        }
    }
    if (blk == 0 && t == 0) g_segoff[NN] = EE;
}

__global__ void scatter_kernel(const int* __restrict__ src, const int* __restrict__ tgt,
                               const int* __restrict__ sdist, const int* __restrict__ spath) {
    int i = blockIdx.x * blockDim.x + threadIdx.x;
    if (i < EE) {
        int tg = tgt[i];
        int pos = atomicAdd(&g_cursor[tg], 1);
        uint32_t dp = (uint32_t)((sdist[i] << 4) | spath[i]);
        g_edge[pos] = (uint32_t)src[i] | (dp << 16);
    }
}

// combine dist+path embeddings for BOTH layers
__global__ void comb2_kernel(const float* __restrict__ de, const float* __restrict__ pe) {
    int c = threadIdx.x;
    for (int r = blockIdx.x; r < 1024; r += gridDim.x) {
        int l = r >> 9;
        int rr = r & 511;
        int d = rr >> 4, p = rr & 15;
        g_comb2[r * HIDN + c] = de[(l * 32 + d) * HIDN + c] + pe[(l * 16 + p) * HIDN + c];
    }
}

// ------------- GEMM (double-buffered, register-staged B, Bl only when needed) --------
enum { EPI_LN = 2, EPI_NODE = 3, EPI_TBL = 4, EPI_MID = 5 };
#define G8_SMEM 51200

template <int KDIM, int EPI, bool GELU_A, bool A_IMG>
__global__ void __launch_bounds__(256) gemm11_kernel(
    const float* __restrict__ Ain,
    const uint32_t* __restrict__ BhGbase, const uint32_t* __restrict__ BlGbase,
    int yStride, int chB,
    uint32_t* __restrict__ AimgH, uint32_t* __restrict__ AimgL,
    const float* __restrict__ bias, const float* __restrict__ bias2,
    const float* __restrict__ res, const float* __restrict__ lng, const float* __restrict__ lnb,
    float* __restrict__ C, __nv_bfloat16* __restrict__ Cb, __nv_bfloat16* __restrict__ Cb2,
    int M)
{
    constexpr int TM = 128;
    constexpr int NC = 128;

    extern __shared__ uint32_t dyn[];
    uint32_t* AhB = dyn;             // 2 x 1536
    uint32_t* AlB = AhB + 3072;
    uint32_t* BhB = AlB + 3072;
    uint32_t* BlB = BhB + 3072;
    float2* redS = (float2*)(BlB + 3072);  // 128 x 2

    int tid = threadIdx.x;
    int wid = tid >> 5, lane = tid & 31;
    int g = lane >> 2, q = lane & 3;
    int wrow = (wid & 3) * 32;
    int wcol = (wid >> 2) * 64;
    int r0 = blockIdx.x * TM;

    const float* A = Ain;
    const uint32_t* BhG;
    const uint32_t* BlG;
    const float* bs = bias;
    __nv_bfloat16* outb = Cb;
    bool third;
    if (EPI == EPI_TBL) {
        int layer = blockIdx.y >> 1, kv = blockIdx.y & 1;
        size_t off = (size_t)layer * IMG_LAYER + kv * 12288;
        BhG = BhGbase + off;
        BlG = BlGbase + off;
        A = Ain + (size_t)layer * 65536;
        bs = (kv ? bias2 : bias) + layer * 128;
        outb = (kv ? Cb2 : Cb) + (size_t)layer * 65536;
        third = false;
    } else {
        BhG = BhGbase + (size_t)blockIdx.y * yStride;
        BlG = BlGbase + (size_t)blockIdx.y * yStride;
        third = (EPI == EPI_NODE) ? (blockIdx.y == 0) : (EPI == EPI_LN || EPI == EPI_MID);
        if (EPI == EPI_NODE && blockIdx.y != 0) {
            bs = nullptr;
            outb = (blockIdx.y == 1) ? Cb : Cb2;
        }
        if (EPI == EPI_MID) bs = bias + blockIdx.y * 128;
    }

    float acc[2][8][4];
#pragma unroll
    for (int a = 0; a < 2; a++)
#pragma unroll
        for (int b = 0; b < 8; b++)
#pragma unroll
            for (int c = 0; c < 4; c++) acc[a][b][c] = 0.f;

    float4 aS[2];
    uint4 aPh4, aPl4;
    uint2 bPh[3], bPl[3];
    int arow = tid >> 1, apart = (tid & 1) * 4;
    size_t abase = (size_t)(r0 + arow) * 8 + apart;

    // prologue: stage chunk 0 (Bl only on 3-pass paths)
    if (A_IMG) {
        aPh4 = *(const uint4*)(AimgH + abase);
        aPl4 = *(const uint4*)(AimgL + abase);
    } else {
#pragma unroll
        for (int i = 0; i < 2; i++) {
            int j = tid + i * 256;
            int row = j >> 2, c4 = j & 3;
            int gr = r0 + row;
            aS[i] = (gr < M) ? *(const float4*)(A + (size_t)gr * KDIM + c4 * 4)
                             : make_float4(0.f, 0.f, 0.f, 0.f);
        }
    }
#pragma unroll
    for (int i = 0; i < 3; i++) bPh[i] = ((const uint2*)BhG)[tid + i * 256];
    if (third) {
#pragma unroll
        for (int i = 0; i < 3; i++) bPl[i] = ((const uint2*)BlG)[tid + i * 256];
    }

    constexpr int NCH = KDIM / 16;
#pragma unroll 1
    for (int c = 0; c < NCH; c++) {
        int p = c & 1;
        uint32_t* Ah = AhB + p * 1536;
        uint32_t* Al = AlB + p * 1536;
        uint32_t* Bh = BhB + p * 1536;
        uint32_t* Bl = BlB + p * 1536;

        // store staged -> smem[p]
        if (A_IMG) {
            *(uint4*)&Ah[arow * 12 + apart] = aPh4;
            *(uint4*)&Al[arow * 12 + apart] = aPl4;
        } else {
#pragma unroll
            for (int i = 0; i < 2; i++) {
                int j = tid + i * 256;
                int row = j >> 2, c4 = j & 3;
                float4 v = aS[i];
                if (GELU_A) { v.x = gelu_f(v.x); v.y = gelu_f(v.y); v.z = gelu_f(v.z); v.w = gelu_f(v.w); }
                uint32_t h01, l01, h23, l23;
                pack_hl(v.x, v.y, h01, l01);
                pack_hl(v.z, v.w, h23, l23);
                *(uint2*)&Ah[row * 12 + c4 * 2] = make_uint2(h01, h23);
                *(uint2*)&Al[row * 12 + c4 * 2] = make_uint2(l01, l23);
            }
        }
#pragma unroll
        for (int i = 0; i < 3; i++) ((uint2*)Bh)[tid + i * 256] = bPh[i];
        if (third) {
#pragma unroll
            for (int i = 0; i < 3; i++) ((uint2*)Bl)[tid + i * 256] = bPl[i];
        }
        __syncthreads();   // single barrier per chunk (double-buffer safe)

        // prefetch next chunk into registers
        if (c + 1 < NCH) {
            if (A_IMG) {
                size_t off = (size_t)(c + 1) * CHROW + abase;
                aPh4 = *(const uint4*)(AimgH + off);
                aPl4 = *(const uint4*)(AimgL + off);
            } else {
                int kn = (c + 1) * 16;
#pragma unroll
                for (int i = 0; i < 2; i++) {
                    int j = tid + i * 256;
                    int row = j >> 2, c4 = j & 3;
                    int gr = r0 + row;
                    aS[i] = (gr < M) ? *(const float4*)(A + (size_t)gr * KDIM + kn + c4 * 4)
                                     : make_float4(0.f, 0.f, 0.f, 0.f);
                }
            }
            int cb = (c + 1) * chB;
#pragma unroll
            for (int i = 0; i < 3; i++) bPh[i] = ((const uint2*)(BhG + cb))[tid + i * 256];
            if (third) {
#pragma unroll
                for (int i = 0; i < 3; i++) bPl[i] = ((const uint2*)(BlG + cb))[tid + i * 256];
            }
        }

        // fragments + mma (from buffer p)
        uint32_t ah[2][4], al[2][4];
#pragma unroll
        for (int mt = 0; mt < 2; mt++) {
            int r = wrow + mt * 16 + g;
            ah[mt][0] = Ah[r * 12 + q];     ah[mt][1] = Ah[(r + 8) * 12 + q];
            ah[mt][2] = Ah[r * 12 + q + 4]; ah[mt][3] = Ah[(r + 8) * 12 + q + 4];
            al[mt][0] = Al[r * 12 + q];     al[mt][1] = Al[(r + 8) * 12 + q];
            al[mt][2] = Al[r * 12 + q + 4]; al[mt][3] = Al[(r + 8) * 12 + q + 4];
        }
#pragma unroll
        for (int nt = 0; nt < 8; nt++) {
            int n = wcol + nt * 8 + g;
            uint32_t bh[2] = {Bh[n * 12 + q], Bh[n * 12 + q + 4]};
#pragma unroll
            for (int mt = 0; mt < 2; mt++) {
                mma_bf16(acc[mt][nt], ah[mt], bh);
                mma_bf16(acc[mt][nt], al[mt], bh);
            }
            if (third) {
                uint32_t bl[2] = {Bl[n * 12 + q], Bl[n * 12 + q + 4]};
#pragma unroll
                for (int mt = 0; mt < 2; mt++) mma_bf16(acc[mt][nt], ah[mt], bl);
            }
        }
    }
    __syncthreads();

    if (EPI == EPI_LN) {
        int wh = wcol >> 6;
        float s0[2] = {0, 0}, q0[2] = {0, 0}, s1[2] = {0, 0}, q1[2] = {0, 0};
#pragma unroll
        for (int mt = 0; mt < 2; mt++) {
            int ra = r0 + wrow + mt * 16 + g, rb = ra + 8;
#pragma unroll
            for (int nt = 0; nt < 8; nt++) {
                int col = wcol + nt * 8 + q * 2;
                float b0 = bias[col], b1 = bias[col + 1];
                float ra0 = (ra < M) ? res[(size_t)ra * NC + col] : 0.f;
                float ra1 = (ra < M) ? res[(size_t)ra * NC + col + 1] : 0.f;
                float rb0 = (rb < M) ? res[(size_t)rb * NC + col] : 0.f;
                float rb1 = (rb < M) ? res[(size_t)rb * NC + col + 1] : 0.f;
                float va0 = acc[mt][nt][0] + b0 + ra0;
                float va1 = acc[mt][nt][1] + b1 + ra1;
                float vb0 = acc[mt][nt][2] + b0 + rb0;
                float vb1 = acc[mt][nt][3] + b1 + rb1;
                acc[mt][nt][0] = va0; acc[mt][nt][1] = va1;
                acc[mt][nt][2] = vb0; acc[mt][nt][3] = vb1;
                s0[mt] += va0 + va1; q0[mt] += va0 * va0 + va1 * va1;
                s1[mt] += vb0 + vb1; q1[mt] += vb0 * vb0 + vb1 * vb1;
            }
        }
#pragma unroll
        for (int mt = 0; mt < 2; mt++) {
            s0[mt] += __shfl_xor_sync(0xffffffffu, s0[mt], 1);
            s0[mt] += __shfl_xor_sync(0xffffffffu, s0[mt], 2);
            q0[mt] += __shfl_xor_sync(0xffffffffu, q0[mt], 1);
            q0[mt] += __shfl_xor_sync(0xffffffffu, q0[mt], 2);
            s1[mt] += __shfl_xor_sync(0xffffffffu, s1[mt], 1);
            s1[mt] += __shfl_xor_sync(0xffffffffu, s1[mt], 2);
            q1[mt] += __shfl_xor_sync(0xffffffffu, q1[mt], 1);
            q1[mt] += __shfl_xor_sync(0xffffffffu, q1[mt], 2);
            if (q == 0) {
                redS[(wrow + mt * 16 + g) * 2 + wh] = make_float2(s0[mt], q0[mt]);
                redS[(wrow + mt * 16 + 8 + g) * 2 + wh] = make_float2(s1[mt], q1[mt]);
            }
        }
        __syncthreads();
#pragma unroll
        for (int mt = 0; mt < 2; mt++) {
            int lra = wrow + mt * 16 + g;
            float2 p0 = redS[lra * 2], p1 = redS[lra * 2 + 1];
            float2 p0b = redS[(lra + 8) * 2], p1b = redS[(lra + 8) * 2 + 1];
            float sa = p0.x + p1.x, qa = p0.y + p1.y;
            float sb = p0b.x + p1b.x, qb = p0b.y + p1b.y;
            float ma = sa * (1.f / 128.f), mb = sb * (1.f / 128.f);
            float rsa = rsqrtf(qa * (1.f / 128.f) - ma * ma + 1e-5f);
            float rsb = rsqrtf(qb * (1.f / 128.f) - mb * mb + 1e-5f);
            int ra = r0 + lra, rb = ra + 8;
#pragma unroll
            for (int nt = 0; nt < 8; nt++) {
                int col = wcol + nt * 8 + q * 2;
                float g0 = lng[col], g1 = lng[col + 1], o0 = lnb[col], o1 = lnb[col + 1];
                if (ra < M)
                    *(float2*)(C + (size_t)ra * NC + col) =
                        make_float2((acc[mt][nt][0] - ma) * rsa * g0 + o0,
                                    (acc[mt][nt][1] - ma) * rsa * g1 + o1);
                if (rb < M)
                    *(float2*)(C + (size_t)rb * NC + col) =
                        make_float2((acc[mt][nt][2] - mb) * rsb * g0 + o0,
                                    (acc[mt][nt][3] - mb) * rsb * g1 + o1);
            }
        }
    } else if (EPI == EPI_MID) {
#pragma unroll
        for (int mt = 0; mt < 2; mt++) {
            int ra = r0 + wrow + mt * 16 + g, rb = ra + 8;
#pragma unroll
            for (int nt = 0; nt < 8; nt++) {
                int col = wcol + nt * 8 + q * 2;
                float b0 = bs[col], b1 = bs[col + 1];
                float va0 = gelu_f(acc[mt][nt][0] + b0);
                float va1 = gelu_f(acc[mt][nt][1] + b1);
                float vb0 = gelu_f(acc[mt][nt][2] + b0);
                float vb1 = gelu_f(acc[mt][nt][3] + b1);
                int kpl = (wcol >> 1) + nt * 4 + q;       // 0..63
                int ch = ((int)blockIdx.y << 3) + (kpl >> 3);
                int kpin = kpl & 7;
                size_t base = (size_t)ch * CHROW + kpin;
                uint32_t hi, lo;
                if (ra < M) {
                    pack_hl(va0, va1, hi, lo);
                    AimgH[base + (size_t)ra * 8] = hi;
                    AimgL[base + (size_t)ra * 8] = lo;
                }
                if (rb < M) {
                    pack_hl(vb0, vb1, hi, lo);
                    AimgH[base + (size_t)rb * 8] = hi;
                    AimgL[base + (size_t)rb * 8] = lo;
                }
            }
        }
    } else if (EPI == EPI_NODE) {
#pragma unroll
        for (int mt = 0; mt < 2; mt++) {
            int ra = r0 + wrow + mt * 16 + g, rb = ra + 8;
#pragma unroll
            for (int nt = 0; nt < 8; nt++) {
                int col = wcol + nt * 8 + q * 2;
                float b0 = bs ? bs[col] : 0.f, b1 = bs ? bs[col + 1] : 0.f;
                float oa0 = acc[mt][nt][0] + b0, oa1 = acc[mt][nt][1] + b1;
                float ob0 = acc[mt][nt][2] + b0, ob1 = acc[mt][nt][3] + b1;
                if (blockIdx.y == 0) {
                    if (ra < M) *(float2*)(C + (size_t)ra * NC + col) = make_float2(oa0, oa1);
                    if (rb < M) *(float2*)(C + (size_t)rb * NC + col) = make_float2(ob0, ob1);
                } else {
                    if (ra < M) *(uint32_t*)(outb + (size_t)ra * NC + col) = f2bf2(oa0, oa1);
                    if (rb < M) *(uint32_t*)(outb + (size_t)rb * NC + col) = f2bf2(ob0, ob1);
                }
            }
        }
    } else {  // EPI_TBL
#pragma unroll
        for (int mt = 0; mt < 2; mt++) {
            int ra = r0 + wrow + mt * 16 + g, rb = ra + 8;
#pragma unroll
            for (int nt = 0; nt < 8; nt++) {
                int col = wcol + nt * 8 + q * 2;
                float b0 = bs[col], b1 = bs[col + 1];
                if (ra < M) *(uint32_t*)(outb + (size_t)ra * NC + col) =
                    f2bf2(acc[mt][nt][0] + b0, acc[mt][nt][1] + b1);
                if (rb < M) *(uint32_t*)(outb + (size_t)rb * NC + col) =
                    f2bf2(acc[mt][nt][2] + b0, acc[mt][nt][3] + b1);
            }
        }
    }
}

// ---------------- edge attention (R9 winner: warp per node, 2-edge unrolled) ---------
__global__ void __launch_bounds__(256) edge_attn_kernel(
    const __nv_bfloat16* __restrict__ tk, const __nv_bfloat16* __restrict__ tv)
{
    int warp = threadIdx.x >> 5, lane = threadIdx.x & 31;
    int n = blockIdx.x * 8 + warp;
    if (n >= NN) return;
    int beg = g_segoff[n], end = g_segoff[n + 1];
    float4 q4 = *(const float4*)(g_Q + (size_t)n * HIDN + lane * 4);
    float den = 0.f, ax = 0.f, ay = 0.f, az = 0.f, aw = 0.f;
    int p = beg;
    for (; p + 2 <= end; p += 2) {
        uint32_t e0 = g_edge[p], e1 = g_edge[p + 1];
        int s0 = (int)(e0 & 0xFFFFu), i0 = (int)(e0 >> 16);
        int s1 = (int)(e1 & 0xFFFFu), i1 = (int)(e1 >> 16);
        float4 ks0 = ld_bf16x4(g_Kb + (size_t)s0 * HIDN + lane * 4);
        float4 kt0 = ld_bf16x4(tk + (size_t)i0 * HIDN + lane * 4);
        float4 vs0 = ld_bf16x4(g_Vb + (size_t)s0 * HIDN + lane * 4);
        float4 vt0 = ld_bf16x4(tv + (size_t)i0 * HIDN + lane * 4);
        float4 ks1 = ld_bf16x4(g_Kb + (size_t)s1 * HIDN + lane * 4);
        float4 kt1 = ld_bf16x4(tk + (size_t)i1 * HIDN + lane * 4);
        float4 vs1 = ld_bf16x4(g_Vb + (size_t)s1 * HIDN + lane * 4);
        float4 vt1 = ld_bf16x4(tv + (size_t)i1 * HIDN + lane * 4);
        float sc0 = q4.x * (ks0.x + kt0.x) + q4.y * (ks0.y + kt0.y)
                  + q4.z * (ks0.z + kt0.z) + q4.w * (ks0.w + kt0.w);
        float sc1 = q4.x * (ks1.x + kt1.x) + q4.y * (ks1.y + kt1.y)
                  + q4.z * (ks1.z + kt1.z) + q4.w * (ks1.w + kt1.w);
        sc0 += __shfl_xor_sync(0xffffffffu, sc0, 1);
        sc1 += __shfl_xor_sync(0xffffffffu, sc1, 1);
        sc0 += __shfl_xor_sync(0xffffffffu, sc0, 2);
        sc1 += __shfl_xor_sync(0xffffffffu, sc1, 2);
        float w0 = __expf(sc0 * 0.25f);
        float w1 = __expf(sc1 * 0.25f);
        den += w0 + w1;
        ax += w0 * (vs0.x + vt0.x) + w1 * (vs1.x + vt1.x);
        ay += w0 * (vs0.y + vt0.y) + w1 * (vs1.y + vt1.y);
        az += w0 * (vs0.z + vt0.z) + w1 * (vs1.z + vt1.z);
        aw += w0 * (vs0.w + vt0.w) + w1 * (vs1.w + vt1.w);
    }
    if (p < end) {
        uint32_t e0 = g_edge[p];
        int s0 = (int)(e0 & 0xFFFFu), i0 = (int)(e0 >> 16);
        float4 ks0 = ld_bf16x4(g_Kb + (size_t)s0 * HIDN + lane * 4);
        float4 kt0 = ld_bf16x4(tk + (size_t)i0 * HIDN + lane * 4);
        float4 vs0 = ld_bf16x4(g_Vb + (size_t)s0 * HIDN + lane * 4);
        float4 vt0 = ld_bf16x4(tv + (size_t)i0 * HIDN + lane * 4);
        float sc0 = q4.x * (ks0.x + kt0.x) + q4.y * (ks0.y + kt0.y)
                  + q4.z * (ks0.z + kt0.z) + q4.w * (ks0.w + kt0.w);
        sc0 += __shfl_xor_sync(0xffffffffu, sc0, 1);
        sc0 += __shfl_xor_sync(0xffffffffu, sc0, 2);
        float w0 = __expf(sc0 * 0.25f);
        den += w0;
        ax += w0 * (vs0.x + vt0.x);
        ay += w0 * (vs0.y + vt0.y);
        az += w0 * (vs0.z + vt0.z);
        aw += w0 * (vs0.w + vt0.w);
    }
    float inv = 1.f / (den + 1e-16f);
    *(float4*)(g_aggr + (size_t)n * HIDN + lane * 4) =
        make_float4(ax * inv, ay * inv, az * inv, aw * inv);
}

// ----------------------------- fused pool + readout -----------------------------
__global__ void pool_readout_kernel(const float* __restrict__ Wout, const float* __restrict__ bout,
                                    float* __restrict__ out) {
    int gi = blockIdx.x;
    int t = threadIdx.x;
    int s = g_goff[gi], e = g_goff[gi + 1];
    float acc = 0.f;
    for (int n = s; n < e; n++) acc += g_x[(size_t)n * HIDN + t];
    float cnt = fmaxf((float)(e - s), 1.f);
    float v = acc / cnt * Wout[t];
    for (int d = 16; d; d >>= 1) v += __shfl_xor_sync(0xffffffffu, v, d);
    __shared__ float sw[4];
    if ((t & 31) == 0) sw[t >> 5] = v;
    __syncthreads();
    if (t == 0) out[gi] = sw[0] + sw[1] + sw[2] + sw[3] + bout[0];
}

// ----------------------------- launch -----------------------------
extern "C" void kernel_launch(void* const* d_in, const int* in_sizes, int n_in,
                              void* d_out, int out_size) {
    const int*   node_attr = (const int*)d_in[0];
    const int*   batch_idx = (const int*)d_in[1];
    const int*   eidx      = (const int*)d_in[2];
    const int*   sdist     = (const int*)d_in[3];
    const int*   spath     = (const int*)d_in[4];
    const float* atom_emb  = (const float*)d_in[5];
    const float* dist_emb  = (const float*)d_in[6];
    const float* path_emb  = (const float*)d_in[7];
    const float* Wq = (const float*)d_in[8];
    const float* bq = (const float*)d_in[9];
    const float* Wk = (const float*)d_in[10];
    const float* bk = (const float*)d_in[11];
    const float* Wv = (const float*)d_in[12];
    const float* bv = (const float*)d_in[13];
    const float* Wa = (const float*)d_in[14];
    const float* ba = (const float*)d_in[15];
    const float* ln1g = (const float*)d_in[16];
    const float* ln1b = (const float*)d_in[17];
    const float* Wmid = (const float*)d_in[18];
    const float* bmid = (const float*)d_in[19];
    const float* Wo = (const float*)d_in[20];
    const float* bo = (const float*)d_in[21];
    const float* ln2g = (const float*)d_in[22];
    const float* ln2b = (const float*)d_in[23];
    const float* Wout = (const float*)d_in[24];
    const float* bout = (const float*)d_in[25];
    float* out = (float*)d_out;

    float *px, *pQ, *pag, *ph, *pcomb;
    __nv_bfloat16 *pKb, *pVb, *pDPk, *pDPv;
    uint32_t *pWh, *pWl, *pMh, *pMl;
    cudaGetSymbolAddress((void**)&px, g_x);
    cudaGetSymbolAddress((void**)&pQ, g_Q);
    cudaGetSymbolAddress((void**)&pKb, g_Kb);
    cudaGetSymbolAddress((void**)&pVb, g_Vb);
    cudaGetSymbolAddress((void**)&pag, g_aggr);
    cudaGetSymbolAddress((void**)&ph, g_h);
    cudaGetSymbolAddress((void**)&pcomb, g_comb2);
    cudaGetSymbolAddress((void**)&pDPk, g_tDPk);
    cudaGetSymbolAddress((void**)&pDPv, g_tDPv);
    cudaGetSymbolAddress((void**)&pWh, g_wHi);
    cudaGetSymbolAddress((void**)&pWl, g_wLo);
    cudaGetSymbolAddress((void**)&pMh, g_midH);
    cudaGetSymbolAddress((void**)&pMl, g_midL);

    static bool attr_set = false;
    if (!attr_set) {
        cudaFuncSetAttribute(gemm11_kernel<128, EPI_NODE, false, false>,
                             cudaFuncAttributeMaxDynamicSharedMemorySize, G8_SMEM);
        cudaFuncSetAttribute(gemm11_kernel<128, EPI_TBL, false, false>,
                             cudaFuncAttributeMaxDynamicSharedMemorySize, G8_SMEM);
        cudaFuncSetAttribute(gemm11_kernel<128, EPI_LN, true, false>,
                             cudaFuncAttributeMaxDynamicSharedMemorySize, G8_SMEM);
        cudaFuncSetAttribute(gemm11_kernel<128, EPI_MID, false, false>,
                             cudaFuncAttributeMaxDynamicSharedMemorySize, G8_SMEM);
        cudaFuncSetAttribute(gemm11_kernel<256, EPI_LN, false, true>,
                             cudaFuncAttributeMaxDynamicSharedMemorySize, G8_SMEM);
        attr_set = true;
    }

    const int* esrc = eidx;
    const int* etgt = eidx + EE;
    int grid128 = cdiv_h(NN, 128);

    // ---- launch #4 is the layer-0 QKV GEMM (profiled slot) ----
    zero_kernel<<<cdiv_h(NN, 256), 256>>>();                               // 1
    encoder_kernel<<<512, 128>>>(node_attr, atom_emb);                     // 2
    prepack_kernel<<<512, 256>>>(Wq, Wk, Wv, Wa, Wmid, Wo);                // 3
    gemm11_kernel<128, EPI_NODE, false, false><<<dim3(grid128, 3), 256, G8_SMEM>>>( // 4
        px, pWh + OFF_Q, pWl + OFF_Q, 12288, 1536, nullptr, nullptr, bq, nullptr,
        nullptr, nullptr, nullptr, pQ, pKb, pVb, NN);
    comb2_kernel<<<256, 128>>>(dist_emb, path_emb);                        // 5
    gemm11_kernel<128, EPI_TBL, false, false><<<dim3(4, 4), 256, G8_SMEM>>>( // 6: both layers' tables
        pcomb, pWh + OFF_K, pWl + OFF_K, 0, 1536, nullptr, nullptr, bk, bv,
        nullptr, nullptr, nullptr, nullptr, pDPk, pDPv, 512);
    count_kernel<<<cdiv_h(EE, 256), 256>>>(etgt, batch_idx);
    scan1_kernel<<<NBLK, 256>>>();
    scan2_kernel<<<1, 256>>>();
    scan3_kernel<<<NBLK, 256>>>();
    scatter_kernel<<<cdiv_h(EE, 256), 256>>>(esrc, etgt, sdist, spath);

    for (int l = 0; l < 2; l++) {
        const uint32_t* wh = pWh + (size_t)l * IMG_LAYER;
        const uint32_t* wl = pWl + (size_t)l * IMG_LAYER;

        if (l == 1) {
            gemm11_kernel<128, EPI_NODE, false, false><<<dim3(grid128, 3), 256, G8_SMEM>>>(
                px, wh + OFF_Q, wl + OFF_Q, 12288, 1536, nullptr, nullptr,
                bq + l * 128, nullptr,
                nullptr, nullptr, nullptr, pQ, pKb, pVb, NN);
        }

        edge_attn_kernel<<<cdiv_h(NN, 8), 256>>>(pDPk + (size_t)l * 65536,
                                                 pDPv + (size_t)l * 65536);

        // h = LN(gelu(aggr)@Wa + ba + x)
        gemm11_kernel<128, EPI_LN, true, false><<<dim3(grid128, 1), 256, G8_SMEM>>>(
            pag, wh + OFF_A, wl + OFF_A, 0, 1536, nullptr, nullptr, ba + l * 128, nullptr,
            px, ln1g + l * 128, ln1b + l * 128, ph, nullptr, nullptr, NN);
        // mid = gelu(h@Wmid + bmid) -> global bf16 hi/lo image (chunk-major)
        gemm11_kernel<128, EPI_MID, false, false><<<dim3(grid128, 2), 256, G8_SMEM>>>(
            ph, wh + OFF_M, wl + OFF_M, 1536, 3072, pMh, pMl, bmid + l * 256, nullptr,
            nullptr, nullptr, nullptr, nullptr, nullptr, nullptr, NN);
        // x = LN(mid@Wo + bo + h), A streamed from the mid image (pure memcpy staging)
        gemm11_kernel<256, EPI_LN, false, true><<<dim3(grid128, 1), 256, G8_SMEM>>>(
            nullptr, wh + OFF_O, wl + OFF_O, 0, 1536, pMh, pMl, bo + l * 128, nullptr,
            ph, ln2g + l * 128, ln2b + l * 128, px, nullptr, nullptr, NN);
    }

    pool_readout_kernel<<<GG, 128>>>(Wout, bout, out);
}

// round 14
// speedup vs baseline: 1.0535x; 1.0071x over previous
#include <cuda_runtime.h>
#include <cuda_bf16.h>
#include <math.h>
#include <stdint.h>

#define NN 50000
#define EE 800000
#define HIDN 128
#define GG 256
#define NBLK 49    // ceil(NN/1024)
#define CHROW 400384  // 50048 rows * 8 words, per-chunk stride of the mid image

static inline int cdiv_h(int a, int b) { return (a + b - 1) / b; }

// ----------------------------- scratch (device globals) -----------------------------
__device__ float g_x[NN * HIDN];
__device__ float g_Q[NN * HIDN];
__device__ __nv_bfloat16 g_KVb[NN * 256];        // interleaved K|V per node: [k4|v4] x 32 groups
__device__ float g_aggr[NN * HIDN];
__device__ float g_h[NN * HIDN];
__device__ float g_comb2[2 * 512 * HIDN];
__device__ __nv_bfloat16 g_tKV[2 * 512 * 256];   // interleaved K|V tables (per layer)
__device__ uint32_t g_wHi[196608];   // prepacked weights (bf16 hi), smem-image layout
__device__ uint32_t g_wLo[196608];   // prepacked weights (bf16 lo residual)
__device__ uint32_t g_midH[16 * CHROW];  // FFN mid image (bf16 hi), chunk-major
__device__ uint32_t g_midL[16 * CHROW];  // FFN mid image (bf16 lo)
__device__ int   g_cnt[NN];
__device__ int   g_segoff[NN + 1];
__device__ int   g_cursor[NN];
__device__ uint32_t g_edge[EE];      // packed: src | (dp<<16)
__device__ int   g_bsum[64];
__device__ int   g_boff[64];
__device__ int   g_gcnt[GG];
__device__ int   g_goff[GG + 1];

// image layout constants (words): per layer 98304
#define IMG_LAYER 98304
#define OFF_Q 0
#define OFF_K 12288
#define OFF_V 24576
#define OFF_A 36864
#define OFF_M 49152
#define OFF_O 73728

// ----------------------------- helpers -----------------------------
__device__ __forceinline__ float gelu_f(float x) {
    return 0.5f * x * (1.0f + erff(x * 0.7071067811865476f));
}

__device__ __forceinline__ void mma_bf16(float c[4], const uint32_t a[4], const uint32_t b[2]) {
    asm volatile(
        "mma.sync.aligned.m16n8k16.row.col.f32.bf16.bf16.f32 "
        "{%0,%1,%2,%3}, {%4,%5,%6,%7}, {%8,%9}, {%0,%1,%2,%3};"
        : "+f"(c[0]), "+f"(c[1]), "+f"(c[2]), "+f"(c[3])
        : "r"(a[0]), "r"(a[1]), "r"(a[2]), "r"(a[3]), "r"(b[0]), "r"(b[1]));
}

__device__ __forceinline__ void pack_hl(float x, float y, uint32_t& hi, uint32_t& lo) {
    __nv_bfloat16 hx = __float2bfloat16(x);
    __nv_bfloat16 hy = __float2bfloat16(y);
    __nv_bfloat16 lx = __float2bfloat16(x - __bfloat162float(hx));
    __nv_bfloat16 ly = __float2bfloat16(y - __bfloat162float(hy));
    __nv_bfloat162 h2 = __halves2bfloat162(hx, hy);
    __nv_bfloat162 l2 = __halves2bfloat162(lx, ly);
    hi = *(uint32_t*)&h2;
    lo = *(uint32_t*)&l2;
}

__device__ __forceinline__ float4 unp4(uint32_t a, uint32_t b) {
    __nv_bfloat162 x = *(__nv_bfloat162*)&a;
    __nv_bfloat162 y = *(__nv_bfloat162*)&b;
    float2 fx = __bfloat1622float2(x), fy = __bfloat1622float2(y);
    return make_float4(fx.x, fx.y, fy.x, fy.y);
}

__device__ __forceinline__ uint32_t f2bf2(float a, float b) {
    __nv_bfloat162 t = __halves2bfloat162(__float2bfloat16(a), __float2bfloat16(b));
    return *(uint32_t*)&t;
}

// ----------------------------- misc kernels -----------------------------
__global__ void zero_kernel() {
    int i = blockIdx.x * blockDim.x + threadIdx.x;
    if (i < NN) g_cnt[i] = 0;
    if (i < GG) g_gcnt[i] = 0;
}

__global__ void encoder_kernel(const int* __restrict__ attr, const float* __restrict__ aemb) {
    int c = threadIdx.x;
    for (int n = blockIdx.x; n < NN; n += gridDim.x) {
        int a0 = attr[n * 4 + 0], a1 = attr[n * 4 + 1], a2 = attr[n * 4 + 2], a3 = attr[n * 4 + 3];
        float v = aemb[(0 * 64 + a0) * HIDN + c] + aemb[(1 * 64 + a1) * HIDN + c]
                + aemb[(2 * 64 + a2) * HIDN + c] + aemb[(3 * 64 + a3) * HIDN + c];
        g_x[(size_t)n * HIDN + c] = v;
    }
}

// prepack ALL weights into GEMM smem-image layout (bf16 hi/lo, kpair-packed, n-major, stride 12)
__global__ void prepack_kernel(const float* __restrict__ Wq, const float* __restrict__ Wk,
                               const float* __restrict__ Wv, const float* __restrict__ Wa,
                               const float* __restrict__ Wm, const float* __restrict__ Wo) {
    for (int id = blockIdx.x * blockDim.x + threadIdx.x; id < 131072;
         id += gridDim.x * blockDim.x) {
        int layer = id >> 16;
        int r = id & 65535;
        const float* W; int N; int segoff; int wi;
        if (r < 32768) {
            int m = r >> 13; wi = r & 8191;
            W = (m == 0 ? Wq : m == 1 ? Wk : m == 2 ? Wv : Wa) + layer * 16384;
            N = 128; segoff = m * 12288;
        } else if (r < 49152) {
            wi = r - 32768; W = Wm + layer * 32768; N = 256; segoff = OFF_M;
        } else {
            wi = r - 49152; W = Wo + layer * 32768; N = 128; segoff = OFF_O;
        }
        int ch = wi / (8 * N);
        int rem = wi % (8 * N);
        int kp = rem / N;
        int n = rem % N;
        int k = ch * 16 + kp * 2;
        float a = W[(size_t)k * N + n], b = W[(size_t)(k + 1) * N + n];
        uint32_t hi, lo;
        pack_hl(a, b, hi, lo);
        int w = layer * IMG_LAYER + segoff + ch * N * 12 + n * 12 + kp;
        g_wHi[w] = hi;
        g_wLo[w] = lo;
    }
}

__global__ void count_kernel(const int* __restrict__ tgt, const int* __restrict__ bidx) {
    int i = blockIdx.x * blockDim.x + threadIdx.x;
    if (i < EE) atomicAdd(&g_cnt[tgt[i]], 1);
    if (i < NN) atomicAdd(&g_gcnt[bidx[i]], 1);
}

__global__ void scan1_kernel() {
    __shared__ int sh[256];
    int blk = blockIdx.x, t = threadIdx.x;
    int idx4 = blk * 256 + t;
    int4 v4 = make_int4(0, 0, 0, 0);
    if (idx4 < NN / 4) v4 = ((const int4*)g_cnt)[idx4];
    int s = v4.x + v4.y + v4.z + v4.w;
    sh[t] = s;
    __syncthreads();
    for (int d = 1; d < 256; d <<= 1) {
        int v = (t >= d) ? sh[t - d] : 0;
        __syncthreads();
        sh[t] += v;
        __syncthreads();
    }
    int run = (t == 0) ? 0 : sh[t - 1];
    int base = blk * 1024 + t * 4;
    int vv[4] = {v4.x, v4.y, v4.z, v4.w};
    for (int j = 0; j < 4; j++) {
        if (base + j < NN) g_segoff[base + j] = run;
        run += vv[j];
    }
    if (t == 255) g_bsum[blk] = sh[255];
}

__global__ void scan2_kernel() {
    __shared__ int sg[256];
    __shared__ int sb[64];
    int t = threadIdx.x;
    sg[t] = g_gcnt[t];
    if (t < 64) sb[t] = (t < NBLK) ? g_bsum[t] : 0;
    __syncthreads();
    for (int d = 1; d < 256; d <<= 1) {
        int v = (t >= d) ? sg[t - d] : 0;
        int v2 = 0;
        if (t < 64 && t >= d && d < 64) v2 = sb[t - d];
        __syncthreads();
        sg[t] += v;
        if (t < 64 && d < 64) sb[t] += v2;
        __syncthreads();
    }
    g_goff[t + 1] = sg[t];
    if (t == 0) g_goff[0] = 0;
    if (t < 64) g_boff[t] = (t == 0) ? 0 : sb[t - 1];
}

__global__ void scan3_kernel() {
    int blk = blockIdx.x, t = threadIdx.x;
    int off = g_boff[blk];
    int base = blk * 1024 + t * 4;
    for (int j = 0; j < 4; j++) {
        int i = base + j;
        if (i < NN) {
            int v = g_segoff[i] + off;
            g_segoff[i] = v;
            g_cursor[i] = v;
        }
    }
    if (blk == 0 && t == 0) g_segoff[NN] = EE;
}

__global__ void scatter_kernel(const int* __restrict__ src, const int* __restrict__ tgt,
                               const int* __restrict__ sdist, const int* __restrict__ spath) {
    int i = blockIdx.x * blockDim.x + threadIdx.x;
    if (i < EE) {
        int tg = tgt[i];
        int pos = atomicAdd(&g_cursor[tg], 1);
        uint32_t dp = (uint32_t)((sdist[i] << 4) | spath[i]);
        g_edge[pos] = (uint32_t)src[i] | (dp << 16);
    }
}

// combine dist+path embeddings for BOTH layers
__global__ void comb2_kernel(const float* __restrict__ de, const float* __restrict__ pe) {
    int c = threadIdx.x;
    for (int r = blockIdx.x; r < 1024; r += gridDim.x) {
        int l = r >> 9;
        int rr = r & 511;
        int d = rr >> 4, p = rr & 15;
        g_comb2[r * HIDN + c] = de[(l * 32 + d) * HIDN + c] + pe[(l * 16 + p) * HIDN + c];
    }
}

// ------------- GEMM (double-buffered, register-staged B, Bl only when needed) --------
enum { EPI_LN = 2, EPI_NODE = 3, EPI_TBL = 4, EPI_MID = 5 };
#define G8_SMEM 51200

template <int KDIM, int EPI, bool GELU_A, bool A_IMG>
__global__ void __launch_bounds__(256) gemm11_kernel(
    const float* __restrict__ Ain,
    const uint32_t* __restrict__ BhGbase, const uint32_t* __restrict__ BlGbase,
    int yStride, int chB,
    uint32_t* __restrict__ AimgH, uint32_t* __restrict__ AimgL,
    const float* __restrict__ bias, const float* __restrict__ bias2,
    const float* __restrict__ res, const float* __restrict__ lng, const float* __restrict__ lnb,
    float* __restrict__ C, __nv_bfloat16* __restrict__ Cb,
    int M)
{
    constexpr int TM = 128;
    constexpr int NC = 128;

    extern __shared__ uint32_t dyn[];
    uint32_t* AhB = dyn;             // 2 x 1536
    uint32_t* AlB = AhB + 3072;
    uint32_t* BhB = AlB + 3072;
    uint32_t* BlB = BhB + 3072;
    float2* redS = (float2*)(BlB + 3072);  // 128 x 2

    int tid = threadIdx.x;
    int wid = tid >> 5, lane = tid & 31;
    int g = lane >> 2, q = lane & 3;
    int wrow = (wid & 3) * 32;
    int wcol = (wid >> 2) * 64;
    int r0 = blockIdx.x * TM;

    const float* A = Ain;
    const uint32_t* BhG;
    const uint32_t* BlG;
    const float* bs = bias;
    uint32_t* outW = (uint32_t*)Cb;   // interleaved KV output (word view)
    int isV = 0;
    bool third;
    if (EPI == EPI_TBL) {
        int layer = blockIdx.y >> 1, kv = blockIdx.y & 1;
        size_t off = (size_t)layer * IMG_LAYER + kv * 12288;
        BhG = BhGbase + off;
        BlG = BlGbase + off;
        A = Ain + (size_t)layer * 65536;
        bs = (kv ? bias2 : bias) + layer * 128;
        outW = (uint32_t*)Cb + (size_t)layer * 65536;   // 512 rows x 128 words
        isV = kv;
        third = false;
    } else {
        BhG = BhGbase + (size_t)blockIdx.y * yStride;
        BlG = BlGbase + (size_t)blockIdx.y * yStride;
        third = (EPI == EPI_NODE) ? (blockIdx.y == 0) : (EPI == EPI_LN || EPI == EPI_MID);
        if (EPI == EPI_NODE && blockIdx.y != 0) {
            bs = nullptr;
            isV = (blockIdx.y == 2);
        }
        if (EPI == EPI_MID) bs = bias + blockIdx.y * 128;
    }

    float acc[2][8][4];
#pragma unroll
    for (int a = 0; a < 2; a++)
#pragma unroll
        for (int b = 0; b < 8; b++)
#pragma unroll
            for (int c = 0; c < 4; c++) acc[a][b][c] = 0.f;

    float4 aS[2];
    uint4 aPh4, aPl4;
    uint2 bPh[3], bPl[3];
    int arow = tid >> 1, apart = (tid & 1) * 4;
    size_t abase = (size_t)(r0 + arow) * 8 + apart;

    // prologue: stage chunk 0 (Bl only on 3-pass paths)
    if (A_IMG) {
        aPh4 = *(const uint4*)(AimgH + abase);
        aPl4 = *(const uint4*)(AimgL + abase);
    } else {
#pragma unroll
        for (int i = 0; i < 2; i++) {
            int j = tid + i * 256;
            int row = j >> 2, c4 = j & 3;
            int gr = r0 + row;
            aS[i] = (gr < M) ? *(const float4*)(A + (size_t)gr * KDIM + c4 * 4)
                             : make_float4(0.f, 0.f, 0.f, 0.f);
        }
    }
#pragma unroll
    for (int i = 0; i < 3; i++) bPh[i] = ((const uint2*)BhG)[tid + i * 256];
    if (third) {
#pragma unroll
        for (int i = 0; i < 3; i++) bPl[i] = ((const uint2*)BlG)[tid + i * 256];
    }

    constexpr int NCH = KDIM / 16;
#pragma unroll 1
    for (int c = 0; c < NCH; c++) {
        int p = c & 1;
        uint32_t* Ah = AhB + p * 1536;
        uint32_t* Al = AlB + p * 1536;
        uint32_t* Bh = BhB + p * 1536;
        uint32_t* Bl = BlB + p * 1536;

        // store staged -> smem[p]
        if (A_IMG) {
            *(uint4*)&Ah[arow * 12 + apart] = aPh4;
            *(uint4*)&Al[arow * 12 + apart] = aPl4;
        } else {
#pragma unroll
            for (int i = 0; i < 2; i++) {
                int j = tid + i * 256;
                int row = j >> 2, c4 = j & 3;
                float4 v = aS[i];
                if (GELU_A) { v.x = gelu_f(v.x); v.y = gelu_f(v.y); v.z = gelu_f(v.z); v.w = gelu_f(v.w); }
                uint32_t h01, l01, h23, l23;
                pack_hl(v.x, v.y, h01, l01);
                pack_hl(v.z, v.w, h23, l23);
                *(uint2*)&Ah[row * 12 + c4 * 2] = make_uint2(h01, h23);
                *(uint2*)&Al[row * 12 + c4 * 2] = make_uint2(l01, l23);
            }
        }
#pragma unroll
        for (int i = 0; i < 3; i++) ((uint2*)Bh)[tid + i * 256] = bPh[i];
        if (third) {
#pragma unroll
            for (int i = 0; i < 3; i++) ((uint2*)Bl)[tid + i * 256] = bPl[i];
        }
        __syncthreads();   // single barrier per chunk (double-buffer safe)

        // prefetch next chunk into registers
        if (c + 1 < NCH) {
            if (A_IMG) {
                size_t off = (size_t)(c + 1) * CHROW + abase;
                aPh4 = *(const uint4*)(AimgH + off);
                aPl4 = *(const uint4*)(AimgL + off);
            } else {
                int kn = (c + 1) * 16;
#pragma unroll
                for (int i = 0; i < 2; i++) {
                    int j = tid + i * 256;
                    int row = j >> 2, c4 = j & 3;
                    int gr = r0 + row;
                    aS[i] = (gr < M) ? *(const float4*)(A + (size_t)gr * KDIM + kn + c4 * 4)
                                     : make_float4(0.f, 0.f, 0.f, 0.f);
                }
            }
            int cb = (c + 1) * chB;
#pragma unroll
            for (int i = 0; i < 3; i++) bPh[i] = ((const uint2*)(BhG + cb))[tid + i * 256];
            if (third) {
#pragma unroll
                for (int i = 0; i < 3; i++) bPl[i] = ((const uint2*)(BlG + cb))[tid + i * 256];
            }
        }

        // fragments + mma (from buffer p)
        uint32_t ah[2][4], al[2][4];
#pragma unroll
        for (int mt = 0; mt < 2; mt++) {
            int r = wrow + mt * 16 + g;
            ah[mt][0] = Ah[r * 12 + q];     ah[mt][1] = Ah[(r + 8) * 12 + q];
            ah[mt][2] = Ah[r * 12 + q + 4]; ah[mt][3] = Ah[(r + 8) * 12 + q + 4];
            al[mt][0] = Al[r * 12 + q];     al[mt][1] = Al[(r + 8) * 12 + q];
            al[mt][2] = Al[r * 12 + q + 4]; al[mt][3] = Al[(r + 8) * 12 + q + 4];
        }
#pragma unroll
        for (int nt = 0; nt < 8; nt++) {
            int n = wcol + nt * 8 + g;
            uint32_t bh[2] = {Bh[n * 12 + q], Bh[n * 12 + q + 4]};
#pragma unroll
            for (int mt = 0; mt < 2; mt++) {
                mma_bf16(acc[mt][nt], ah[mt], bh);
                mma_bf16(acc[mt][nt], al[mt], bh);
            }
            if (third) {
                uint32_t bl[2] = {Bl[n * 12 + q], Bl[n * 12 + q + 4]};
#pragma unroll
                for (int mt = 0; mt < 2; mt++) mma_bf16(acc[mt][nt], ah[mt], bl);
            }
        }
    }
    __syncthreads();

    if (EPI == EPI_LN) {
        int wh = wcol >> 6;
        float s0[2] = {0, 0}, q0[2] = {0, 0}, s1[2] = {0, 0}, q1[2] = {0, 0};
#pragma unroll
        for (int mt = 0; mt < 2; mt++) {
            int ra = r0 + wrow + mt * 16 + g, rb = ra + 8;
#pragma unroll
            for (int nt = 0; nt < 8; nt++) {
                int col = wcol + nt * 8 + q * 2;
                float b0 = bias[col], b1 = bias[col + 1];
                float ra0 = (ra < M) ? res[(size_t)ra * NC + col] : 0.f;
                float ra1 = (ra < M) ? res[(size_t)ra * NC + col + 1] : 0.f;
                float rb0 = (rb < M) ? res[(size_t)rb * NC + col] : 0.f;
                float rb1 = (rb < M) ? res[(size_t)rb * NC + col + 1] : 0.f;
                float va0 = acc[mt][nt][0] + b0 + ra0;
                float va1 = acc[mt][nt][1] + b1 + ra1;
                float vb0 = acc[mt][nt][2] + b0 + rb0;
                float vb1 = acc[mt][nt][3] + b1 + rb1;
                acc[mt][nt][0] = va0; acc[mt][nt][1] = va1;
                acc[mt][nt][2] = vb0; acc[mt][nt][3] = vb1;
                s0[mt] += va0 + va1; q0[mt] += va0 * va0 + va1 * va1;
                s1[mt] += vb0 + vb1; q1[mt] += vb0 * vb0 + vb1 * vb1;
            }
        }
#pragma unroll
        for (int mt = 0; mt < 2; mt++) {
            s0[mt] += __shfl_xor_sync(0xffffffffu, s0[mt], 1);
            s0[mt] += __shfl_xor_sync(0xffffffffu, s0[mt], 2);
            q0[mt] += __shfl_xor_sync(0xffffffffu, q0[mt], 1);
            q0[mt] += __shfl_xor_sync(0xffffffffu, q0[mt], 2);
            s1[mt] += __shfl_xor_sync(0xffffffffu, s1[mt], 1);
            s1[mt] += __shfl_xor_sync(0xffffffffu, s1[mt], 2);
            q1[mt] += __shfl_xor_sync(0xffffffffu, q1[mt], 1);
            q1[mt] += __shfl_xor_sync(0xffffffffu, q1[mt], 2);
            if (q == 0) {
                redS[(wrow + mt * 16 + g) * 2 + wh] = make_float2(s0[mt], q0[mt]);
                redS[(wrow + mt * 16 + 8 + g) * 2 + wh] = make_float2(s1[mt], q1[mt]);
            }
        }
        __syncthreads();
#pragma unroll
        for (int mt = 0; mt < 2; mt++) {
            int lra = wrow + mt * 16 + g;
            float2 p0 = redS[lra * 2], p1 = redS[lra * 2 + 1];
            float2 p0b = redS[(lra + 8) * 2], p1b = redS[(lra + 8) * 2 + 1];
            float sa = p0.x + p1.x, qa = p0.y + p1.y;
            float sb = p0b.x + p1b.x, qb = p0b.y + p1b.y;
            float ma = sa * (1.f / 128.f), mb = sb * (1.f / 128.f);
            float rsa = rsqrtf(qa * (1.f / 128.f) - ma * ma + 1e-5f);
            float rsb = rsqrtf(qb * (1.f / 128.f) - mb * mb + 1e-5f);
            int ra = r0 + lra, rb = ra + 8;
#pragma unroll
            for (int nt = 0; nt < 8; nt++) {
                int col = wcol + nt * 8 + q * 2;
                float g0 = lng[col], g1 = lng[col + 1], o0 = lnb[col], o1 = lnb[col + 1];
                if (ra < M)
                    *(float2*)(C + (size_t)ra * NC + col) =
                        make_float2((acc[mt][nt][0] - ma) * rsa * g0 + o0,
                                    (acc[mt][nt][1] - ma) * rsa * g1 + o1);
                if (rb < M)
                    *(float2*)(C + (size_t)rb * NC + col) =
                        make_float2((acc[mt][nt][2] - mb) * rsb * g0 + o0,
                                    (acc[mt][nt][3] - mb) * rsb * g1 + o1);
            }
        }
    } else if (EPI == EPI_MID) {
#pragma unroll
        for (int mt = 0; mt < 2; mt++) {
            int ra = r0 + wrow + mt * 16 + g, rb = ra + 8;
#pragma unroll
            for (int nt = 0; nt < 8; nt++) {
                int col = wcol + nt * 8 + q * 2;
                float b0 = bs[col], b1 = bs[col + 1];
                float va0 = gelu_f(acc[mt][nt][0] + b0);
                float va1 = gelu_f(acc[mt][nt][1] + b1);
                float vb0 = gelu_f(acc[mt][nt][2] + b0);
                float vb1 = gelu_f(acc[mt][nt][3] + b1);
                int kpl = (wcol >> 1) + nt * 4 + q;       // 0..63
                int ch = ((int)blockIdx.y << 3) + (kpl >> 3);
                int kpin = kpl & 7;
                size_t base = (size_t)ch * CHROW + kpin;
                uint32_t hi, lo;
                if (ra < M) {
                    pack_hl(va0, va1, hi, lo);
                    AimgH[base + (size_t)ra * 8] = hi;
                    AimgL[base + (size_t)ra * 8] = lo;
                }
                if (rb < M) {
                    pack_hl(vb0, vb1, hi, lo);
                    AimgH[base + (size_t)rb * 8] = hi;
                    AimgL[base + (size_t)rb * 8] = lo;
                }
            }
        }
    } else if (EPI == EPI_NODE) {
#pragma unroll
        for (int mt = 0; mt < 2; mt++) {
            int ra = r0 + wrow + mt * 16 + g, rb = ra + 8;
#pragma unroll
            for (int nt = 0; nt < 8; nt++) {
                int col = wcol + nt * 8 + q * 2;
                float b0 = bs ? bs[col] : 0.f, b1 = bs ? bs[col + 1] : 0.f;
                float oa0 = acc[mt][nt][0] + b0, oa1 = acc[mt][nt][1] + b1;
                float ob0 = acc[mt][nt][2] + b0, ob1 = acc[mt][nt][3] + b1;
                if (blockIdx.y == 0) {
                    if (ra < M) *(float2*)(C + (size_t)ra * NC + col) = make_float2(oa0, oa1);
                    if (rb < M) *(float2*)(C + (size_t)rb * NC + col) = make_float2(ob0, ob1);
                } else {
                    // interleaved KV layout: word = n*128 + (col>>2)*4 + ((col&3)>>1) + isV*2
                    int wofs = ((col >> 2) << 2) + ((col & 3) >> 1) + isV * 2;
                    if (ra < M) outW[(size_t)ra * 128 + wofs] = f2bf2(oa0, oa1);
                    if (rb < M) outW[(size_t)rb * 128 + wofs] = f2bf2(ob0, ob1);
                }
            }
        }
    } else {  // EPI_TBL -> interleaved KV table
#pragma unroll
        for (int mt = 0; mt < 2; mt++) {
            int ra = r0 + wrow + mt * 16 + g, rb = ra + 8;
#pragma unroll
            for (int nt = 0; nt < 8; nt++) {
                int col = wcol + nt * 8 + q * 2;
                float b0 = bs[col], b1 = bs[col + 1];
                int wofs = ((col >> 2) << 2) + ((col & 3) >> 1) + isV * 2;
                if (ra < M) outW[(size_t)ra * 128 + wofs] =
                    f2bf2(acc[mt][nt][0] + b0, acc[mt][nt][1] + b1);
                if (rb < M) outW[(size_t)rb * 128 + wofs] =
                    f2bf2(acc[mt][nt][2] + b0, acc[mt][nt][3] + b1);
            }
        }
    }
}

// ---------------- edge attention (interleaved KV: 2 gathers/edge, 2-edge unrolled) ----
__global__ void __launch_bounds__(256) edge_attn_kernel(
    const uint4* __restrict__ KV, const uint4* __restrict__ TB)
{
    int warp = threadIdx.x >> 5, lane = threadIdx.x & 31;
    int n = blockIdx.x * 8 + warp;
    if (n >= NN) return;
    int beg = g_segoff[n], end = g_segoff[n + 1];
    float4 q4 = *(const float4*)(g_Q + (size_t)n * HIDN + lane * 4);
    float den = 0.f, ax = 0.f, ay = 0.f, az = 0.f, aw = 0.f;
    int p = beg;
    for (; p + 2 <= end; p += 2) {
        uint32_t e0 = g_edge[p], e1 = g_edge[p + 1];
        int s0 = (int)(e0 & 0xFFFFu), i0 = (int)(e0 >> 16);
        int s1 = (int)(e1 & 0xFFFFu), i1 = (int)(e1 >> 16);
        uint4 kvs0 = KV[(size_t)s0 * 32 + lane];
        uint4 kvt0 = TB[(size_t)i0 * 32 + lane];
        uint4 kvs1 = KV[(size_t)s1 * 32 + lane];
        uint4 kvt1 = TB[(size_t)i1 * 32 + lane];
        float4 ks0 = unp4(kvs0.x, kvs0.y), vs0 = unp4(kvs0.z, kvs0.w);
        float4 kt0 = unp4(kvt0.x, kvt0.y), vt0 = unp4(kvt0.z, kvt0.w);
        float4 ks1 = unp4(kvs1.x, kvs1.y), vs1 = unp4(kvs1.z, kvs1.w);
        float4 kt1 = unp4(kvt1.x, kvt1.y), vt1 = unp4(kvt1.z, kvt1.w);
        float sc0 = q4.x * (ks0.x + kt0.x) + q4.y * (ks0.y + kt0.y)
                  + q4.z * (ks0.z + kt0.z) + q4.w * (ks0.w + kt0.w);
        float sc1 = q4.x * (ks1.x + kt1.x) + q4.y * (ks1.y + kt1.y)
                  + q4.z * (ks1.z + kt1.z) + q4.w * (ks1.w + kt1.w);
        sc0 += __shfl_xor_sync(0xffffffffu, sc0, 1);
        sc1 += __shfl_xor_sync(0xffffffffu, sc1, 1);
        sc0 += __shfl_xor_sync(0xffffffffu, sc0, 2);
        sc1 += __shfl_xor_sync(0xffffffffu, sc1, 2);
        float w0 = __expf(sc0 * 0.25f);
        float w1 = __expf(sc1 * 0.25f);
        den += w0 + w1;
        ax += w0 * (vs0.x + vt0.x) + w1 * (vs1.x + vt1.x);
        ay += w0 * (vs0.y + vt0.y) + w1 * (vs1.y + vt1.y);
        az += w0 * (vs0.z + vt0.z) + w1 * (vs1.z + vt1.z);
        aw += w0 * (vs0.w + vt0.w) + w1 * (vs1.w + vt1.w);
    }
    if (p < end) {
        uint32_t e0 = g_edge[p];
        int s0 = (int)(e0 & 0xFFFFu), i0 = (int)(e0 >> 16);
        uint4 kvs0 = KV[(size_t)s0 * 32 + lane];
        uint4 kvt0 = TB[(size_t)i0 * 32 + lane];
        float4 ks0 = unp4(kvs0.x, kvs0.y), vs0 = unp4(kvs0.z, kvs0.w);
        float4 kt0 = unp4(kvt0.x, kvt0.y), vt0 = unp4(kvt0.z, kvt0.w);
        float sc0 = q4.x * (ks0.x + kt0.x) + q4.y * (ks0.y + kt0.y)
                  + q4.z * (ks0.z + kt0.z) + q4.w * (ks0.w + kt0.w);
        sc0 += __shfl_xor_sync(0xffffffffu, sc0, 1);
        sc0 += __shfl_xor_sync(0xffffffffu, sc0, 2);
        float w0 = __expf(sc0 * 0.25f);
        den += w0;
        ax += w0 * (vs0.x + vt0.x);
        ay += w0 * (vs0.y + vt0.y);
        az += w0 * (vs0.z + vt0.z);
        aw += w0 * (vs0.w + vt0.w);
    }
    float inv = 1.f / (den + 1e-16f);
    *(float4*)(g_aggr + (size_t)n * HIDN + lane * 4) =
        make_float4(ax * inv, ay * inv, az * inv, aw * inv);
}

// ----------------------------- fused pool + readout -----------------------------
__global__ void pool_readout_kernel(const float* __restrict__ Wout, const float* __restrict__ bout,
                                    float* __restrict__ out) {
    int gi = blockIdx.x;
    int t = threadIdx.x;
    int s = g_goff[gi], e = g_goff[gi + 1];
    float acc = 0.f;
    for (int n = s; n < e; n++) acc += g_x[(size_t)n * HIDN + t];
    float cnt = fmaxf((float)(e - s), 1.f);
    float v = acc / cnt * Wout[t];
    for (int d = 16; d; d >>= 1) v += __shfl_xor_sync(0xffffffffu, v, d);
    __shared__ float sw[4];
    if ((t & 31) == 0) sw[t >> 5] = v;
    __syncthreads();
    if (t == 0) out[gi] = sw[0] + sw[1] + sw[2] + sw[3] + bout[0];
}

// ----------------------------- launch -----------------------------
extern "C" void kernel_launch(void* const* d_in, const int* in_sizes, int n_in,
                              void* d_out, int out_size) {
    const int*   node_attr = (const int*)d_in[0];
    const int*   batch_idx = (const int*)d_in[1];
    const int*   eidx      = (const int*)d_in[2];
    const int*   sdist     = (const int*)d_in[3];
    const int*   spath     = (const int*)d_in[4];
    const float* atom_emb  = (const float*)d_in[5];
    const float* dist_emb  = (const float*)d_in[6];
    const float* path_emb  = (const float*)d_in[7];
    const float* Wq = (const float*)d_in[8];
    const float* bq = (const float*)d_in[9];
    const float* Wk = (const float*)d_in[10];
    const float* bk = (const float*)d_in[11];
    const float* Wv = (const float*)d_in[12];
    const float* bv = (const float*)d_in[13];
    const float* Wa = (const float*)d_in[14];
    const float* ba = (const float*)d_in[15];
    const float* ln1g = (const float*)d_in[16];
    const float* ln1b = (const float*)d_in[17];
    const float* Wmid = (const float*)d_in[18];
    const float* bmid = (const float*)d_in[19];
    const float* Wo = (const float*)d_in[20];
    const float* bo = (const float*)d_in[21];
    const float* ln2g = (const float*)d_in[22];
    const float* ln2b = (const float*)d_in[23];
    const float* Wout = (const float*)d_in[24];
    const float* bout = (const float*)d_in[25];
    float* out = (float*)d_out;

    float *px, *pQ, *pag, *ph, *pcomb;
    __nv_bfloat16 *pKVb, *pTkv;
    uint32_t *pWh, *pWl, *pMh, *pMl;
    cudaGetSymbolAddress((void**)&px, g_x);
    cudaGetSymbolAddress((void**)&pQ, g_Q);
    cudaGetSymbolAddress((void**)&pKVb, g_KVb);
    cudaGetSymbolAddress((void**)&pag, g_aggr);
    cudaGetSymbolAddress((void**)&ph, g_h);
    cudaGetSymbolAddress((void**)&pcomb, g_comb2);
    cudaGetSymbolAddress((void**)&pTkv, g_tKV);
    cudaGetSymbolAddress((void**)&pWh, g_wHi);
    cudaGetSymbolAddress((void**)&pWl, g_wLo);
    cudaGetSymbolAddress((void**)&pMh, g_midH);
    cudaGetSymbolAddress((void**)&pMl, g_midL);

    static bool attr_set = false;
    if (!attr_set) {
        cudaFuncSetAttribute(gemm11_kernel<128, EPI_NODE, false, false>,
                             cudaFuncAttributeMaxDynamicSharedMemorySize, G8_SMEM);
        cudaFuncSetAttribute(gemm11_kernel<128, EPI_TBL, false, false>,
                             cudaFuncAttributeMaxDynamicSharedMemorySize, G8_SMEM);
        cudaFuncSetAttribute(gemm11_kernel<128, EPI_LN, true, false>,
                             cudaFuncAttributeMaxDynamicSharedMemorySize, G8_SMEM);
        cudaFuncSetAttribute(gemm11_kernel<128, EPI_MID, false, false>,
                             cudaFuncAttributeMaxDynamicSharedMemorySize, G8_SMEM);
        cudaFuncSetAttribute(gemm11_kernel<256, EPI_LN, false, true>,
                             cudaFuncAttributeMaxDynamicSharedMemorySize, G8_SMEM);
        attr_set = true;
    }

    const int* esrc = eidx;
    const int* etgt = eidx + EE;
    int grid128 = cdiv_h(NN, 128);

    // ---- launch #4 is the layer-0 QKV GEMM (profiled slot) ----
    zero_kernel<<<cdiv_h(NN, 256), 256>>>();                               // 1
    encoder_kernel<<<512, 128>>>(node_attr, atom_emb);                     // 2
    prepack_kernel<<<512, 256>>>(Wq, Wk, Wv, Wa, Wmid, Wo);                // 3
    gemm11_kernel<128, EPI_NODE, false, false><<<dim3(grid128, 3), 256, G8_SMEM>>>( // 4
        px, pWh + OFF_Q, pWl + OFF_Q, 12288, 1536, nullptr, nullptr, bq, nullptr,
        nullptr, nullptr, nullptr, pQ, pKVb, NN);
    comb2_kernel<<<256, 128>>>(dist_emb, path_emb);                        // 5
    gemm11_kernel<128, EPI_TBL, false, false><<<dim3(4, 4), 256, G8_SMEM>>>( // 6: both layers' tables
        pcomb, pWh + OFF_K, pWl + OFF_K, 0, 1536, nullptr, nullptr, bk, bv,
        nullptr, nullptr, nullptr, nullptr, pTkv, 512);
    count_kernel<<<cdiv_h(EE, 256), 256>>>(etgt, batch_idx);
    scan1_kernel<<<NBLK, 256>>>();
    scan2_kernel<<<1, 256>>>();
    scan3_kernel<<<NBLK, 256>>>();
    scatter_kernel<<<cdiv_h(EE, 256), 256>>>(esrc, etgt, sdist, spath);

    for (int l = 0; l < 2; l++) {
        const uint32_t* wh = pWh + (size_t)l * IMG_LAYER;
        const uint32_t* wl = pWl + (size_t)l * IMG_LAYER;

        if (l == 1) {
            gemm11_kernel<128, EPI_NODE, false, false><<<dim3(grid128, 3), 256, G8_SMEM>>>(
                px, wh + OFF_Q, wl + OFF_Q, 12288, 1536, nullptr, nullptr,
                bq + l * 128, nullptr,
                nullptr, nullptr, nullptr, pQ, pKVb, NN);
        }

        edge_attn_kernel<<<cdiv_h(NN, 8), 256>>>(
            (const uint4*)pKVb, (const uint4*)(pTkv + (size_t)l * 512 * 256));

        // h = LN(gelu(aggr)@Wa + ba + x)
        gemm11_kernel<128, EPI_LN, true, false><<<dim3(grid128, 1), 256, G8_SMEM>>>(
            pag, wh + OFF_A, wl + OFF_A, 0, 1536, nullptr, nullptr, ba + l * 128, nullptr,
            px, ln1g + l * 128, ln1b + l * 128, ph, nullptr, NN);
        // mid = gelu(h@Wmid + bmid) -> global bf16 hi/lo image (chunk-major)
        gemm11_kernel<128, EPI_MID, false, false><<<dim3(grid128, 2), 256, G8_SMEM>>>(
            ph, wh + OFF_M, wl + OFF_M, 1536, 3072, pMh, pMl, bmid + l * 256, nullptr,
            nullptr, nullptr, nullptr, nullptr, nullptr, NN);
        // x = LN(mid@Wo + bo + h), A streamed from the mid image (pure memcpy staging)
        gemm11_kernel<256, EPI_LN, false, true><<<dim3(grid128, 1), 256, G8_SMEM>>>(
            nullptr, wh + OFF_O, wl + OFF_O, 0, 1536, pMh, pMl, bo + l * 128, nullptr,
            ph, ln2g + l * 128, ln2b + l * 128, px, nullptr, NN);
    }

    pool_readout_kernel<<<GG, 128>>>(Wout, bout, out);
}

// round 15
// speedup vs baseline: 1.1191x; 1.0623x over previous
#include <cuda_runtime.h>
#include <cuda_bf16.h>
#include <math.h>
#include <stdint.h>

#define NN 50000
#define EE 800000
#define HIDN 128
#define GG 256
#define NBLK 49    // ceil(NN/1024)
#define CHROW 400384  // 50048 rows * 8 words, per-chunk stride of the mid image

static inline int cdiv_h(int a, int b) { return (a + b - 1) / b; }

// ----------------------------- scratch (device globals) -----------------------------
__device__ float g_x[NN * HIDN];
__device__ float g_Q[NN * HIDN];
__device__ __nv_bfloat16 g_KVb[NN * 256];        // interleaved K|V per node: [k4|v4] x 32 groups
__device__ float g_aggr[NN * HIDN];
__device__ float g_h[NN * HIDN];
__device__ float g_comb2[2 * 512 * HIDN];
__device__ __nv_bfloat16 g_tKV[2 * 512 * 256];   // interleaved K|V tables (per layer)
__device__ uint32_t g_wHi[196608];   // prepacked weights (bf16 hi), smem-image layout
__device__ uint32_t g_wLo[196608];   // prepacked weights (bf16 lo residual; unused in 2-pass mode)
__device__ uint32_t g_midH[16 * CHROW];  // FFN mid image (bf16 hi), chunk-major
__device__ uint32_t g_midL[16 * CHROW];  // FFN mid image (bf16 lo)
__device__ int   g_cnt[NN];
__device__ int   g_segoff[NN + 1];
__device__ int   g_cursor[NN];
__device__ uint32_t g_edge[EE];      // packed: src | (dp<<16)
__device__ int   g_bsum[64];
__device__ int   g_boff[64];
__device__ int   g_gcnt[GG];
__device__ int   g_goff[GG + 1];

// image layout constants (words): per layer 98304
#define IMG_LAYER 98304
#define OFF_Q 0
#define OFF_K 12288
#define OFF_V 24576
#define OFF_A 36864
#define OFF_M 49152
#define OFF_O 73728

// ----------------------------- helpers -----------------------------
__device__ __forceinline__ float gelu_f(float x) {
    return 0.5f * x * (1.0f + erff(x * 0.7071067811865476f));
}

__device__ __forceinline__ void mma_bf16(float c[4], const uint32_t a[4], const uint32_t b[2]) {
    asm volatile(
        "mma.sync.aligned.m16n8k16.row.col.f32.bf16.bf16.f32 "
        "{%0,%1,%2,%3}, {%4,%5,%6,%7}, {%8,%9}, {%0,%1,%2,%3};"
        : "+f"(c[0]), "+f"(c[1]), "+f"(c[2]), "+f"(c[3])
        : "r"(a[0]), "r"(a[1]), "r"(a[2]), "r"(a[3]), "r"(b[0]), "r"(b[1]));
}

__device__ __forceinline__ void pack_hl(float x, float y, uint32_t& hi, uint32_t& lo) {
    __nv_bfloat16 hx = __float2bfloat16(x);
    __nv_bfloat16 hy = __float2bfloat16(y);
    __nv_bfloat16 lx = __float2bfloat16(x - __bfloat162float(hx));
    __nv_bfloat16 ly = __float2bfloat16(y - __bfloat162float(hy));
    __nv_bfloat162 h2 = __halves2bfloat162(hx, hy);
    __nv_bfloat162 l2 = __halves2bfloat162(lx, ly);
    hi = *(uint32_t*)&h2;
    lo = *(uint32_t*)&l2;
}

__device__ __forceinline__ float4 unp4(uint32_t a, uint32_t b) {
    __nv_bfloat162 x = *(__nv_bfloat162*)&a;
    __nv_bfloat162 y = *(__nv_bfloat162*)&b;
    float2 fx = __bfloat1622float2(x), fy = __bfloat1622float2(y);
    return make_float4(fx.x, fx.y, fy.x, fy.y);
}

__device__ __forceinline__ uint32_t f2bf2(float a, float b) {
    __nv_bfloat162 t = __halves2bfloat162(__float2bfloat16(a), __float2bfloat16(b));
    return *(uint32_t*)&t;
}

// ----------------------------- misc kernels -----------------------------
__global__ void zero_kernel() {
    int i = blockIdx.x * blockDim.x + threadIdx.x;
    if (i < NN) g_cnt[i] = 0;
    if (i < GG) g_gcnt[i] = 0;
}

__global__ void encoder_kernel(const int* __restrict__ attr, const float* __restrict__ aemb) {
    int c = threadIdx.x;
    for (int n = blockIdx.x; n < NN; n += gridDim.x) {
        int a0 = attr[n * 4 + 0], a1 = attr[n * 4 + 1], a2 = attr[n * 4 + 2], a3 = attr[n * 4 + 3];
        float v = aemb[(0 * 64 + a0) * HIDN + c] + aemb[(1 * 64 + a1) * HIDN + c]
                + aemb[(2 * 64 + a2) * HIDN + c] + aemb[(3 * 64 + a3) * HIDN + c];
        g_x[(size_t)n * HIDN + c] = v;
    }
}

// prepack ALL weights into GEMM smem-image layout (bf16 hi/lo, kpair-packed, n-major, stride 12)
__global__ void prepack_kernel(const float* __restrict__ Wq, const float* __restrict__ Wk,
                               const float* __restrict__ Wv, const float* __restrict__ Wa,
                               const float* __restrict__ Wm, const float* __restrict__ Wo) {
    for (int id = blockIdx.x * blockDim.x + threadIdx.x; id < 131072;
         id += gridDim.x * blockDim.x) {
        int layer = id >> 16;
        int r = id & 65535;
        const float* W; int N; int segoff; int wi;
        if (r < 32768) {
            int m = r >> 13; wi = r & 8191;
            W = (m == 0 ? Wq : m == 1 ? Wk : m == 2 ? Wv : Wa) + layer * 16384;
            N = 128; segoff = m * 12288;
        } else if (r < 49152) {
            wi = r - 32768; W = Wm + layer * 32768; N = 256; segoff = OFF_M;
        } else {
            wi = r - 49152; W = Wo + layer * 32768; N = 128; segoff = OFF_O;
        }
        int ch = wi / (8 * N);
        int rem = wi % (8 * N);
        int kp = rem / N;
        int n = rem % N;
        int k = ch * 16 + kp * 2;
        float a = W[(size_t)k * N + n], b = W[(size_t)(k + 1) * N + n];
        uint32_t hi, lo;
        pack_hl(a, b, hi, lo);
        int w = layer * IMG_LAYER + segoff + ch * N * 12 + n * 12 + kp;
        g_wHi[w] = hi;
        g_wLo[w] = lo;
    }
}

__global__ void count_kernel(const int* __restrict__ tgt, const int* __restrict__ bidx) {
    int i = blockIdx.x * blockDim.x + threadIdx.x;
    if (i < EE) atomicAdd(&g_cnt[tgt[i]], 1);
    if (i < NN) atomicAdd(&g_gcnt[bidx[i]], 1);
}

__global__ void scan1_kernel() {
    __shared__ int sh[256];
    int blk = blockIdx.x, t = threadIdx.x;
    int idx4 = blk * 256 + t;
    int4 v4 = make_int4(0, 0, 0, 0);
    if (idx4 < NN / 4) v4 = ((const int4*)g_cnt)[idx4];
    int s = v4.x + v4.y + v4.z + v4.w;
    sh[t] = s;
    __syncthreads();
    for (int d = 1; d < 256; d <<= 1) {
        int v = (t >= d) ? sh[t - d] : 0;
        __syncthreads();
        sh[t] += v;
        __syncthreads();
    }
    int run = (t == 0) ? 0 : sh[t - 1];
    int base = blk * 1024 + t * 4;
    int vv[4] = {v4.x, v4.y, v4.z, v4.w};
    for (int j = 0; j < 4; j++) {
        if (base + j < NN) g_segoff[base + j] = run;
        run += vv[j];
    }
    if (t == 255) g_bsum[blk] = sh[255];
}

__global__ void scan2_kernel() {
    __shared__ int sg[256];
    __shared__ int sb[64];
    int t = threadIdx.x;
    sg[t] = g_gcnt[t];
    if (t < 64) sb[t] = (t < NBLK) ? g_bsum[t] : 0;
    __syncthreads();
    for (int d = 1; d < 256; d <<= 1) {
        int v = (t >= d) ? sg[t - d] : 0;
        int v2 = 0;
        if (t < 64 && t >= d && d < 64) v2 = sb[t - d];
        __syncthreads();
        sg[t] += v;
        if (t < 64 && d < 64) sb[t] += v2;
        __syncthreads();
    }
    g_goff[t + 1] = sg[t];
    if (t == 0) g_goff[0] = 0;
    if (t < 64) g_boff[t] = (t == 0) ? 0 : sb[t - 1];
}

__global__ void scan3_kernel() {
    int blk = blockIdx.x, t = threadIdx.x;
    int off = g_boff[blk];
    int base = blk * 1024 + t * 4;
    for (int j = 0; j < 4; j++) {
        int i = base + j;
        if (i < NN) {
            int v = g_segoff[i] + off;
            g_segoff[i] = v;
            g_cursor[i] = v;
        }
    }
    if (blk == 0 && t == 0) g_segoff[NN] = EE;
}

__global__ void scatter_kernel(const int* __restrict__ src, const int* __restrict__ tgt,
                               const int* __restrict__ sdist, const int* __restrict__ spath) {
    int i = blockIdx.x * blockDim.x + threadIdx.x;
    if (i < EE) {
        int tg = tgt[i];
        int pos = atomicAdd(&g_cursor[tg], 1);
        uint32_t dp = (uint32_t)((sdist[i] << 4) | spath[i]);
        g_edge[pos] = (uint32_t)src[i] | (dp << 16);
    }
}

// combine dist+path embeddings for BOTH layers
__global__ void comb2_kernel(const float* __restrict__ de, const float* __restrict__ pe) {
    int c = threadIdx.x;
    for (int r = blockIdx.x; r < 1024; r += gridDim.x) {
        int l = r >> 9;
        int rr = r & 511;
        int d = rr >> 4, p = rr & 15;
        g_comb2[r * HIDN + c] = de[(l * 32 + d) * HIDN + c] + pe[(l * 16 + p) * HIDN + c];
    }
}

// ------------- GEMM (double-buffered, register-staged B, 2-pass bf16: weights in bf16)
enum { EPI_LN = 2, EPI_NODE = 3, EPI_TBL = 4, EPI_MID = 5 };
#define G8_SMEM 51200

template <int KDIM, int EPI, bool GELU_A, bool A_IMG>
__global__ void __launch_bounds__(256) gemm12_kernel(
    const float* __restrict__ Ain,
    const uint32_t* __restrict__ BhGbase, const uint32_t* __restrict__ BlGbase,
    int yStride, int chB,
    uint32_t* __restrict__ AimgH, uint32_t* __restrict__ AimgL,
    const float* __restrict__ bias, const float* __restrict__ bias2,
    const float* __restrict__ res, const float* __restrict__ lng, const float* __restrict__ lnb,
    float* __restrict__ C, __nv_bfloat16* __restrict__ Cb,
    int M)
{
    constexpr int TM = 128;
    constexpr int NC = 128;

    extern __shared__ uint32_t dyn[];
    uint32_t* AhB = dyn;             // 2 x 1536
    uint32_t* AlB = AhB + 3072;
    uint32_t* BhB = AlB + 3072;
    float2* redS = (float2*)(BhB + 3072);  // 128 x 2

    int tid = threadIdx.x;
    int wid = tid >> 5, lane = tid & 31;
    int g = lane >> 2, q = lane & 3;
    int wrow = (wid & 3) * 32;
    int wcol = (wid >> 2) * 64;
    int r0 = blockIdx.x * TM;

    const float* A = Ain;
    const uint32_t* BhG;
    const float* bs = bias;
    uint32_t* outW = (uint32_t*)Cb;   // interleaved KV output (word view)
    int isV = 0;
    if (EPI == EPI_TBL) {
        int layer = blockIdx.y >> 1, kv = blockIdx.y & 1;
        size_t off = (size_t)layer * IMG_LAYER + kv * 12288;
        BhG = BhGbase + off;
        A = Ain + (size_t)layer * 65536;
        bs = (kv ? bias2 : bias) + layer * 128;
        outW = (uint32_t*)Cb + (size_t)layer * 65536;   // 512 rows x 128 words
        isV = kv;
    } else {
        BhG = BhGbase + (size_t)blockIdx.y * yStride;
        if (EPI == EPI_NODE && blockIdx.y != 0) {
            bs = nullptr;
            isV = (blockIdx.y == 2);
        }
        if (EPI == EPI_MID) bs = bias + blockIdx.y * 128;
    }
    (void)BlGbase;

    float acc[2][8][4];
#pragma unroll
    for (int a = 0; a < 2; a++)
#pragma unroll
        for (int b = 0; b < 8; b++)
#pragma unroll
            for (int c = 0; c < 4; c++) acc[a][b][c] = 0.f;

    float4 aS[2];
    uint4 aPh4, aPl4;
    uint2 bPh[3];
    int arow = tid >> 1, apart = (tid & 1) * 4;
    size_t abase = (size_t)(r0 + arow) * 8 + apart;

    // prologue: stage chunk 0
    if (A_IMG) {
        aPh4 = *(const uint4*)(AimgH + abase);
        aPl4 = *(const uint4*)(AimgL + abase);
    } else {
#pragma unroll
        for (int i = 0; i < 2; i++) {
            int j = tid + i * 256;
            int row = j >> 2, c4 = j & 3;
            int gr = r0 + row;
            aS[i] = (gr < M) ? *(const float4*)(A + (size_t)gr * KDIM + c4 * 4)
                             : make_float4(0.f, 0.f, 0.f, 0.f);
        }
    }
#pragma unroll
    for (int i = 0; i < 3; i++) bPh[i] = ((const uint2*)BhG)[tid + i * 256];

    constexpr int NCH = KDIM / 16;
#pragma unroll 1
    for (int c = 0; c < NCH; c++) {
        int p = c & 1;
        uint32_t* Ah = AhB + p * 1536;
        uint32_t* Al = AlB + p * 1536;
        uint32_t* Bh = BhB + p * 1536;

        // store staged -> smem[p]
        if (A_IMG) {
            *(uint4*)&Ah[arow * 12 + apart] = aPh4;
            *(uint4*)&Al[arow * 12 + apart] = aPl4;
        } else {
#pragma unroll
            for (int i = 0; i < 2; i++) {
                int j = tid + i * 256;
                int row = j >> 2, c4 = j & 3;
                float4 v = aS[i];
                if (GELU_A) { v.x = gelu_f(v.x); v.y = gelu_f(v.y); v.z = gelu_f(v.z); v.w = gelu_f(v.w); }
                uint32_t h01, l01, h23, l23;
                pack_hl(v.x, v.y, h01, l01);
                pack_hl(v.z, v.w, h23, l23);
                *(uint2*)&Ah[row * 12 + c4 * 2] = make_uint2(h01, h23);
                *(uint2*)&Al[row * 12 + c4 * 2] = make_uint2(l01, l23);
            }
        }
#pragma unroll
        for (int i = 0; i < 3; i++) ((uint2*)Bh)[tid + i * 256] = bPh[i];
        __syncthreads();   // single barrier per chunk (double-buffer safe)

        // prefetch next chunk into registers
        if (c + 1 < NCH) {
            if (A_IMG) {
                size_t off = (size_t)(c + 1) * CHROW + abase;
                aPh4 = *(const uint4*)(AimgH + off);
                aPl4 = *(const uint4*)(AimgL + off);
            } else {
                int kn = (c + 1) * 16;
#pragma unroll
                for (int i = 0; i < 2; i++) {
                    int j = tid + i * 256;
                    int row = j >> 2, c4 = j & 3;
                    int gr = r0 + row;
                    aS[i] = (gr < M) ? *(const float4*)(A + (size_t)gr * KDIM + kn + c4 * 4)
                                     : make_float4(0.f, 0.f, 0.f, 0.f);
                }
            }
            int cb = (c + 1) * chB;
#pragma unroll
            for (int i = 0; i < 3; i++) bPh[i] = ((const uint2*)(BhG + cb))[tid + i * 256];
        }

        // fragments + mma (from buffer p): 2 passes (A hi+lo) x (B hi)
        uint32_t ah[2][4], al[2][4];
#pragma unroll
        for (int mt = 0; mt < 2; mt++) {
            int r = wrow + mt * 16 + g;
            ah[mt][0] = Ah[r * 12 + q];     ah[mt][1] = Ah[(r + 8) * 12 + q];
            ah[mt][2] = Ah[r * 12 + q + 4]; ah[mt][3] = Ah[(r + 8) * 12 + q + 4];
            al[mt][0] = Al[r * 12 + q];     al[mt][1] = Al[(r + 8) * 12 + q];
            al[mt][2] = Al[r * 12 + q + 4]; al[mt][3] = Al[(r + 8) * 12 + q + 4];
        }
#pragma unroll
        for (int nt = 0; nt < 8; nt++) {
            int n = wcol + nt * 8 + g;
            uint32_t bh[2] = {Bh[n * 12 + q], Bh[n * 12 + q + 4]};
#pragma unroll
            for (int mt = 0; mt < 2; mt++) {
                mma_bf16(acc[mt][nt], ah[mt], bh);
                mma_bf16(acc[mt][nt], al[mt], bh);
            }
        }
    }
    __syncthreads();

    if (EPI == EPI_LN) {
        int wh = wcol >> 6;
        float s0[2] = {0, 0}, q0[2] = {0, 0}, s1[2] = {0, 0}, q1[2] = {0, 0};
#pragma unroll
        for (int mt = 0; mt < 2; mt++) {
            int ra = r0 + wrow + mt * 16 + g, rb = ra + 8;
#pragma unroll
            for (int nt = 0; nt < 8; nt++) {
                int col = wcol + nt * 8 + q * 2;
                float b0 = bias[col], b1 = bias[col + 1];
                float ra0 = (ra < M) ? res[(size_t)ra * NC + col] : 0.f;
                float ra1 = (ra < M) ? res[(size_t)ra * NC + col + 1] : 0.f;
                float rb0 = (rb < M) ? res[(size_t)rb * NC + col] : 0.f;
                float rb1 = (rb < M) ? res[(size_t)rb * NC + col + 1] : 0.f;
                float va0 = acc[mt][nt][0] + b0 + ra0;
                float va1 = acc[mt][nt][1] + b1 + ra1;
                float vb0 = acc[mt][nt][2] + b0 + rb0;
                float vb1 = acc[mt][nt][3] + b1 + rb1;
                acc[mt][nt][0] = va0; acc[mt][nt][1] = va1;
                acc[mt][nt][2] = vb0; acc[mt][nt][3] = vb1;
                s0[mt] += va0 + va1; q0[mt] += va0 * va0 + va1 * va1;
                s1[mt] += vb0 + vb1; q1[mt] += vb0 * vb0 + vb1 * vb1;
            }
        }
#pragma unroll
        for (int mt = 0; mt < 2; mt++) {
            s0[mt] += __shfl_xor_sync(0xffffffffu, s0[mt], 1);
            s0[mt] += __shfl_xor_sync(0xffffffffu, s0[mt], 2);
            q0[mt] += __shfl_xor_sync(0xffffffffu, q0[mt], 1);
            q0[mt] += __shfl_xor_sync(0xffffffffu, q0[mt], 2);
            s1[mt] += __shfl_xor_sync(0xffffffffu, s1[mt], 1);
            s1[mt] += __shfl_xor_sync(0xffffffffu, s1[mt], 2);
            q1[mt] += __shfl_xor_sync(0xffffffffu, q1[mt], 1);
            q1[mt] += __shfl_xor_sync(0xffffffffu, q1[mt], 2);
            if (q == 0) {
                redS[(wrow + mt * 16 + g) * 2 + wh] = make_float2(s0[mt], q0[mt]);
                redS[(wrow + mt * 16 + 8 + g) * 2 + wh] = make_float2(s1[mt], q1[mt]);
            }
        }
        __syncthreads();
#pragma unroll
        for (int mt = 0; mt < 2; mt++) {
            int lra = wrow + mt * 16 + g;
            float2 p0 = redS[lra * 2], p1 = redS[lra * 2 + 1];
            float2 p0b = redS[(lra + 8) * 2], p1b = redS[(lra + 8) * 2 + 1];
            float sa = p0.x + p1.x, qa = p0.y + p1.y;
            float sb = p0b.x + p1b.x, qb = p0b.y + p1b.y;
            float ma = sa * (1.f / 128.f), mb = sb * (1.f / 128.f);
            float rsa = rsqrtf(qa * (1.f / 128.f) - ma * ma + 1e-5f);
            float rsb = rsqrtf(qb * (1.f / 128.f) - mb * mb + 1e-5f);
            int ra = r0 + lra, rb = ra + 8;
#pragma unroll
            for (int nt = 0; nt < 8; nt++) {
                int col = wcol + nt * 8 + q * 2;
                float g0 = lng[col], g1 = lng[col + 1], o0 = lnb[col], o1 = lnb[col + 1];
                if (ra < M)
                    *(float2*)(C + (size_t)ra * NC + col) =
                        make_float2((acc[mt][nt][0] - ma) * rsa * g0 + o0,
                                    (acc[mt][nt][1] - ma) * rsa * g1 + o1);
                if (rb < M)
                    *(float2*)(C + (size_t)rb * NC + col) =
                        make_float2((acc[mt][nt][2] - mb) * rsb * g0 + o0,
                                    (acc[mt][nt][3] - mb) * rsb * g1 + o1);
            }
        }
    } else if (EPI == EPI_MID) {
#pragma unroll
        for (int mt = 0; mt < 2; mt++) {
            int ra = r0 + wrow + mt * 16 + g, rb = ra + 8;
#pragma unroll
            for (int nt = 0; nt < 8; nt++) {
                int col = wcol + nt * 8 + q * 2;
                float b0 = bs[col], b1 = bs[col + 1];
                float va0 = gelu_f(acc[mt][nt][0] + b0);
                float va1 = gelu_f(acc[mt][nt][1] + b1);
                float vb0 = gelu_f(acc[mt][nt][2] + b0);
                float vb1 = gelu_f(acc[mt][nt][3] + b1);
                int kpl = (wcol >> 1) + nt * 4 + q;       // 0..63
                int ch = ((int)blockIdx.y << 3) + (kpl >> 3);
                int kpin = kpl & 7;
                size_t base = (size_t)ch * CHROW + kpin;
                uint32_t hi, lo;
                if (ra < M) {
                    pack_hl(va0, va1, hi, lo);
                    AimgH[base + (size_t)ra * 8] = hi;
                    AimgL[base + (size_t)ra * 8] = lo;
                }
                if (rb < M) {
                    pack_hl(vb0, vb1, hi, lo);
                    AimgH[base + (size_t)rb * 8] = hi;
                    AimgL[base + (size_t)rb * 8] = lo;
                }
            }
        }
    } else if (EPI == EPI_NODE) {
#pragma unroll
        for (int mt = 0; mt < 2; mt++) {
            int ra = r0 + wrow + mt * 16 + g, rb = ra + 8;
#pragma unroll
            for (int nt = 0; nt < 8; nt++) {
                int col = wcol + nt * 8 + q * 2;
                float b0 = bs ? bs[col] : 0.f, b1 = bs ? bs[col + 1] : 0.f;
                float oa0 = acc[mt][nt][0] + b0, oa1 = acc[mt][nt][1] + b1;
                float ob0 = acc[mt][nt][2] + b0, ob1 = acc[mt][nt][3] + b1;
                if (blockIdx.y == 0) {
                    if (ra < M) *(float2*)(C + (size_t)ra * NC + col) = make_float2(oa0, oa1);
                    if (rb < M) *(float2*)(C + (size_t)rb * NC + col) = make_float2(ob0, ob1);
                } else {
                    // interleaved KV layout: word = n*128 + (col>>2)*4 + ((col&3)>>1) + isV*2
                    int wofs = ((col >> 2) << 2) + ((col & 3) >> 1) + isV * 2;
                    if (ra < M) outW[(size_t)ra * 128 + wofs] = f2bf2(oa0, oa1);
                    if (rb < M) outW[(size_t)rb * 128 + wofs] = f2bf2(ob0, ob1);
                }
            }
        }
    } else {  // EPI_TBL -> interleaved KV table
#pragma unroll
        for (int mt = 0; mt < 2; mt++) {
            int ra = r0 + wrow + mt * 16 + g, rb = ra + 8;
#pragma unroll
            for (int nt = 0; nt < 8; nt++) {
                int col = wcol + nt * 8 + q * 2;
                float b0 = bs[col], b1 = bs[col + 1];
                int wofs = ((col >> 2) << 2) + ((col & 3) >> 1) + isV * 2;
                if (ra < M) outW[(size_t)ra * 128 + wofs] =
                    f2bf2(acc[mt][nt][0] + b0, acc[mt][nt][1] + b1);
                if (rb < M) outW[(size_t)rb * 128 + wofs] =
                    f2bf2(acc[mt][nt][2] + b0, acc[mt][nt][3] + b1);
            }
        }
    }
}

// ---------------- edge attention (interleaved KV: 2 gathers/edge, 2-edge unrolled) ----
__global__ void __launch_bounds__(256) edge_attn_kernel(
    const uint4* __restrict__ KV, const uint4* __restrict__ TB)
{
    int warp = threadIdx.x >> 5, lane = threadIdx.x & 31;
    int n = blockIdx.x * 8 + warp;
    if (n >= NN) return;
    int beg = g_segoff[n], end = g_segoff[n + 1];
    float4 q4 = *(const float4*)(g_Q + (size_t)n * HIDN + lane * 4);
    float den = 0.f, ax = 0.f, ay = 0.f, az = 0.f, aw = 0.f;
    int p = beg;
    for (; p + 2 <= end; p += 2) {
        uint32_t e0 = g_edge[p], e1 = g_edge[p + 1];
        int s0 = (int)(e0 & 0xFFFFu), i0 = (int)(e0 >> 16);
        int s1 = (int)(e1 & 0xFFFFu), i1 = (int)(e1 >> 16);
        uint4 kvs0 = KV[(size_t)s0 * 32 + lane];
        uint4 kvt0 = TB[(size_t)i0 * 32 + lane];
        uint4 kvs1 = KV[(size_t)s1 * 32 + lane];
        uint4 kvt1 = TB[(size_t)i1 * 32 + lane];
        float4 ks0 = unp4(kvs0.x, kvs0.y), vs0 = unp4(kvs0.z, kvs0.w);
        float4 kt0 = unp4(kvt0.x, kvt0.y), vt0 = unp4(kvt0.z, kvt0.w);
        float4 ks1 = unp4(kvs1.x, kvs1.y), vs1 = unp4(kvs1.z, kvs1.w);
        float4 kt1 = unp4(kvt1.x, kvt1.y), vt1 = unp4(kvt1.z, kvt1.w);
        float sc0 = q4.x * (ks0.x + kt0.x) + q4.y * (ks0.y + kt0.y)
                  + q4.z * (ks0.z + kt0.z) + q4.w * (ks0.w + kt0.w);
        float sc1 = q4.x * (ks1.x + kt1.x) + q4.y * (ks1.y + kt1.y)
                  + q4.z * (ks1.z + kt1.z) + q4.w * (ks1.w + kt1.w);
        sc0 += __shfl_xor_sync(0xffffffffu, sc0, 1);
        sc1 += __shfl_xor_sync(0xffffffffu, sc1, 1);
        sc0 += __shfl_xor_sync(0xffffffffu, sc0, 2);
        sc1 += __shfl_xor_sync(0xffffffffu, sc1, 2);
        float w0 = __expf(sc0 * 0.25f);
        float w1 = __expf(sc1 * 0.25f);
        den += w0 + w1;
        ax += w0 * (vs0.x + vt0.x) + w1 * (vs1.x + vt1.x);
        ay += w0 * (vs0.y + vt0.y) + w1 * (vs1.y + vt1.y);
        az += w0 * (vs0.z + vt0.z) + w1 * (vs1.z + vt1.z);
        aw += w0 * (vs0.w + vt0.w) + w1 * (vs1.w + vt1.w);
    }
    if (p < end) {
        uint32_t e0 = g_edge[p];
        int s0 = (int)(e0 & 0xFFFFu), i0 = (int)(e0 >> 16);
        uint4 kvs0 = KV[(size_t)s0 * 32 + lane];
        uint4 kvt0 = TB[(size_t)i0 * 32 + lane];
        float4 ks0 = unp4(kvs0.x, kvs0.y), vs0 = unp4(kvs0.z, kvs0.w);
        float4 kt0 = unp4(kvt0.x, kvt0.y), vt0 = unp4(kvt0.z, kvt0.w);
        float sc0 = q4.x * (ks0.x + kt0.x) + q4.y * (ks0.y + kt0.y)
                  + q4.z * (ks0.z + kt0.z) + q4.w * (ks0.w + kt0.w);
        sc0 += __shfl_xor_sync(0xffffffffu, sc0, 1);
        sc0 += __shfl_xor_sync(0xffffffffu, sc0, 2);
        float w0 = __expf(sc0 * 0.25f);
        den += w0;
        ax += w0 * (vs0.x + vt0.x);
        ay += w0 * (vs0.y + vt0.y);
        az += w0 * (vs0.z + vt0.z);
        aw += w0 * (vs0.w + vt0.w);
    }
    float inv = 1.f / (den + 1e-16f);
    *(float4*)(g_aggr + (size_t)n * HIDN + lane * 4) =
        make_float4(ax * inv, ay * inv, az * inv, aw * inv);
}

// ----------------------------- fused pool + readout -----------------------------
__global__ void pool_readout_kernel(const float* __restrict__ Wout, const float* __restrict__ bout,
                                    float* __restrict__ out) {
    int gi = blockIdx.x;
    int t = threadIdx.x;
    int s = g_goff[gi], e = g_goff[gi + 1];
    float acc = 0.f;
    for (int n = s; n < e; n++) acc += g_x[(size_t)n * HIDN + t];
    float cnt = fmaxf((float)(e - s), 1.f);
    float v = acc / cnt * Wout[t];
    for (int d = 16; d; d >>= 1) v += __shfl_xor_sync(0xffffffffu, v, d);
    __shared__ float sw[4];
    if ((t & 31) == 0) sw[t >> 5] = v;
    __syncthreads();
    if (t == 0) out[gi] = sw[0] + sw[1] + sw[2] + sw[3] + bout[0];
}

// ----------------------------- launch -----------------------------
extern "C" void kernel_launch(void* const* d_in, const int* in_sizes, int n_in,
                              void* d_out, int out_size) {
    const int*   node_attr = (const int*)d_in[0];
    const int*   batch_idx = (const int*)d_in[1];
    const int*   eidx      = (const int*)d_in[2];
    const int*   sdist     = (const int*)d_in[3];
    const int*   spath     = (const int*)d_in[4];
    const float* atom_emb  = (const float*)d_in[5];
    const float* dist_emb  = (const float*)d_in[6];
    const float* path_emb  = (const float*)d_in[7];
    const float* Wq = (const float*)d_in[8];
    const float* bq = (const float*)d_in[9];
    const float* Wk = (const float*)d_in[10];
    const float* bk = (const float*)d_in[11];
    const float* Wv = (const float*)d_in[12];
    const float* bv = (const float*)d_in[13];
    const float* Wa = (const float*)d_in[14];
    const float* ba = (const float*)d_in[15];
    const float* ln1g = (const float*)d_in[16];
    const float* ln1b = (const float*)d_in[17];
    const float* Wmid = (const float*)d_in[18];
    const float* bmid = (const float*)d_in[19];
    const float* Wo = (const float*)d_in[20];
    const float* bo = (const float*)d_in[21];
    const float* ln2g = (const float*)d_in[22];
    const float* ln2b = (const float*)d_in[23];
    const float* Wout = (const float*)d_in[24];
    const float* bout = (const float*)d_in[25];
    float* out = (float*)d_out;

    float *px, *pQ, *pag, *ph, *pcomb;
    __nv_bfloat16 *pKVb, *pTkv;
    uint32_t *pWh, *pWl, *pMh, *pMl;
    cudaGetSymbolAddress((void**)&px, g_x);
    cudaGetSymbolAddress((void**)&pQ, g_Q);
    cudaGetSymbolAddress((void**)&pKVb, g_KVb);
    cudaGetSymbolAddress((void**)&pag, g_aggr);
    cudaGetSymbolAddress((void**)&ph, g_h);
    cudaGetSymbolAddress((void**)&pcomb, g_comb2);
    cudaGetSymbolAddress((void**)&pTkv, g_tKV);
    cudaGetSymbolAddress((void**)&pWh, g_wHi);
    cudaGetSymbolAddress((void**)&pWl, g_wLo);
    cudaGetSymbolAddress((void**)&pMh, g_midH);
    cudaGetSymbolAddress((void**)&pMl, g_midL);

    static bool attr_set = false;
    if (!attr_set) {
        cudaFuncSetAttribute(gemm12_kernel<128, EPI_NODE, false, false>,
                             cudaFuncAttributeMaxDynamicSharedMemorySize, G8_SMEM);
        cudaFuncSetAttribute(gemm12_kernel<128, EPI_TBL, false, false>,
                             cudaFuncAttributeMaxDynamicSharedMemorySize, G8_SMEM);
        cudaFuncSetAttribute(gemm12_kernel<128, EPI_LN, true, false>,
                             cudaFuncAttributeMaxDynamicSharedMemorySize, G8_SMEM);
        cudaFuncSetAttribute(gemm12_kernel<128, EPI_MID, false, false>,
                             cudaFuncAttributeMaxDynamicSharedMemorySize, G8_SMEM);
        cudaFuncSetAttribute(gemm12_kernel<256, EPI_LN, false, true>,
                             cudaFuncAttributeMaxDynamicSharedMemorySize, G8_SMEM);
        attr_set = true;
    }

    const int* esrc = eidx;
    const int* etgt = eidx + EE;
    int grid128 = cdiv_h(NN, 128);

    // ---- launch #4 is the layer-0 QKV GEMM (profiled slot) ----
    zero_kernel<<<cdiv_h(NN, 256), 256>>>();                               // 1
    encoder_kernel<<<512, 128>>>(node_attr, atom_emb);                     // 2
    prepack_kernel<<<512, 256>>>(Wq, Wk, Wv, Wa, Wmid, Wo);                // 3
    gemm12_kernel<128, EPI_NODE, false, false><<<dim3(grid128, 3), 256, G8_SMEM>>>( // 4
        px, pWh + OFF_Q, pWl + OFF_Q, 12288, 1536, nullptr, nullptr, bq, nullptr,
        nullptr, nullptr, nullptr, pQ, pKVb, NN);
    comb2_kernel<<<256, 128>>>(dist_emb, path_emb);                        // 5
    gemm12_kernel<128, EPI_TBL, false, false><<<dim3(4, 4), 256, G8_SMEM>>>( // 6: both layers' tables
        pcomb, pWh + OFF_K, pWl + OFF_K, 0, 1536, nullptr, nullptr, bk, bv,
        nullptr, nullptr, nullptr, nullptr, pTkv, 512);
    count_kernel<<<cdiv_h(EE, 256), 256>>>(etgt, batch_idx);
    scan1_kernel<<<NBLK, 256>>>();
    scan2_kernel<<<1, 256>>>();
    scan3_kernel<<<NBLK, 256>>>();
    scatter_kernel<<<cdiv_h(EE, 256), 256>>>(esrc, etgt, sdist, spath);

    for (int l = 0; l < 2; l++) {
        const uint32_t* wh = pWh + (size_t)l * IMG_LAYER;
        const uint32_t* wl = pWl + (size_t)l * IMG_LAYER;

        if (l == 1) {
            gemm12_kernel<128, EPI_NODE, false, false><<<dim3(grid128, 3), 256, G8_SMEM>>>(
                px, wh + OFF_Q, wl + OFF_Q, 12288, 1536, nullptr, nullptr,
                bq + l * 128, nullptr,
                nullptr, nullptr, nullptr, pQ, pKVb, NN);
        }

        edge_attn_kernel<<<cdiv_h(NN, 8), 256>>>(
            (const uint4*)pKVb, (const uint4*)(pTkv + (size_t)l * 512 * 256));

        // h = LN(gelu(aggr)@Wa + ba + x)
        gemm12_kernel<128, EPI_LN, true, false><<<dim3(grid128, 1), 256, G8_SMEM>>>(
            pag, wh + OFF_A, wl + OFF_A, 0, 1536, nullptr, nullptr, ba + l * 128, nullptr,
            px, ln1g + l * 128, ln1b + l * 128, ph, nullptr, NN);
        // mid = gelu(h@Wmid + bmid) -> global bf16 hi/lo image (chunk-major)
        gemm12_kernel<128, EPI_MID, false, false><<<dim3(grid128, 2), 256, G8_SMEM>>>(
            ph, wh + OFF_M, wl + OFF_M, 1536, 3072, pMh, pMl, bmid + l * 256, nullptr,
            nullptr, nullptr, nullptr, nullptr, nullptr, NN);
        // x = LN(mid@Wo + bo + h), A streamed from the mid image (pure memcpy staging)
        gemm12_kernel<256, EPI_LN, false, true><<<dim3(grid128, 1), 256, G8_SMEM>>>(
            nullptr, wh + OFF_O, wl + OFF_O, 0, 1536, pMh, pMl, bo + l * 128, nullptr,
            ph, ln2g + l * 128, ln2b + l * 128, px, nullptr, NN);
    }

    pool_readout_kernel<<<GG, 128>>>(Wout, bout, out);
}

// round 16
// speedup vs baseline: 1.2325x; 1.1013x over previous
#include <cuda_runtime.h>
#include <cuda_bf16.h>
#include <math.h>
#include <stdint.h>

#define NN 50000
#define EE 800000
#define HIDN 128
#define GG 256
#define NBLK 49    // ceil(NN/1024)
#define CHROW 400384  // 50048 rows * 8 words, per-chunk stride of the mid image

static inline int cdiv_h(int a, int b) { return (a + b - 1) / b; }

// ----------------------------- scratch (device globals) -----------------------------
__device__ float g_x[NN * HIDN];
__device__ float g_Q[NN * HIDN];
__device__ __nv_bfloat16 g_KVb[NN * 256];        // interleaved K|V per node: [k4|v4] x 32 groups
__device__ float g_aggr[NN * HIDN];
__device__ float g_h[NN * HIDN];
__device__ float g_comb2[2 * 512 * HIDN];
__device__ __nv_bfloat16 g_tKV[2 * 512 * 256];   // interleaved K|V tables (per layer)
__device__ uint32_t g_wHi[196608];   // prepacked weights (bf16), smem-image layout
__device__ uint32_t g_midH[16 * CHROW];  // FFN mid image (bf16), chunk-major
__device__ int   g_cnt[NN];
__device__ int   g_segoff[NN + 1];
__device__ int   g_cursor[NN];
__device__ uint32_t g_edge[EE];      // packed: src | (dp<<16)
__device__ int   g_bsum[64];
__device__ int   g_boff[64];
__device__ int   g_gcnt[GG];
__device__ int   g_goff[GG + 1];

// image layout constants (words): per layer 98304
#define IMG_LAYER 98304
#define OFF_Q 0
#define OFF_K 12288
#define OFF_V 24576
#define OFF_A 36864
#define OFF_M 49152
#define OFF_O 73728

// ----------------------------- helpers -----------------------------
__device__ __forceinline__ float gelu_f(float x) {
    return 0.5f * x * (1.0f + erff(x * 0.7071067811865476f));
}

__device__ __forceinline__ void mma_bf16(float c[4], const uint32_t a[4], const uint32_t b[2]) {
    asm volatile(
        "mma.sync.aligned.m16n8k16.row.col.f32.bf16.bf16.f32 "
        "{%0,%1,%2,%3}, {%4,%5,%6,%7}, {%8,%9}, {%0,%1,%2,%3};"
        : "+f"(c[0]), "+f"(c[1]), "+f"(c[2]), "+f"(c[3])
        : "r"(a[0]), "r"(a[1]), "r"(a[2]), "r"(a[3]), "r"(b[0]), "r"(b[1]));
}

__device__ __forceinline__ uint32_t f2bf2(float a, float b) {
    __nv_bfloat162 t = __halves2bfloat162(__float2bfloat16(a), __float2bfloat16(b));
    return *(uint32_t*)&t;
}

__device__ __forceinline__ float4 unp4(uint32_t a, uint32_t b) {
    __nv_bfloat162 x = *(__nv_bfloat162*)&a;
    __nv_bfloat162 y = *(__nv_bfloat162*)&b;
    float2 fx = __bfloat1622float2(x), fy = __bfloat1622float2(y);
    return make_float4(fx.x, fx.y, fy.x, fy.y);
}

// ----------------------------- misc kernels -----------------------------
__global__ void zero_kernel() {
    int i = blockIdx.x * blockDim.x + threadIdx.x;
    if (i < NN) g_cnt[i] = 0;
    if (i < GG) g_gcnt[i] = 0;
}

__global__ void encoder_kernel(const int* __restrict__ attr, const float* __restrict__ aemb) {
    int c = threadIdx.x;
    for (int n = blockIdx.x; n < NN; n += gridDim.x) {
        int a0 = attr[n * 4 + 0], a1 = attr[n * 4 + 1], a2 = attr[n * 4 + 2], a3 = attr[n * 4 + 3];
        float v = aemb[(0 * 64 + a0) * HIDN + c] + aemb[(1 * 64 + a1) * HIDN + c]
                + aemb[(2 * 64 + a2) * HIDN + c] + aemb[(3 * 64 + a3) * HIDN + c];
        g_x[(size_t)n * HIDN + c] = v;
    }
}

// prepack ALL weights into GEMM smem-image layout (bf16, kpair-packed, n-major, stride 12)
__global__ void prepack_kernel(const float* __restrict__ Wq, const float* __restrict__ Wk,
                               const float* __restrict__ Wv, const float* __restrict__ Wa,
                               const float* __restrict__ Wm, const float* __restrict__ Wo) {
    for (int id = blockIdx.x * blockDim.x + threadIdx.x; id < 131072;
         id += gridDim.x * blockDim.x) {
        int layer = id >> 16;
        int r = id & 65535;
        const float* W; int N; int segoff; int wi;
        if (r < 32768) {
            int m = r >> 13; wi = r & 8191;
            W = (m == 0 ? Wq : m == 1 ? Wk : m == 2 ? Wv : Wa) + layer * 16384;
            N = 128; segoff = m * 12288;
        } else if (r < 49152) {
            wi = r - 32768; W = Wm + layer * 32768; N = 256; segoff = OFF_M;
        } else {
            wi = r - 49152; W = Wo + layer * 32768; N = 128; segoff = OFF_O;
        }
        int ch = wi / (8 * N);
        int rem = wi % (8 * N);
        int kp = rem / N;
        int n = rem % N;
        int k = ch * 16 + kp * 2;
        float a = W[(size_t)k * N + n], b = W[(size_t)(k + 1) * N + n];
        int w = layer * IMG_LAYER + segoff + ch * N * 12 + n * 12 + kp;
        g_wHi[w] = f2bf2(a, b);
    }
}

__global__ void count_kernel(const int* __restrict__ tgt, const int* __restrict__ bidx) {
    int i = blockIdx.x * blockDim.x + threadIdx.x;
    if (i < EE) atomicAdd(&g_cnt[tgt[i]], 1);
    if (i < NN) atomicAdd(&g_gcnt[bidx[i]], 1);
}

__global__ void scan1_kernel() {
    __shared__ int sh[256];
    int blk = blockIdx.x, t = threadIdx.x;
    int idx4 = blk * 256 + t;
    int4 v4 = make_int4(0, 0, 0, 0);
    if (idx4 < NN / 4) v4 = ((const int4*)g_cnt)[idx4];
    int s = v4.x + v4.y + v4.z + v4.w;
    sh[t] = s;
    __syncthreads();
    for (int d = 1; d < 256; d <<= 1) {
        int v = (t >= d) ? sh[t - d] : 0;
        __syncthreads();
        sh[t] += v;
        __syncthreads();
    }
    int run = (t == 0) ? 0 : sh[t - 1];
    int base = blk * 1024 + t * 4;
    int vv[4] = {v4.x, v4.y, v4.z, v4.w};
    for (int j = 0; j < 4; j++) {
        if (base + j < NN) g_segoff[base + j] = run;
        run += vv[j];
    }
    if (t == 255) g_bsum[blk] = sh[255];
}

__global__ void scan2_kernel() {
    __shared__ int sg[256];
    __shared__ int sb[64];
    int t = threadIdx.x;
    sg[t] = g_gcnt[t];
    if (t < 64) sb[t] = (t < NBLK) ? g_bsum[t] : 0;
    __syncthreads();
    for (int d = 1; d < 256; d <<= 1) {
        int v = (t >= d) ? sg[t - d] : 0;
        int v2 = 0;
        if (t < 64 && t >= d && d < 64) v2 = sb[t - d];
        __syncthreads();
        sg[t] += v;
        if (t < 64 && d < 64) sb[t] += v2;
        __syncthreads();
    }
    g_goff[t + 1] = sg[t];
    if (t == 0) g_goff[0] = 0;
    if (t < 64) g_boff[t] = (t == 0) ? 0 : sb[t - 1];
}

__global__ void scan3_kernel() {
    int blk = blockIdx.x, t = threadIdx.x;
    int off = g_boff[blk];
    int base = blk * 1024 + t * 4;
    for (int j = 0; j < 4; j++) {
        int i = base + j;
        if (i < NN) {
            int v = g_segoff[i] + off;
            g_segoff[i] = v;
            g_cursor[i] = v;
        }
    }
    if (blk == 0 && t == 0) g_segoff[NN] = EE;
}

__global__ void scatter_kernel(const int* __restrict__ src, const int* __restrict__ tgt,
                               const int* __restrict__ sdist, const int* __restrict__ spath) {
    int i = blockIdx.x * blockDim.x + threadIdx.x;
    if (i < EE) {
        int tg = tgt[i];
        int pos = atomicAdd(&g_cursor[tg], 1);
        uint32_t dp = (uint32_t)((sdist[i] << 4) | spath[i]);
        g_edge[pos] = (uint32_t)src[i] | (dp << 16);
    }
}

// combine dist+path embeddings for BOTH layers
__global__ void comb2_kernel(const float* __restrict__ de, const float* __restrict__ pe) {
    int c = threadIdx.x;
    for (int r = blockIdx.x; r < 1024; r += gridDim.x) {
        int l = r >> 9;
        int rr = r & 511;
        int d = rr >> 4, p = rr & 15;
        g_comb2[r * HIDN + c] = de[(l * 32 + d) * HIDN + c] + pe[(l * 16 + p) * HIDN + c];
    }
}

// ------------- GEMM (double-buffered, register-staged B, pure single-pass bf16) ------
enum { EPI_LN = 2, EPI_NODE = 3, EPI_TBL = 4, EPI_MID = 5 };
#define G13_SMEM 26624

template <int KDIM, int EPI, bool GELU_A, bool A_IMG>
__global__ void __launch_bounds__(256) gemm13_kernel(
    const float* __restrict__ Ain,
    const uint32_t* __restrict__ BhGbase,
    int yStride, int chB,
    uint32_t* __restrict__ AimgH,
    const float* __restrict__ bias, const float* __restrict__ bias2,
    const float* __restrict__ res, const float* __restrict__ lng, const float* __restrict__ lnb,
    float* __restrict__ C, __nv_bfloat16* __restrict__ Cb,
    int M)
{
    constexpr int TM = 128;
    constexpr int NC = 128;

    extern __shared__ uint32_t dyn[];
    uint32_t* AhB = dyn;             // 2 x 1536
    uint32_t* BhB = AhB + 3072;      // 2 x 1536
    float2* redS = (float2*)(BhB + 3072);  // 128 x 2

    int tid = threadIdx.x;
    int wid = tid >> 5, lane = tid & 31;
    int g = lane >> 2, q = lane & 3;
    int wrow = (wid & 3) * 32;
    int wcol = (wid >> 2) * 64;
    int r0 = blockIdx.x * TM;

    const float* A = Ain;
    const uint32_t* BhG;
    const float* bs = bias;
    uint32_t* outW = (uint32_t*)Cb;   // interleaved KV output (word view)
    int isV = 0;
    if (EPI == EPI_TBL) {
        int layer = blockIdx.y >> 1, kv = blockIdx.y & 1;
        size_t off = (size_t)layer * IMG_LAYER + kv * 12288;
        BhG = BhGbase + off;
        A = Ain + (size_t)layer * 65536;
        bs = (kv ? bias2 : bias) + layer * 128;
        outW = (uint32_t*)Cb + (size_t)layer * 65536;   // 512 rows x 128 words
        isV = kv;
    } else {
        BhG = BhGbase + (size_t)blockIdx.y * yStride;
        if (EPI == EPI_NODE && blockIdx.y != 0) {
            bs = nullptr;
            isV = (blockIdx.y == 2);
        }
        if (EPI == EPI_MID) bs = bias + blockIdx.y * 128;
    }

    float acc[2][8][4];
#pragma unroll
    for (int a = 0; a < 2; a++)
#pragma unroll
        for (int b = 0; b < 8; b++)
#pragma unroll
            for (int c = 0; c < 4; c++) acc[a][b][c] = 0.f;

    float4 aS[2];
    uint4 aP4;
    uint2 bPh[3];
    int arow = tid >> 1, apart = (tid & 1) * 4;
    size_t abase = (size_t)(r0 + arow) * 8 + apart;

    // prologue: stage chunk 0
    if (A_IMG) {
        aP4 = *(const uint4*)(AimgH + abase);
    } else {
#pragma unroll
        for (int i = 0; i < 2; i++) {
            int j = tid + i * 256;
            int row = j >> 2, c4 = j & 3;
            int gr = r0 + row;
            aS[i] = (gr < M) ? *(const float4*)(A + (size_t)gr * KDIM + c4 * 4)
                             : make_float4(0.f, 0.f, 0.f, 0.f);
        }
    }
#pragma unroll
    for (int i = 0; i < 3; i++) bPh[i] = ((const uint2*)BhG)[tid + i * 256];

    constexpr int NCH = KDIM / 16;
#pragma unroll 1
    for (int c = 0; c < NCH; c++) {
        int p = c & 1;
        uint32_t* Ah = AhB + p * 1536;
        uint32_t* Bh = BhB + p * 1536;

        // store staged -> smem[p]
        if (A_IMG) {
            *(uint4*)&Ah[arow * 12 + apart] = aP4;
        } else {
#pragma unroll
            for (int i = 0; i < 2; i++) {
                int j = tid + i * 256;
                int row = j >> 2, c4 = j & 3;
                float4 v = aS[i];
                if (GELU_A) { v.x = gelu_f(v.x); v.y = gelu_f(v.y); v.z = gelu_f(v.z); v.w = gelu_f(v.w); }
                *(uint2*)&Ah[row * 12 + c4 * 2] = make_uint2(f2bf2(v.x, v.y), f2bf2(v.z, v.w));
            }
        }
#pragma unroll
        for (int i = 0; i < 3; i++) ((uint2*)Bh)[tid + i * 256] = bPh[i];
        __syncthreads();   // single barrier per chunk (double-buffer safe)

        // prefetch next chunk into registers
        if (c + 1 < NCH) {
            if (A_IMG) {
                size_t off = (size_t)(c + 1) * CHROW + abase;
                aP4 = *(const uint4*)(AimgH + off);
            } else {
                int kn = (c + 1) * 16;
#pragma unroll
                for (int i = 0; i < 2; i++) {
                    int j = tid + i * 256;
                    int row = j >> 2, c4 = j & 3;
                    int gr = r0 + row;
                    aS[i] = (gr < M) ? *(const float4*)(A + (size_t)gr * KDIM + kn + c4 * 4)
                                     : make_float4(0.f, 0.f, 0.f, 0.f);
                }
            }
            int cb = (c + 1) * chB;
#pragma unroll
            for (int i = 0; i < 3; i++) bPh[i] = ((const uint2*)(BhG + cb))[tid + i * 256];
        }

        // fragments + mma (from buffer p): single pass bf16
        uint32_t ah[2][4];
#pragma unroll
        for (int mt = 0; mt < 2; mt++) {
            int r = wrow + mt * 16 + g;
            ah[mt][0] = Ah[r * 12 + q];     ah[mt][1] = Ah[(r + 8) * 12 + q];
            ah[mt][2] = Ah[r * 12 + q + 4]; ah[mt][3] = Ah[(r + 8) * 12 + q + 4];
        }
#pragma unroll
        for (int nt = 0; nt < 8; nt++) {
            int n = wcol + nt * 8 + g;
            uint32_t bh[2] = {Bh[n * 12 + q], Bh[n * 12 + q + 4]};
#pragma unroll
            for (int mt = 0; mt < 2; mt++) mma_bf16(acc[mt][nt], ah[mt], bh);
        }
    }
    __syncthreads();

    if (EPI == EPI_LN) {
        int wh = wcol >> 6;
        float s0[2] = {0, 0}, q0[2] = {0, 0}, s1[2] = {0, 0}, q1[2] = {0, 0};
#pragma unroll
        for (int mt = 0; mt < 2; mt++) {
            int ra = r0 + wrow + mt * 16 + g, rb = ra + 8;
#pragma unroll
            for (int nt = 0; nt < 8; nt++) {
                int col = wcol + nt * 8 + q * 2;
                float b0 = bias[col], b1 = bias[col + 1];
                float ra0 = (ra < M) ? res[(size_t)ra * NC + col] : 0.f;
                float ra1 = (ra < M) ? res[(size_t)ra * NC + col + 1] : 0.f;
                float rb0 = (rb < M) ? res[(size_t)rb * NC + col] : 0.f;
                float rb1 = (rb < M) ? res[(size_t)rb * NC + col + 1] : 0.f;
                float va0 = acc[mt][nt][0] + b0 + ra0;
                float va1 = acc[mt][nt][1] + b1 + ra1;
                float vb0 = acc[mt][nt][2] + b0 + rb0;
                float vb1 = acc[mt][nt][3] + b1 + rb1;
                acc[mt][nt][0] = va0; acc[mt][nt][1] = va1;
                acc[mt][nt][2] = vb0; acc[mt][nt][3] = vb1;
                s0[mt] += va0 + va1; q0[mt] += va0 * va0 + va1 * va1;
                s1[mt] += vb0 + vb1; q1[mt] += vb0 * vb0 + vb1 * vb1;
            }
        }
#pragma unroll
        for (int mt = 0; mt < 2; mt++) {
            s0[mt] += __shfl_xor_sync(0xffffffffu, s0[mt], 1);
            s0[mt] += __shfl_xor_sync(0xffffffffu, s0[mt], 2);
            q0[mt] += __shfl_xor_sync(0xffffffffu, q0[mt], 1);
            q0[mt] += __shfl_xor_sync(0xffffffffu, q0[mt], 2);
            s1[mt] += __shfl_xor_sync(0xffffffffu, s1[mt], 1);
            s1[mt] += __shfl_xor_sync(0xffffffffu, s1[mt], 2);
            q1[mt] += __shfl_xor_sync(0xffffffffu, q1[mt], 1);
            q1[mt] += __shfl_xor_sync(0xffffffffu, q1[mt], 2);
            if (q == 0) {
                redS[(wrow + mt * 16 + g) * 2 + wh] = make_float2(s0[mt], q0[mt]);
                redS[(wrow + mt * 16 + 8 + g) * 2 + wh] = make_float2(s1[mt], q1[mt]);
            }
        }
        __syncthreads();
#pragma unroll
        for (int mt = 0; mt < 2; mt++) {
            int lra = wrow + mt * 16 + g;
            float2 p0 = redS[lra * 2], p1 = redS[lra * 2 + 1];
            float2 p0b = redS[(lra + 8) * 2], p1b = redS[(lra + 8) * 2 + 1];
            float sa = p0.x + p1.x, qa = p0.y + p1.y;
            float sb = p0b.x + p1b.x, qb = p0b.y + p1b.y;
            float ma = sa * (1.f / 128.f), mb = sb * (1.f / 128.f);
            float rsa = rsqrtf(qa * (1.f / 128.f) - ma * ma + 1e-5f);
            float rsb = rsqrtf(qb * (1.f / 128.f) - mb * mb + 1e-5f);
            int ra = r0 + lra, rb = ra + 8;
#pragma unroll
            for (int nt = 0; nt < 8; nt++) {
                int col = wcol + nt * 8 + q * 2;
                float g0 = lng[col], g1 = lng[col + 1], o0 = lnb[col], o1 = lnb[col + 1];
                if (ra < M)
                    *(float2*)(C + (size_t)ra * NC + col) =
                        make_float2((acc[mt][nt][0] - ma) * rsa * g0 + o0,
                                    (acc[mt][nt][1] - ma) * rsa * g1 + o1);
                if (rb < M)
                    *(float2*)(C + (size_t)rb * NC + col) =
                        make_float2((acc[mt][nt][2] - mb) * rsb * g0 + o0,
                                    (acc[mt][nt][3] - mb) * rsb * g1 + o1);
            }
        }
    } else if (EPI == EPI_MID) {
#pragma unroll
        for (int mt = 0; mt < 2; mt++) {
            int ra = r0 + wrow + mt * 16 + g, rb = ra + 8;
#pragma unroll
            for (int nt = 0; nt < 8; nt++) {
                int col = wcol + nt * 8 + q * 2;
                float b0 = bs[col], b1 = bs[col + 1];
                float va0 = gelu_f(acc[mt][nt][0] + b0);
                float va1 = gelu_f(acc[mt][nt][1] + b1);
                float vb0 = gelu_f(acc[mt][nt][2] + b0);
                float vb1 = gelu_f(acc[mt][nt][3] + b1);
                int kpl = (wcol >> 1) + nt * 4 + q;       // 0..63
                int ch = ((int)blockIdx.y << 3) + (kpl >> 3);
                int kpin = kpl & 7;
                size_t base = (size_t)ch * CHROW + kpin;
                if (ra < M) AimgH[base + (size_t)ra * 8] = f2bf2(va0, va1);
                if (rb < M) AimgH[base + (size_t)rb * 8] = f2bf2(vb0, vb1);
            }
        }
    } else if (EPI == EPI_NODE) {
#pragma unroll
        for (int mt = 0; mt < 2; mt++) {
            int ra = r0 + wrow + mt * 16 + g, rb = ra + 8;
#pragma unroll
            for (int nt = 0; nt < 8; nt++) {
                int col = wcol + nt * 8 + q * 2;
                float b0 = bs ? bs[col] : 0.f, b1 = bs ? bs[col + 1] : 0.f;
                float oa0 = acc[mt][nt][0] + b0, oa1 = acc[mt][nt][1] + b1;
                float ob0 = acc[mt][nt][2] + b0, ob1 = acc[mt][nt][3] + b1;
                if (blockIdx.y == 0) {
                    if (ra < M) *(float2*)(C + (size_t)ra * NC + col) = make_float2(oa0, oa1);
                    if (rb < M) *(float2*)(C + (size_t)rb * NC + col) = make_float2(ob0, ob1);
                } else {
                    // interleaved KV layout: word = n*128 + (col>>2)*4 + ((col&3)>>1) + isV*2
                    int wofs = ((col >> 2) << 2) + ((col & 3) >> 1) + isV * 2;
                    if (ra < M) outW[(size_t)ra * 128 + wofs] = f2bf2(oa0, oa1);
                    if (rb < M) outW[(size_t)rb * 128 + wofs] = f2bf2(ob0, ob1);
                }
            }
        }
    } else {  // EPI_TBL -> interleaved KV table
#pragma unroll
        for (int mt = 0; mt < 2; mt++) {
            int ra = r0 + wrow + mt * 16 + g, rb = ra + 8;
#pragma unroll
            for (int nt = 0; nt < 8; nt++) {
                int col = wcol + nt * 8 + q * 2;
                float b0 = bs[col], b1 = bs[col + 1];
                int wofs = ((col >> 2) << 2) + ((col & 3) >> 1) + isV * 2;
                if (ra < M) outW[(size_t)ra * 128 + wofs] =
                    f2bf2(acc[mt][nt][0] + b0, acc[mt][nt][1] + b1);
                if (rb < M) outW[(size_t)rb * 128 + wofs] =
                    f2bf2(acc[mt][nt][2] + b0, acc[mt][nt][3] + b1);
            }
        }
    }
}

// ---------------- edge attention (interleaved KV: 2 gathers/edge, 2-edge unrolled) ----
__global__ void __launch_bounds__(256) edge_attn_kernel(
    const uint4* __restrict__ KV, const uint4* __restrict__ TB)
{
    int warp = threadIdx.x >> 5, lane = threadIdx.x & 31;
    int n = blockIdx.x * 8 + warp;
    if (n >= NN) return;
    int beg = g_segoff[n], end = g_segoff[n + 1];
    float4 q4 = *(const float4*)(g_Q + (size_t)n * HIDN + lane * 4);
    float den = 0.f, ax = 0.f, ay = 0.f, az = 0.f, aw = 0.f;
    int p = beg;
    for (; p + 2 <= end; p += 2) {
        uint32_t e0 = g_edge[p], e1 = g_edge[p + 1];
        int s0 = (int)(e0 & 0xFFFFu), i0 = (int)(e0 >> 16);
        int s1 = (int)(e1 & 0xFFFFu), i1 = (int)(e1 >> 16);
        uint4 kvs0 = KV[(size_t)s0 * 32 + lane];
        uint4 kvt0 = TB[(size_t)i0 * 32 + lane];
        uint4 kvs1 = KV[(size_t)s1 * 32 + lane];
        uint4 kvt1 = TB[(size_t)i1 * 32 + lane];
        float4 ks0 = unp4(kvs0.x, kvs0.y), vs0 = unp4(kvs0.z, kvs0.w);
        float4 kt0 = unp4(kvt0.x, kvt0.y), vt0 = unp4(kvt0.z, kvt0.w);
        float4 ks1 = unp4(kvs1.x, kvs1.y), vs1 = unp4(kvs1.z, kvs1.w);
        float4 kt1 = unp4(kvt1.x, kvt1.y), vt1 = unp4(kvt1.z, kvt1.w);
        float sc0 = q4.x * (ks0.x + kt0.x) + q4.y * (ks0.y + kt0.y)
                  + q4.z * (ks0.z + kt0.z) + q4.w * (ks0.w + kt0.w);
        float sc1 = q4.x * (ks1.x + kt1.x) + q4.y * (ks1.y + kt1.y)
                  + q4.z * (ks1.z + kt1.z) + q4.w * (ks1.w + kt1.w);
        sc0 += __shfl_xor_sync(0xffffffffu, sc0, 1);
        sc1 += __shfl_xor_sync(0xffffffffu, sc1, 1);
        sc0 += __shfl_xor_sync(0xffffffffu, sc0, 2);
        sc1 += __shfl_xor_sync(0xffffffffu, sc1, 2);
        float w0 = __expf(sc0 * 0.25f);
        float w1 = __expf(sc1 * 0.25f);
        den += w0 + w1;
        ax += w0 * (vs0.x + vt0.x) + w1 * (vs1.x + vt1.x);
        ay += w0 * (vs0.y + vt0.y) + w1 * (vs1.y + vt1.y);
        az += w0 * (vs0.z + vt0.z) + w1 * (vs1.z + vt1.z);
        aw += w0 * (vs0.w + vt0.w) + w1 * (vs1.w + vt1.w);
    }
    if (p < end) {
        uint32_t e0 = g_edge[p];
        int s0 = (int)(e0 & 0xFFFFu), i0 = (int)(e0 >> 16);
        uint4 kvs0 = KV[(size_t)s0 * 32 + lane];
        uint4 kvt0 = TB[(size_t)i0 * 32 + lane];
        float4 ks0 = unp4(kvs0.x, kvs0.y), vs0 = unp4(kvs0.z, kvs0.w);
        float4 kt0 = unp4(kvt0.x, kvt0.y), vt0 = unp4(kvt0.z, kvt0.w);
        float sc0 = q4.x * (ks0.x + kt0.x) + q4.y * (ks0.y + kt0.y)
                  + q4.z * (ks0.z + kt0.z) + q4.w * (ks0.w + kt0.w);
        sc0 += __shfl_xor_sync(0xffffffffu, sc0, 1);
        sc0 += __shfl_xor_sync(0xffffffffu, sc0, 2);
        float w0 = __expf(sc0 * 0.25f);
        den += w0;
        ax += w0 * (vs0.x + vt0.x);
        ay += w0 * (vs0.y + vt0.y);
        az += w0 * (vs0.z + vt0.z);
        aw += w0 * (vs0.w + vt0.w);
    }
    float inv = 1.f / (den + 1e-16f);
    *(float4*)(g_aggr + (size_t)n * HIDN + lane * 4) =
        make_float4(ax * inv, ay * inv, az * inv, aw * inv);
}

// ----------------------------- fused pool + readout -----------------------------
__global__ void pool_readout_kernel(const float* __restrict__ Wout, const float* __restrict__ bout,
                                    float* __restrict__ out) {
    int gi = blockIdx.x;
    int t = threadIdx.x;
    int s = g_goff[gi], e = g_goff[gi + 1];
    float acc = 0.f;
    for (int n = s; n < e; n++) acc += g_x[(size_t)n * HIDN + t];
    float cnt = fmaxf((float)(e - s), 1.f);
    float v = acc / cnt * Wout[t];
    for (int d = 16; d; d >>= 1) v += __shfl_xor_sync(0xffffffffu, v, d);
    __shared__ float sw[4];
    if ((t & 31) == 0) sw[t >> 5] = v;
    __syncthreads();
    if (t == 0) out[gi] = sw[0] + sw[1] + sw[2] + sw[3] + bout[0];
}

// ----------------------------- launch -----------------------------
extern "C" void kernel_launch(void* const* d_in, const int* in_sizes, int n_in,
                              void* d_out, int out_size) {
    const int*   node_attr = (const int*)d_in[0];
    const int*   batch_idx = (const int*)d_in[1];
    const int*   eidx      = (const int*)d_in[2];
    const int*   sdist     = (const int*)d_in[3];
    const int*   spath     = (const int*)d_in[4];
    const float* atom_emb  = (const float*)d_in[5];
    const float* dist_emb  = (const float*)d_in[6];
    const float* path_emb  = (const float*)d_in[7];
    const float* Wq = (const float*)d_in[8];
    const float* bq = (const float*)d_in[9];
    const float* Wk = (const float*)d_in[10];
    const float* bk = (const float*)d_in[11];
    const float* Wv = (const float*)d_in[12];
    const float* bv = (const float*)d_in[13];
    const float* Wa = (const float*)d_in[14];
    const float* ba = (const float*)d_in[15];
    const float* ln1g = (const float*)d_in[16];
    const float* ln1b = (const float*)d_in[17];
    const float* Wmid = (const float*)d_in[18];
    const float* bmid = (const float*)d_in[19];
    const float* Wo = (const float*)d_in[20];
    const float* bo = (const float*)d_in[21];
    const float* ln2g = (const float*)d_in[22];
    const float* ln2b = (const float*)d_in[23];
    const float* Wout = (const float*)d_in[24];
    const float* bout = (const float*)d_in[25];
    float* out = (float*)d_out;

    float *px, *pQ, *pag, *ph, *pcomb;
    __nv_bfloat16 *pKVb, *pTkv;
    uint32_t *pWh, *pMh;
    cudaGetSymbolAddress((void**)&px, g_x);
    cudaGetSymbolAddress((void**)&pQ, g_Q);
    cudaGetSymbolAddress((void**)&pKVb, g_KVb);
    cudaGetSymbolAddress((void**)&pag, g_aggr);
    cudaGetSymbolAddress((void**)&ph, g_h);
    cudaGetSymbolAddress((void**)&pcomb, g_comb2);
    cudaGetSymbolAddress((void**)&pTkv, g_tKV);
    cudaGetSymbolAddress((void**)&pWh, g_wHi);
    cudaGetSymbolAddress((void**)&pMh, g_midH);

    const int* esrc = eidx;
    const int* etgt = eidx + EE;
    int grid128 = cdiv_h(NN, 128);

    // ---- launch #4 is the layer-0 QKV GEMM (profiled slot) ----
    zero_kernel<<<cdiv_h(NN, 256), 256>>>();                               // 1
    encoder_kernel<<<512, 128>>>(node_attr, atom_emb);                     // 2
    prepack_kernel<<<512, 256>>>(Wq, Wk, Wv, Wa, Wmid, Wo);                // 3
    gemm13_kernel<128, EPI_NODE, false, false><<<dim3(grid128, 3), 256, G13_SMEM>>>( // 4
        px, pWh + OFF_Q, 12288, 1536, nullptr, bq, nullptr,
        nullptr, nullptr, nullptr, pQ, pKVb, NN);
    comb2_kernel<<<256, 128>>>(dist_emb, path_emb);                        // 5
    gemm13_kernel<128, EPI_TBL, false, false><<<dim3(4, 4), 256, G13_SMEM>>>( // 6: both layers' tables
        pcomb, pWh + OFF_K, 0, 1536, nullptr, bk, bv,
        nullptr, nullptr, nullptr, nullptr, pTkv, 512);
    count_kernel<<<cdiv_h(EE, 256), 256>>>(etgt, batch_idx);
    scan1_kernel<<<NBLK, 256>>>();
    scan2_kernel<<<1, 256>>>();
    scan3_kernel<<<NBLK, 256>>>();
    scatter_kernel<<<cdiv_h(EE, 256), 256>>>(esrc, etgt, sdist, spath);

    for (int l = 0; l < 2; l++) {
        const uint32_t* wh = pWh + (size_t)l * IMG_LAYER;

        if (l == 1) {
            gemm13_kernel<128, EPI_NODE, false, false><<<dim3(grid128, 3), 256, G13_SMEM>>>(
                px, wh + OFF_Q, 12288, 1536, nullptr, bq + l * 128, nullptr,
                nullptr, nullptr, nullptr, pQ, pKVb, NN);
        }

        edge_attn_kernel<<<cdiv_h(NN, 8), 256>>>(
            (const uint4*)pKVb, (const uint4*)(pTkv + (size_t)l * 512 * 256));

        // h = LN(gelu(aggr)@Wa + ba + x)
        gemm13_kernel<128, EPI_LN, true, false><<<dim3(grid128, 1), 256, G13_SMEM>>>(
            pag, wh + OFF_A, 0, 1536, nullptr, ba + l * 128, nullptr,
            px, ln1g + l * 128, ln1b + l * 128, ph, nullptr, NN);
        // mid = gelu(h@Wmid + bmid) -> global bf16 image (chunk-major)
        gemm13_kernel<128, EPI_MID, false, false><<<dim3(grid128, 2), 256, G13_SMEM>>>(
            ph, wh + OFF_M, 1536, 3072, pMh, bmid + l * 256, nullptr,
            nullptr, nullptr, nullptr, nullptr, nullptr, NN);
        // x = LN(mid@Wo + bo + h), A streamed from the mid image (pure memcpy staging)
        gemm13_kernel<256, EPI_LN, false, true><<<dim3(grid128, 1), 256, G13_SMEM>>>(
            nullptr, wh + OFF_O, 0, 1536, pMh, bo + l * 128, nullptr,
            ph, ln2g + l * 128, ln2b + l * 128, px, nullptr, NN);
    }

    pool_readout_kernel<<<GG, 128>>>(Wout, bout, out);
}